// round 6
// baseline (speedup 1.0000x reference)
#include <cuda_runtime.h>
#include <math.h>

#define NB 8
#define NC 256
#define NHW 9216
#define NHEAD 8
#define NCP 32

// ---------------- scratch (device globals; no allocation anywhere) ----------
__device__ float  g_v[NB*NC*NHW];      // 75.5 MB
__device__ float  g_S[NB*256*256];     // sum_s x x^T      (per batch, symmetric)
__device__ float  g_M[NB*256*256];     // sum_s x x_rev^T  (per batch, symmetric)
__device__ float  g_m[NB*256];
__device__ float  g_nq[NB*256], g_nk[NB*256];
__device__ float  g_w1m[NB*256], g_w2m[NB*256];
__device__ float2 g_Chat[64*1024];
__device__ float2 g_gtab[96*96];
__device__ float2 g_Tt[NB*NC*NHW];     // [ch][a][r]
__device__ float  g_R [NB*NC*NHW];

// ---------------- fp32 SGEMM: Y[b][o][s] = sum_c W[o][c] X[b][c][s] (+bias) --
__global__ void __launch_bounds__(256) k_gemm(
    const float* __restrict__ X, const float* __restrict__ W,
    const float* __restrict__ bias, float* __restrict__ Y)
{
    __shared__ __align__(16) float Ws[8][132];
    __shared__ __align__(16) float Xs[8][132];
    const int t  = threadIdx.x;
    const int s0 = blockIdx.x * 128;
    const int o0 = blockIdx.y * 128;
    const int b  = blockIdx.z;
    const int tx = t & 15, ty = t >> 4;
    const float* Xb = X + (size_t)b * NC * NHW;

    float acc[8][8];
#pragma unroll
    for (int i = 0; i < 8; i++)
#pragma unroll
        for (int j = 0; j < 8; j++) acc[i][j] = 0.f;

    const int wi = t >> 1, wk = (t & 1) * 4;
    const int xr = t >> 5, xc = (t & 31) * 4;

    for (int kc = 0; kc < 256; kc += 8) {
        float4 w4 = *(const float4*)&W[(o0 + wi) * 256 + kc + wk];
        float4 x4 = *(const float4*)&Xb[(size_t)(kc + xr) * NHW + s0 + xc];
        __syncthreads();
        Ws[wk + 0][wi] = w4.x; Ws[wk + 1][wi] = w4.y;
        Ws[wk + 2][wi] = w4.z; Ws[wk + 3][wi] = w4.w;
        *(float4*)&Xs[xr][xc] = x4;
        __syncthreads();
#pragma unroll
        for (int kk = 0; kk < 8; kk++) {
            float a[8], bb[8];
            *(float4*)&a[0]  = *(float4*)&Ws[kk][ty * 4];
            *(float4*)&a[4]  = *(float4*)&Ws[kk][64 + ty * 4];
            *(float4*)&bb[0] = *(float4*)&Xs[kk][tx * 4];
            *(float4*)&bb[4] = *(float4*)&Xs[kk][64 + tx * 4];
#pragma unroll
            for (int i = 0; i < 8; i++)
#pragma unroll
                for (int j = 0; j < 8; j++) acc[i][j] += a[i] * bb[j];
        }
    }
#pragma unroll
    for (int i = 0; i < 8; i++) {
        int o = o0 + ((i < 4) ? ty * 4 + i : 64 + ty * 4 + i - 4);
        float bv = bias ? bias[o] : 0.f;
        float* yp = Y + (size_t)(b * NC + o) * NHW + s0;
        float4 v0 = make_float4(acc[i][0] + bv, acc[i][1] + bv, acc[i][2] + bv, acc[i][3] + bv);
        float4 v1 = make_float4(acc[i][4] + bv, acc[i][5] + bv, acc[i][6] + bv, acc[i][7] + bv);
        *(float4*)&yp[tx * 4]      = v0;
        *(float4*)&yp[64 + tx * 4] = v1;
    }
}

// ---------------- zero S and M ----------------
__global__ void k_zeroSM()
{
    int i = blockIdx.x * 256 + threadIdx.x;
    g_S[i] = 0.f;
    g_M[i] = 0.f;
}

// ---------------- m[b][c] = sum_s x[b][c][s] ----------------
__global__ void __launch_bounds__(256) k_xsum(const float* __restrict__ X)
{
    const int bc = blockIdx.x;
    const float4* x4 = (const float4*)(X + (size_t)bc * NHW);
    float s = 0.f;
    for (int i = threadIdx.x; i < NHW / 4; i += 256) {
        float4 a = x4[i]; s += a.x + a.y + a.z + a.w;
    }
#pragma unroll
    for (int o = 16; o; o >>= 1) s += __shfl_xor_sync(0xffffffff, s, o);
    __shared__ float sb[8];
    int w = threadIdx.x >> 5;
    if ((threadIdx.x & 31) == 0) sb[w] = s;
    __syncthreads();
    if (threadIdx.x == 0) {
        float a = 0.f;
        for (int i = 0; i < 8; i++) a += sb[i];
        g_m[bc] = a;
    }
}

// ---------------- Gram GEMM: 128x128 tiles, 8x8/thread, split-K over s ------
// grid: x = split-K chunk (8 chunks of 1152), y = pair (0:(0,0) 1:(0,1) 2:(1,1)),
//       z = b*2 + mat  (mat 0 -> S, 1 -> M)
__global__ void __launch_bounds__(256) k_gram2(const float* __restrict__ X)
{
    const int sch = blockIdx.x, pr = blockIdx.y;
    const int b = blockIdx.z >> 1, mat = blockIdx.z & 1;
    const int ci = (pr == 2) ? 1 : 0;
    const int dj = (pr == 0) ? 0 : 1;
    __shared__ __align__(16) float xa[8][132];
    __shared__ __align__(16) float xd[8][132];
    const float* Xb = X + (size_t)b * NC * NHW;
    const int t = threadIdx.x;
    const int tx = t & 15, ty = t >> 4;
    const int r2 = t >> 1, h4 = (t & 1) * 4;

    float acc[8][8];
#pragma unroll
    for (int i = 0; i < 8; i++)
#pragma unroll
        for (int j = 0; j < 8; j++) acc[i][j] = 0.f;

    for (int ks = 0; ks < 144; ks++) {
        const int s0 = sch * 1152 + ks * 8;
        float4 av = *(const float4*)&Xb[(size_t)(ci * 128 + r2) * NHW + s0 + h4];
        float4 dv;
        if (mat == 0) {
            dv = *(const float4*)&Xb[(size_t)(dj * 128 + r2) * NHW + s0 + h4];
        } else {
            int y  = s0 / 96;
            int x0 = s0 - y * 96;
            int ry = (y == 0) ? 0 : 96 - y;
            const float* rowp = &Xb[(size_t)(dj * 128 + r2) * NHW + ry * 96];
            float tmp[4];
#pragma unroll
            for (int q = 0; q < 4; q++) {
                int x = x0 + h4 + q;
                int rx = (x == 0) ? 0 : 96 - x;
                tmp[q] = rowp[rx];
            }
            dv = make_float4(tmp[0], tmp[1], tmp[2], tmp[3]);
        }
        __syncthreads();
        xa[h4 + 0][r2] = av.x; xa[h4 + 1][r2] = av.y;
        xa[h4 + 2][r2] = av.z; xa[h4 + 3][r2] = av.w;
        xd[h4 + 0][r2] = dv.x; xd[h4 + 1][r2] = dv.y;
        xd[h4 + 2][r2] = dv.z; xd[h4 + 3][r2] = dv.w;
        __syncthreads();
#pragma unroll
        for (int kk = 0; kk < 8; kk++) {
            float a[8], bb[8];
            *(float4*)&a[0]  = *(float4*)&xa[kk][ty * 4];
            *(float4*)&a[4]  = *(float4*)&xa[kk][64 + ty * 4];
            *(float4*)&bb[0] = *(float4*)&xd[kk][tx * 4];
            *(float4*)&bb[4] = *(float4*)&xd[kk][64 + tx * 4];
#pragma unroll
            for (int i = 0; i < 8; i++)
#pragma unroll
                for (int j = 0; j < 8; j++) acc[i][j] += a[i] * bb[j];
        }
    }
    float* Out = (mat ? g_M : g_S) + b * 65536;
#pragma unroll
    for (int i = 0; i < 8; i++) {
        int ri = ci * 128 + ((i < 4) ? ty * 4 + i : 64 + ty * 4 + i - 4);
#pragma unroll
        for (int j = 0; j < 8; j++) {
            int rj = dj * 128 + ((j < 4) ? tx * 4 + j : 64 + tx * 4 + j - 4);
            atomicAdd(&Out[ri * 256 + rj], acc[i][j]);
        }
    }
}

// ---------------- mirror lower-left 128x128 block from upper-right ----------
__global__ void k_mirror()
{
    const int bm = blockIdx.y;                 // b*2+mat
    float* Out = (bm & 1 ? g_M : g_S) + (bm >> 1) * 65536;
    int idx = blockIdx.x * 256 + threadIdx.x;  // 0..16383
    int i = idx >> 7, jl = idx & 127;
    Out[(128 + jl) * 256 + i] = Out[i * 256 + 128 + jl];
}

// ---------------- norms: n[b][c] = w_c S w_c^T (+bias terms), wm = w_c . m --
// grid (8 row-tiles of 32, 8 b, 2 which). W read direct from global (L1/L2 hot).
__global__ void __launch_bounds__(256) k_norms(
    const float* __restrict__ W1, const float* __restrict__ W2,
    const float* __restrict__ b1, const float* __restrict__ b2)
{
    const int c0 = blockIdx.x * 32, b = blockIdx.y, which = blockIdx.z;
    const float* W  = which ? W2 : W1;
    const float* bs = which ? b2 : b1;
    const int t = threadIdx.x;
    const int cl = t >> 3, j0 = (t & 7) * 32;
    const float* Wr = W + (c0 + cl) * 256;
    const float* Sb = g_S + b * 65536;
    const float* mb = g_m + b * 256;

    float wm = 0.f;
#pragma unroll 8
    for (int j = 0; j < 32; j++) wm += Wr[j0 + j] * mb[j0 + j];

    float tmp[32];
#pragma unroll
    for (int j = 0; j < 32; j++) tmp[j] = 0.f;
    for (int k = 0; k < 256; k++) {
        float wck = Wr[k];
        const float4* sp = (const float4*)&Sb[k * 256 + j0];
#pragma unroll
        for (int j4 = 0; j4 < 8; j4++) {
            float4 sv = sp[j4];
            tmp[j4 * 4 + 0] += wck * sv.x;
            tmp[j4 * 4 + 1] += wck * sv.y;
            tmp[j4 * 4 + 2] += wck * sv.z;
            tmp[j4 * 4 + 3] += wck * sv.w;
        }
    }
    float n = 0.f;
#pragma unroll
    for (int j = 0; j < 32; j++) n += tmp[j] * Wr[j0 + j];
#pragma unroll
    for (int o = 4; o; o >>= 1) {
        n  += __shfl_xor_sync(0xffffffff, n,  o);
        wm += __shfl_xor_sync(0xffffffff, wm, o);
    }
    if ((t & 7) == 0) {
        int c = c0 + cl;
        float bc = bs[c];
        float nf = n + 2.f * bc * wm + 9216.f * bc * bc;
        if (which) { g_nk[b * 256 + c] = nf; g_w2m[b * 256 + c] = wm; }
        else       { g_nq[b * 256 + c] = nf; g_w1m[b * 256 + c] = wm; }
    }
}

// ---------------- attn: Y=W1_h M, G=Y W2_h^T, logits, softmax, Chat ---------
// W1 read direct from global in the Y pass (smem fits: Ys 33KB + misc < 40KB)
__global__ void __launch_bounds__(256) k_attn3(
    const float* __restrict__ W1, const float* __restrict__ W2,
    const float* __restrict__ b1, const float* __restrict__ b2,
    const float* __restrict__ temperature)
{
    const int bh = blockIdx.x;
    const int b = bh >> 3, h = bh & 7;
    const int ch0 = h * 32;
    __shared__ float Ys[32][260];
    __shared__ float Gs[32][33];
    __shared__ float A[32][33];
    __shared__ float rq[32], rk[32], sw1m[32], sw2m[32], sb1[32], sb2[32];
    __shared__ float2 tab[32];
    const int t = threadIdx.x;

    if (t < 32) {
        int C = b * 256 + ch0 + t;
        rq[t] = rsqrtf(g_nq[C]);
        rk[t] = rsqrtf(g_nk[C]);
        sw1m[t] = g_w1m[C];
        sw2m[t] = g_w2m[C];
        sb1[t] = b1[ch0 + t];
        sb2[t] = b2[ch0 + t];
        float ang = 6.283185307179586f * (float)t / 32.0f;
        tab[t] = make_float2(cosf(ang), sinf(ang));
    }

    // Y[cl][j] = sum_k W1[ch0+cl][k] M[b][k][j]
    {
        const int cl = t >> 3, j0 = (t & 7) * 32;
        const float* W1r = W1 + (ch0 + cl) * 256;
        const float* Mb = g_M + b * 65536;
        float tmp[32];
#pragma unroll
        for (int j = 0; j < 32; j++) tmp[j] = 0.f;
        for (int k = 0; k < 256; k++) {
            float wck = W1r[k];
            const float4* mp = (const float4*)&Mb[k * 256 + j0];
#pragma unroll
            for (int j4 = 0; j4 < 8; j4++) {
                float4 mv = mp[j4];
                tmp[j4 * 4 + 0] += wck * mv.x;
                tmp[j4 * 4 + 1] += wck * mv.y;
                tmp[j4 * 4 + 2] += wck * mv.z;
                tmp[j4 * 4 + 3] += wck * mv.w;
            }
        }
#pragma unroll
        for (int j = 0; j < 32; j++) Ys[cl][j0 + j] = tmp[j];
    }
    __syncthreads();

    // G[c][d] = sum_j Ys[c][j] W2[ch0+d][j]   (4 outputs per thread)
    {
        int o = t * 4;
        int c = o >> 5, d0 = o & 31;
        float acc[4] = {0.f, 0.f, 0.f, 0.f};
        for (int j4 = 0; j4 < 64; j4++) {
            float4 yv = *(const float4*)&Ys[c][j4 * 4];
#pragma unroll
            for (int q = 0; q < 4; q++) {
                const float* w2r = &W2[(ch0 + d0 + q) * 256 + j4 * 4];
                acc[q] += yv.x * w2r[0] + yv.y * w2r[1] + yv.z * w2r[2] + yv.w * w2r[3];
            }
        }
#pragma unroll
        for (int q = 0; q < 4; q++) Gs[c][d0 + q] = acc[q];
    }
    __syncthreads();

    const float ts = temperature[h];
    const int w = t >> 5, lane = t & 31;
    for (int r = w; r < 32; r += 8) {
        float L = (Gs[r][lane] + sw1m[r] * sb2[lane] + sb1[r] * sw2m[lane]
                   + 9216.f * sb1[r] * sb2[lane]) * rq[r] * rk[lane] * ts;
        float m = L;
#pragma unroll
        for (int o = 16; o; o >>= 1) m = fmaxf(m, __shfl_xor_sync(0xffffffff, m, o));
        float e = expf(L - m);
        float s = e;
#pragma unroll
        for (int o = 16; o; o >>= 1) s += __shfl_xor_sync(0xffffffff, s, o);
        A[r][lane] = e / s;
    }
    __syncthreads();
    for (int idx = t; idx < 1024; idx += 256) {
        int e = idx >> 5, d = idx & 31;
        float re = 0.f, im = 0.f;
#pragma unroll 8
        for (int c = 0; c < 32; c++) {
            float a = A[c][d];
            float2 tb = tab[(c * e) & 31];
            re += a * tb.x; im += a * tb.y;
        }
        re *= (1.0f / 32.0f); im *= (1.0f / 32.0f);
        if (e == 0) im += (1.0f / 32.0f);
        g_Chat[bh * 1024 + idx] = make_float2(re, im);
    }
}

// ---------------- g table (stable half-angle form) ----------------
__global__ void k_gtab()
{
    int idx = blockIdx.x * 256 + threadIdx.x;
    if (idx >= 96 * 96) return;
    int hr = idx / 96, tt = idx - hr * 96;
    float2 g;
    if (hr == 0) {
        g = make_float2(tt == 0 ? 1.f : 0.f, 0.f);
    } else {
        const float PI = 3.14159265358979323846f;
        float h1 = PI * (float)hr / 96.0f;
        float h2 = PI * (96.0f * (float)tt + (float)hr) / 9216.0f;
        float r = sinf(h1) / (96.0f * sinf(h2));
        float psi = h1 - h2;
        g = make_float2(r * cosf(psi), r * sinf(psi));
    }
    g_gtab[idx] = g;
}

// ---------------- v -> Tt directly (fused transpose) ------------------------
__global__ void __launch_bounds__(256) k_vtrans2()
{
    const int ch0 = blockIdx.x * 2, r0 = blockIdx.y * 32;
    __shared__ float  vsm[2 * 32 * 96];
    __shared__ float2 gsm[32 * 96];
    const int t = threadIdx.x;
#pragma unroll
    for (int i = 0; i < 6; i++) {
        int idx = i * 256 + t;
        int row = idx / 24, c4 = idx % 24;
        int ch = row >> 5, rr = row & 31;
        float4 v = *(const float4*)&g_v[(size_t)(ch0 + ch) * NHW + (r0 + rr) * 96 + c4 * 4];
        *(float4*)&vsm[(ch * 32 + rr) * 96 + c4 * 4] = v;
    }
#pragma unroll
    for (int i = 0; i < 12; i++) {
        int idx = i * 256 + t;
        int rr = idx / 96, c = idx % 96;
        gsm[rr * 96 + c] = g_gtab[(r0 + rr) * 96 + c];
    }
    __syncthreads();
    const int lane = t & 31, a0 = (t >> 5) * 12;
    float ar[2][12], ai[2][12];
#pragma unroll
    for (int c = 0; c < 2; c++)
#pragma unroll
        for (int j = 0; j < 12; j++) { ar[c][j] = 0.f; ai[c][j] = 0.f; }

    const float*  v0p = &vsm[lane * 96];
    const float*  v1p = &vsm[(32 + lane) * 96];
    const float2* gp  = &gsm[lane * 96];
    for (int w0 = 0; w0 < 96; w0++) {
        int we = w0 + lane; if (we >= 96) we -= 96;
        float v0 = v0p[we], v1 = v1p[we];
        int base = a0 - we; if (base < 0) base += 96;
#pragma unroll
        for (int j = 0; j < 12; j++) {
            int ii = base + j; if (ii >= 96) ii -= 96;
            float2 g = gp[ii];
            ar[0][j] += v0 * g.x; ai[0][j] += v0 * g.y;
            ar[1][j] += v1 * g.x; ai[1][j] += v1 * g.y;
        }
    }
#pragma unroll
    for (int c = 0; c < 2; c++)
#pragma unroll
        for (int j = 0; j < 12; j++)
            g_Tt[(size_t)(ch0 + c) * NHW + (a0 + j) * 96 + r0 + lane] =
                make_float2(ar[c][j], ai[c][j]);
}

// ---------------- mix: R[bh*32+e][s] = | sum_d Chat[e][d] * Tt[bh*32+d][s] |
__global__ void __launch_bounds__(256) k_mix()
{
    const int s0 = blockIdx.x * 128;
    const int bh = blockIdx.y;
    __shared__ float2 Ch[1024];
    __shared__ float2 Ts[32][128];
    const int t = threadIdx.x;
    for (int i = t; i < 1024; i += 256) Ch[i] = g_Chat[bh * 1024 + i];
    for (int i = t; i < 4096; i += 256) {
        int d = i >> 7, j = i & 127;
        Ts[d][j] = g_Tt[(size_t)(bh * 32 + d) * NHW + s0 + j];
    }
    __syncthreads();
    const int sl = t & 63, eg = t >> 6;
    float ar0[8], ai0[8], ar1[8], ai1[8];
#pragma unroll
    for (int i = 0; i < 8; i++) { ar0[i] = ai0[i] = ar1[i] = ai1[i] = 0.f; }

    for (int d = 0; d < 32; d++) {
        float2 t0 = Ts[d][sl];
        float2 t1 = Ts[d][sl + 64];
#pragma unroll
        for (int i = 0; i < 8; i++) {
            float2 c = Ch[(eg * 8 + i) * 32 + d];
            ar0[i] += c.x * t0.x - c.y * t0.y;
            ai0[i] += c.x * t0.y + c.y * t0.x;
            ar1[i] += c.x * t1.x - c.y * t1.y;
            ai1[i] += c.x * t1.y + c.y * t1.x;
        }
    }
#pragma unroll
    for (int i = 0; i < 8; i++) {
        int row = bh * 32 + eg * 8 + i;
        g_R[(size_t)row * NHW + s0 + sl]      = sqrtf(ar0[i] * ar0[i] + ai0[i] * ai0[i]);
        g_R[(size_t)row * NHW + s0 + sl + 64] = sqrtf(ar1[i] * ar1[i] + ai1[i] * ai1[i]);
    }
}

// ---------------- launch ----------------
extern "C" void kernel_launch(void* const* d_in, const int* in_sizes, int n_in,
                              void* d_out, int out_size)
{
    const float* x    = (const float*)d_in[0];
    const float* w1   = (const float*)d_in[1];
    const float* b1   = (const float*)d_in[2];
    const float* w2   = (const float*)d_in[3];
    const float* b2   = (const float*)d_in[4];
    const float* w3   = (const float*)d_in[5];
    const float* b3   = (const float*)d_in[6];
    const float* wo   = (const float*)d_in[7];
    const float* temp = (const float*)d_in[8];
    float* out = (float*)d_out;

    float *vp = nullptr, *Rp = nullptr;
    cudaGetSymbolAddress((void**)&vp, g_v);
    cudaGetSymbolAddress((void**)&Rp, g_R);

    dim3 gg(72, 2, 8);

    k_gemm   <<<gg, 256>>>(x, w3, b3, vp);             // v
    k_zeroSM <<<2048, 256>>>();
    k_xsum   <<<2048, 256>>>(x);
    k_gram2  <<<dim3(8, 3, 16), 256>>>(x);             // S, M (upper pairs)
    k_mirror <<<dim3(64, 16), 256>>>();
    k_norms  <<<dim3(8, 8, 2), 256>>>(w1, w2, b1, b2);
    k_gtab   <<<36, 256>>>();
    k_attn3  <<<64, 256>>>(w1, w2, b1, b2, temp);
    k_vtrans2<<<dim3(1024, 3), 256>>>();
    k_mix    <<<dim3(72, 64), 256>>>();
    k_gemm   <<<gg, 256>>>(Rp, wo, nullptr, out);
}

// round 7
// speedup vs baseline: 1.4279x; 1.4279x over previous
#include <cuda_runtime.h>
#include <math.h>

#define NB 8
#define NC 256
#define NHW 9216
#define NHEAD 8
#define NCP 32
#define KCH 24            // gram split-K chunks

// ---------------- scratch (device globals; no allocation anywhere) ----------
__device__ float  g_v[NB*NC*NHW];       // 75.5 MB
__device__ float  g_xrev[NB*NC*NHW];    // 75.5 MB  x with spatially-reversed rows
__device__ float  g_gp[KCH*3*16*128*128]; // 75.5 MB gram partials
__device__ float  g_S[NB*256*256];
__device__ float  g_M[NB*256*256];
__device__ float  g_P[NB*256*256];
__device__ float  g_Gf[NB*256*256];
__device__ float  g_m[NB*256];
__device__ float  g_nq[NB*256], g_nk[NB*256];
__device__ float  g_w1m[NB*256], g_w2m[NB*256];
__device__ float2 g_Chat[64*1024];
__device__ float2 g_gtab[96*96];
__device__ float2 g_Tt[NB*NC*NHW];      // 151 MB [ch][a][r]
__device__ float  g_R [NB*NC*NHW];

// ---------------- fp32 SGEMM: Y[b][o][s] = sum_c W[o][c] X[b][c][s] (+bias) --
__global__ void __launch_bounds__(256) k_gemm(
    const float* __restrict__ X, const float* __restrict__ W,
    const float* __restrict__ bias, float* __restrict__ Y)
{
    __shared__ __align__(16) float Ws[8][132];
    __shared__ __align__(16) float Xs[8][132];
    const int t  = threadIdx.x;
    const int s0 = blockIdx.x * 128;
    const int o0 = blockIdx.y * 128;
    const int b  = blockIdx.z;
    const int tx = t & 15, ty = t >> 4;
    const float* Xb = X + (size_t)b * NC * NHW;

    float acc[8][8];
#pragma unroll
    for (int i = 0; i < 8; i++)
#pragma unroll
        for (int j = 0; j < 8; j++) acc[i][j] = 0.f;

    const int wi = t >> 1, wk = (t & 1) * 4;
    const int xr = t >> 5, xc = (t & 31) * 4;

    for (int kc = 0; kc < 256; kc += 8) {
        float4 w4 = *(const float4*)&W[(o0 + wi) * 256 + kc + wk];
        float4 x4 = *(const float4*)&Xb[(size_t)(kc + xr) * NHW + s0 + xc];
        __syncthreads();
        Ws[wk + 0][wi] = w4.x; Ws[wk + 1][wi] = w4.y;
        Ws[wk + 2][wi] = w4.z; Ws[wk + 3][wi] = w4.w;
        *(float4*)&Xs[xr][xc] = x4;
        __syncthreads();
#pragma unroll
        for (int kk = 0; kk < 8; kk++) {
            float a[8], bb[8];
            *(float4*)&a[0]  = *(float4*)&Ws[kk][ty * 4];
            *(float4*)&a[4]  = *(float4*)&Ws[kk][64 + ty * 4];
            *(float4*)&bb[0] = *(float4*)&Xs[kk][tx * 4];
            *(float4*)&bb[4] = *(float4*)&Xs[kk][64 + tx * 4];
#pragma unroll
            for (int i = 0; i < 8; i++)
#pragma unroll
                for (int j = 0; j < 8; j++) acc[i][j] += a[i] * bb[j];
        }
    }
#pragma unroll
    for (int i = 0; i < 8; i++) {
        int o = o0 + ((i < 4) ? ty * 4 + i : 64 + ty * 4 + i - 4);
        float bv = bias ? bias[o] : 0.f;
        float* yp = Y + (size_t)(b * NC + o) * NHW + s0;
        float4 v0 = make_float4(acc[i][0] + bv, acc[i][1] + bv, acc[i][2] + bv, acc[i][3] + bv);
        float4 v1 = make_float4(acc[i][4] + bv, acc[i][5] + bv, acc[i][6] + bv, acc[i][7] + bv);
        *(float4*)&yp[tx * 4]      = v0;
        *(float4*)&yp[64 + tx * 4] = v1;
    }
}

// ---------------- reversed copy: xrev[c][y*96+x] = x[c][ry*96+rx] ------------
__global__ void __launch_bounds__(256) k_revx(const float* __restrict__ X)
{
    const int ch = blockIdx.x;              // 0..2047
    const int seg = blockIdx.y;             // 0..8  (1024 each)
    const float* src = X + (size_t)ch * NHW;
    float* dst = g_xrev + (size_t)ch * NHW;
    int s = seg * 1024 + threadIdx.x;
#pragma unroll
    for (int i = 0; i < 4; i++, s += 256) {
        int y = s / 96, x = s - y * 96;
        int ry = (y == 0) ? 0 : 96 - y;
        int rx = (x == 0) ? 0 : 96 - x;
        dst[s] = src[ry * 96 + rx];
    }
}

// ---------------- m[b][c] = sum_s x[b][c][s] ----------------
__global__ void __launch_bounds__(256) k_xsum(const float* __restrict__ X)
{
    const int bc = blockIdx.x;
    const float4* x4 = (const float4*)(X + (size_t)bc * NHW);
    float s = 0.f;
    for (int i = threadIdx.x; i < NHW / 4; i += 256) {
        float4 a = x4[i]; s += a.x + a.y + a.z + a.w;
    }
#pragma unroll
    for (int o = 16; o; o >>= 1) s += __shfl_xor_sync(0xffffffff, s, o);
    __shared__ float sb[8];
    int w = threadIdx.x >> 5;
    if ((threadIdx.x & 31) == 0) sb[w] = s;
    __syncthreads();
    if (threadIdx.x == 0) {
        float a = 0.f;
        for (int i = 0; i < 8; i++) a += sb[i];
        g_m[bc] = a;
    }
}

// ---------------- Gram GEMM with partial tiles -------------------------------
// grid (KCH sch, 3 pr, 16 b*2+mat). 128x128 tile, 8x8/thread, all loads float4.
__global__ void __launch_bounds__(256) k_gram3(const float* __restrict__ X)
{
    const int sch = blockIdx.x, pr = blockIdx.y;
    const int b = blockIdx.z >> 1, mat = blockIdx.z & 1;
    const int ci = (pr == 2) ? 1 : 0;
    const int dj = (pr == 0) ? 0 : 1;
    __shared__ __align__(16) float xa[8][132];
    __shared__ __align__(16) float xd[8][132];
    const float* Xa = X + (size_t)b * NC * NHW;
    const float* Xd = (mat ? g_xrev : X) + (size_t)b * NC * NHW;
    const int t = threadIdx.x;
    const int tx = t & 15, ty = t >> 4;
    const int r2 = t >> 1, h4 = (t & 1) * 4;

    float acc[8][8];
#pragma unroll
    for (int i = 0; i < 8; i++)
#pragma unroll
        for (int j = 0; j < 8; j++) acc[i][j] = 0.f;

    for (int ks = 0; ks < NHW / (KCH * 8); ks++) {
        const int s0 = sch * (NHW / KCH) + ks * 8;
        float4 av = *(const float4*)&Xa[(size_t)(ci * 128 + r2) * NHW + s0 + h4];
        float4 dv = *(const float4*)&Xd[(size_t)(dj * 128 + r2) * NHW + s0 + h4];
        __syncthreads();
        xa[h4 + 0][r2] = av.x; xa[h4 + 1][r2] = av.y;
        xa[h4 + 2][r2] = av.z; xa[h4 + 3][r2] = av.w;
        xd[h4 + 0][r2] = dv.x; xd[h4 + 1][r2] = dv.y;
        xd[h4 + 2][r2] = dv.z; xd[h4 + 3][r2] = dv.w;
        __syncthreads();
#pragma unroll
        for (int kk = 0; kk < 8; kk++) {
            float a[8], bb[8];
            *(float4*)&a[0]  = *(float4*)&xa[kk][ty * 4];
            *(float4*)&a[4]  = *(float4*)&xa[kk][64 + ty * 4];
            *(float4*)&bb[0] = *(float4*)&xd[kk][tx * 4];
            *(float4*)&bb[4] = *(float4*)&xd[kk][64 + tx * 4];
#pragma unroll
            for (int i = 0; i < 8; i++)
#pragma unroll
                for (int j = 0; j < 8; j++) acc[i][j] += a[i] * bb[j];
        }
    }
    // write 128x128 partial tile, coalesced
    float* Out = g_gp + ((size_t)(blockIdx.z * 3 + pr) * KCH + sch) * 16384;
#pragma unroll
    for (int i = 0; i < 8; i++) {
        int ri = (i < 4) ? ty * 4 + i : 64 + ty * 4 + i - 4;
        *(float4*)&Out[ri * 128 + tx * 4]      = make_float4(acc[i][0], acc[i][1], acc[i][2], acc[i][3]);
        *(float4*)&Out[ri * 128 + 64 + tx * 4] = make_float4(acc[i][4], acc[i][5], acc[i][6], acc[i][7]);
    }
}

// ---------------- reduce partials into S / M --------------------------------
// grid (64, 3, 16): 64*256 = 16384 elems per (pr, bm)
__global__ void __launch_bounds__(256) k_gred()
{
    const int pr = blockIdx.y, bm = blockIdx.z;
    const int b = bm >> 1, mat = bm & 1;
    const int ci = (pr == 2) ? 1 : 0;
    const int dj = (pr == 0) ? 0 : 1;
    const int off = blockIdx.x * 256 + threadIdx.x;
    const float* Pp = g_gp + (size_t)(bm * 3 + pr) * KCH * 16384 + off;
    float s = 0.f;
#pragma unroll
    for (int c = 0; c < KCH; c++) s += Pp[c * 16384];
    int il = off >> 7, jl = off & 127;
    float* Out = (mat ? g_M : g_S) + b * 65536;
    Out[(ci * 128 + il) * 256 + dj * 128 + jl] = s;
}

// ---------------- mirror lower-left 128x128 block from upper-right ----------
__global__ void k_mirror()
{
    const int bm = blockIdx.y;
    float* Out = (bm & 1 ? g_M : g_S) + (bm >> 1) * 65536;
    int idx = blockIdx.x * 256 + threadIdx.x;
    int i = idx >> 7, jl = idx & 127;
    Out[(128 + jl) * 256 + i] = Out[i * 256 + 128 + jl];
}

// ---------------- P[b] = M[b] * W2^T ----------------------------------------
__global__ void __launch_bounds__(256) k_mmA(const float* __restrict__ Wg)
{
    const int j0 = blockIdx.x * 64, i0 = blockIdx.y * 64, b = blockIdx.z;
    const float* A = g_M + b * 65536;
    float* C = g_P + b * 65536;
    __shared__ float As[16][68];
    __shared__ float Bs[16][68];
    const int t = threadIdx.x;
    const int it = (t >> 4) * 4, jt = (t & 15) * 4;
    float acc[4][4];
#pragma unroll
    for (int i = 0; i < 4; i++)
#pragma unroll
        for (int j = 0; j < 4; j++) acc[i][j] = 0.f;
    for (int kc = 0; kc < 256; kc += 16) {
        __syncthreads();
#pragma unroll
        for (int i = 0; i < 4; i++) {
            int idx = i * 256 + t;
            int r = idx >> 4, kk = idx & 15;
            As[kk][r] = A[(i0 + r) * 256 + kc + kk];
            Bs[kk][r] = Wg[(j0 + r) * 256 + kc + kk];
        }
        __syncthreads();
#pragma unroll
        for (int kk = 0; kk < 16; kk++) {
            float a[4], bb[4];
            *(float4*)a  = *(float4*)&As[kk][it];
            *(float4*)bb = *(float4*)&Bs[kk][jt];
#pragma unroll
            for (int i = 0; i < 4; i++)
#pragma unroll
                for (int j = 0; j < 4; j++) acc[i][j] += a[i] * bb[j];
        }
    }
#pragma unroll
    for (int i = 0; i < 4; i++)
#pragma unroll
        for (int j = 0; j < 4; j++)
            C[(i0 + it + i) * 256 + j0 + jt + j] = acc[i][j];
}

// ---------------- C[b] = Ag * B[b] ------------------------------------------
__global__ void __launch_bounds__(256) k_mmB(
    const float* __restrict__ Ag, const float* __restrict__ Bb, float* __restrict__ Cb)
{
    const int j0 = blockIdx.x * 64, i0 = blockIdx.y * 64, b = blockIdx.z;
    const float* B = Bb + b * 65536;
    float* C = Cb + b * 65536;
    __shared__ float As[16][68];
    __shared__ float Bs[16][68];
    const int t = threadIdx.x;
    const int it = (t >> 4) * 4, jt = (t & 15) * 4;
    float acc[4][4];
#pragma unroll
    for (int i = 0; i < 4; i++)
#pragma unroll
        for (int j = 0; j < 4; j++) acc[i][j] = 0.f;
    for (int kc = 0; kc < 256; kc += 16) {
        __syncthreads();
#pragma unroll
        for (int i = 0; i < 4; i++) {
            int idx = i * 256 + t;
            int r = idx >> 4, kk = idx & 15;
            As[kk][r] = Ag[(i0 + r) * 256 + kc + kk];
        }
#pragma unroll
        for (int i = 0; i < 4; i++) {
            int idx = i * 256 + t;
            int kk = idx >> 6, j = idx & 63;
            Bs[kk][j] = B[(kc + kk) * 256 + j0 + j];
        }
        __syncthreads();
#pragma unroll
        for (int kk = 0; kk < 16; kk++) {
            float a[4], bb[4];
            *(float4*)a  = *(float4*)&As[kk][it];
            *(float4*)bb = *(float4*)&Bs[kk][jt];
#pragma unroll
            for (int i = 0; i < 4; i++)
#pragma unroll
                for (int j = 0; j < 4; j++) acc[i][j] += a[i] * bb[j];
        }
    }
#pragma unroll
    for (int i = 0; i < 4; i++)
#pragma unroll
        for (int j = 0; j < 4; j++)
            C[(i0 + it + i) * 256 + j0 + jt + j] = acc[i][j];
}

// ---------------- row-dot: norms + W*m --------------------------------------
__global__ void __launch_bounds__(256) k_rowdot(
    const float* __restrict__ U, const float* __restrict__ W,
    const float* __restrict__ bias, float* __restrict__ outN, float* __restrict__ outWM)
{
    const int bC = blockIdx.x;
    const int b = bC >> 8, C = bC & 255;
    const int t = threadIdx.x;
    float wv = W[C * 256 + t];
    float un = U[(size_t)b * 65536 + C * 256 + t] * wv;
    float wm = wv * g_m[b * 256 + t];
#pragma unroll
    for (int o = 16; o; o >>= 1) {
        un += __shfl_xor_sync(0xffffffff, un, o);
        wm += __shfl_xor_sync(0xffffffff, wm, o);
    }
    __shared__ float s1[8], s2[8];
    int w = t >> 5;
    if ((t & 31) == 0) { s1[w] = un; s2[w] = wm; }
    __syncthreads();
    if (t == 0) {
        float a = 0.f, c = 0.f;
        for (int i = 0; i < 8; i++) { a += s1[i]; c += s2[i]; }
        float bc = bias[C];
        outWM[bC] = c;
        outN[bC] = a + 2.f * bc * c + 9216.f * bc * bc;
    }
}

// ---------------- attn: logits, softmax, build Chat -------------------------
__global__ void __launch_bounds__(256) k_attn2(
    const float* __restrict__ b1, const float* __restrict__ b2,
    const float* __restrict__ temperature)
{
    const int bh = blockIdx.x;
    const int b = bh >> 3, h = bh & 7;
    const int ch0 = h * 32;
    __shared__ float A[32][33];
    __shared__ float rq[32], rk[32], sw1m[32], sw2m[32], sb1[32], sb2[32];
    __shared__ float2 tab[32];
    const int t = threadIdx.x;
    if (t < 32) {
        int C = b * 256 + ch0 + t;
        rq[t] = rsqrtf(g_nq[C]);
        rk[t] = rsqrtf(g_nk[C]);
        sw1m[t] = g_w1m[C];
        sw2m[t] = g_w2m[C];
        sb1[t] = b1[ch0 + t];
        sb2[t] = b2[ch0 + t];
        float ang = 6.283185307179586f * (float)t / 32.0f;
        tab[t] = make_float2(cosf(ang), sinf(ang));
    }
    __syncthreads();
    const float ts = temperature[h];
    const int w = t >> 5, lane = t & 31;
    for (int r = w; r < 32; r += 8) {
        float Gv = g_Gf[(size_t)b * 65536 + (ch0 + r) * 256 + ch0 + lane];
        float L = (Gv + sw1m[r] * sb2[lane] + sb1[r] * sw2m[lane]
                   + 9216.f * sb1[r] * sb2[lane]) * rq[r] * rk[lane] * ts;
        float m = L;
#pragma unroll
        for (int o = 16; o; o >>= 1) m = fmaxf(m, __shfl_xor_sync(0xffffffff, m, o));
        float e = expf(L - m);
        float s = e;
#pragma unroll
        for (int o = 16; o; o >>= 1) s += __shfl_xor_sync(0xffffffff, s, o);
        A[r][lane] = e / s;
    }
    __syncthreads();
    for (int idx = t; idx < 1024; idx += 256) {
        int e = idx >> 5, d = idx & 31;
        float re = 0.f, im = 0.f;
#pragma unroll 8
        for (int c = 0; c < 32; c++) {
            float a = A[c][d];
            float2 tb = tab[(c * e) & 31];
            re += a * tb.x; im += a * tb.y;
        }
        re *= (1.0f / 32.0f); im *= (1.0f / 32.0f);
        if (e == 0) im += (1.0f / 32.0f);
        g_Chat[bh * 1024 + idx] = make_float2(re, im);
    }
}

// ---------------- g table (stable half-angle form) ----------------
__global__ void k_gtab()
{
    int idx = blockIdx.x * 256 + threadIdx.x;
    if (idx >= 96 * 96) return;
    int hr = idx / 96, tt = idx - hr * 96;
    float2 g;
    if (hr == 0) {
        g = make_float2(tt == 0 ? 1.f : 0.f, 0.f);
    } else {
        const float PI = 3.14159265358979323846f;
        float h1 = PI * (float)hr / 96.0f;
        float h2 = PI * (96.0f * (float)tt + (float)hr) / 9216.0f;
        float r = sinf(h1) / (96.0f * sinf(h2));
        float psi = h1 - h2;
        g = make_float2(r * cosf(psi), r * sinf(psi));
    }
    g_gtab[idx] = g;
}

// ---------------- v -> Tt directly (fused transpose) ------------------------
__global__ void __launch_bounds__(256) k_vtrans2()
{
    const int ch0 = blockIdx.x * 2, r0 = blockIdx.y * 32;
    __shared__ float  vsm[2 * 32 * 96];
    __shared__ float2 gsm[32 * 96];
    const int t = threadIdx.x;
#pragma unroll
    for (int i = 0; i < 6; i++) {
        int idx = i * 256 + t;
        int row = idx / 24, c4 = idx % 24;
        int ch = row >> 5, rr = row & 31;
        float4 v = *(const float4*)&g_v[(size_t)(ch0 + ch) * NHW + (r0 + rr) * 96 + c4 * 4];
        *(float4*)&vsm[(ch * 32 + rr) * 96 + c4 * 4] = v;
    }
#pragma unroll
    for (int i = 0; i < 12; i++) {
        int idx = i * 256 + t;
        int rr = idx / 96, c = idx % 96;
        gsm[rr * 96 + c] = g_gtab[(r0 + rr) * 96 + c];
    }
    __syncthreads();
    const int lane = t & 31, a0 = (t >> 5) * 12;
    float ar[2][12], ai[2][12];
#pragma unroll
    for (int c = 0; c < 2; c++)
#pragma unroll
        for (int j = 0; j < 12; j++) { ar[c][j] = 0.f; ai[c][j] = 0.f; }

    const float*  v0p = &vsm[lane * 96];
    const float*  v1p = &vsm[(32 + lane) * 96];
    const float2* gp  = &gsm[lane * 96];
    for (int w0 = 0; w0 < 96; w0++) {
        int we = w0 + lane; if (we >= 96) we -= 96;
        float v0 = v0p[we], v1 = v1p[we];
        int base = a0 - we; if (base < 0) base += 96;
#pragma unroll
        for (int j = 0; j < 12; j++) {
            int ii = base + j; if (ii >= 96) ii -= 96;
            float2 g = gp[ii];
            ar[0][j] += v0 * g.x; ai[0][j] += v0 * g.y;
            ar[1][j] += v1 * g.x; ai[1][j] += v1 * g.y;
        }
    }
#pragma unroll
    for (int c = 0; c < 2; c++)
#pragma unroll
        for (int j = 0; j < 12; j++)
            g_Tt[(size_t)(ch0 + c) * NHW + (a0 + j) * 96 + r0 + lane] =
                make_float2(ar[c][j], ai[c][j]);
}

// ---------------- mix: R[bh*32+e][s] = | sum_d Chat[e][d] * Tt[bh*32+d][s] |
__global__ void __launch_bounds__(256) k_mix()
{
    const int s0 = blockIdx.x * 128;
    const int bh = blockIdx.y;
    __shared__ float2 Ch[1024];
    __shared__ float2 Ts[32][128];
    const int t = threadIdx.x;
    for (int i = t; i < 1024; i += 256) Ch[i] = g_Chat[bh * 1024 + i];
    for (int i = t; i < 4096; i += 256) {
        int d = i >> 7, j = i & 127;
        Ts[d][j] = g_Tt[(size_t)(bh * 32 + d) * NHW + s0 + j];
    }
    __syncthreads();
    const int sl = t & 63, eg = t >> 6;
    float ar0[8], ai0[8], ar1[8], ai1[8];
#pragma unroll
    for (int i = 0; i < 8; i++) { ar0[i] = ai0[i] = ar1[i] = ai1[i] = 0.f; }

    for (int d = 0; d < 32; d++) {
        float2 t0 = Ts[d][sl];
        float2 t1 = Ts[d][sl + 64];
#pragma unroll
        for (int i = 0; i < 8; i++) {
            float2 c = Ch[(eg * 8 + i) * 32 + d];
            ar0[i] += c.x * t0.x - c.y * t0.y;
            ai0[i] += c.x * t0.y + c.y * t0.x;
            ar1[i] += c.x * t1.x - c.y * t1.y;
            ai1[i] += c.x * t1.y + c.y * t1.x;
        }
    }
#pragma unroll
    for (int i = 0; i < 8; i++) {
        int row = bh * 32 + eg * 8 + i;
        g_R[(size_t)row * NHW + s0 + sl]      = sqrtf(ar0[i] * ar0[i] + ai0[i] * ai0[i]);
        g_R[(size_t)row * NHW + s0 + sl + 64] = sqrtf(ar1[i] * ar1[i] + ai1[i] * ai1[i]);
    }
}

// ---------------- launch ----------------
extern "C" void kernel_launch(void* const* d_in, const int* in_sizes, int n_in,
                              void* d_out, int out_size)
{
    const float* x    = (const float*)d_in[0];
    const float* w1   = (const float*)d_in[1];
    const float* b1   = (const float*)d_in[2];
    const float* w2   = (const float*)d_in[3];
    const float* b2   = (const float*)d_in[4];
    const float* w3   = (const float*)d_in[5];
    const float* b3   = (const float*)d_in[6];
    const float* wo   = (const float*)d_in[7];
    const float* temp = (const float*)d_in[8];
    float* out = (float*)d_out;

    float *vp = nullptr, *Rp = nullptr, *Pp = nullptr, *Sp = nullptr, *Gfp = nullptr;
    float *nqp = nullptr, *nkp = nullptr, *w1mp = nullptr, *w2mp = nullptr;
    cudaGetSymbolAddress((void**)&vp,  g_v);
    cudaGetSymbolAddress((void**)&Rp,  g_R);
    cudaGetSymbolAddress((void**)&Pp,  g_P);
    cudaGetSymbolAddress((void**)&Sp,  g_S);
    cudaGetSymbolAddress((void**)&Gfp, g_Gf);
    cudaGetSymbolAddress((void**)&nqp,  g_nq);
    cudaGetSymbolAddress((void**)&nkp,  g_nk);
    cudaGetSymbolAddress((void**)&w1mp, g_w1m);
    cudaGetSymbolAddress((void**)&w2mp, g_w2m);

    dim3 gg(72, 2, 8);
    dim3 gm(4, 4, 8);

    k_gemm   <<<gg, 256>>>(x, w3, b3, vp);              // v
    k_revx   <<<dim3(2048, 9), 256>>>(x);
    k_xsum   <<<2048, 256>>>(x);
    k_gram3  <<<dim3(KCH, 3, 16), 256>>>(x);            // partial tiles
    k_gred   <<<dim3(64, 3, 16), 256>>>();              // -> S, M
    k_mirror <<<dim3(64, 16), 256>>>();
    k_mmA    <<<gm, 256>>>(w2);                         // P = M * W2^T
    k_mmB    <<<gm, 256>>>(w1, Pp, Gfp);                // Gf = W1 * P
    k_mmB    <<<gm, 256>>>(w1, Sp, Pp);                 // U1 = W1 * S
    k_rowdot <<<2048, 256>>>(Pp, w1, b1, nqp, w1mp);
    k_mmB    <<<gm, 256>>>(w2, Sp, Pp);                 // U2 = W2 * S
    k_rowdot <<<2048, 256>>>(Pp, w2, b2, nkp, w2mp);
    k_gtab   <<<36, 256>>>();
    k_attn2  <<<64, 256>>>(b1, b2, temp);
    k_vtrans2<<<dim3(1024, 3), 256>>>();
    k_mix    <<<dim3(72, 64), 256>>>();
    k_gemm   <<<gg, 256>>>(Rp, wo, nullptr, out);
}

// round 8
// speedup vs baseline: 1.9296x; 1.3514x over previous
#include <cuda_runtime.h>
#include <math.h>
#include <stdint.h>

#define NB 8
#define NC 256
#define NHW 9216
#define NHEAD 8
#define NCP 32
#define KCH 24            // gram split-K chunks

// ---------------- scratch (device globals; no allocation anywhere) ----------
__device__ float  g_v[NB*NC*NHW];       // 75.5 MB
__device__ float  g_xrev[NB*NC*NHW];    // 75.5 MB
__device__ float  g_gp[KCH*3*16*128*128]; // 75.5 MB gram partials
__device__ float  g_S[NB*256*256];
__device__ float  g_M[NB*256*256];
__device__ float  g_P[NB*256*256];
__device__ float  g_Gf[NB*256*256];
__device__ float  g_m[NB*256];
__device__ float  g_nq[NB*256], g_nk[NB*256];
__device__ float  g_w1m[NB*256], g_w2m[NB*256];
__device__ float2 g_Chat[64*1024];
__device__ float2 g_gtab[96*96];
__device__ float2 g_Tt[NB*NC*NHW];      // 151 MB [ch][a][r]
__device__ float  g_R [NB*NC*NHW];

// ---------------- tf32 helpers ----------------------------------------------
__device__ __forceinline__ uint32_t f2tf32(float x) {
    uint32_t r;
    asm("cvt.rna.tf32.f32 %0, %1;" : "=r"(r) : "f"(x));
    return r;
}
__device__ __forceinline__ void mma_tf32(float* c, const uint32_t* a, const uint32_t* b) {
    asm volatile(
        "mma.sync.aligned.m16n8k8.row.col.f32.tf32.tf32.f32 "
        "{%0,%1,%2,%3}, {%4,%5,%6,%7}, {%8,%9}, {%0,%1,%2,%3};"
        : "+f"(c[0]), "+f"(c[1]), "+f"(c[2]), "+f"(c[3])
        : "r"(a[0]), "r"(a[1]), "r"(a[2]), "r"(a[3]), "r"(b[0]), "r"(b[1]));
}

// ---------------- tf32 GEMM: Y[b][o][s] = sum_c W[o][c] X[b][c][s] (+bias) ---
// 128x128 block, 8 warps as 2(M)x4(N), warp tile 64x32, K-chunk 8.
__global__ void __launch_bounds__(256) k_gemm_tf32(
    const float* __restrict__ X, const float* __restrict__ W,
    const float* __restrict__ bias, float* __restrict__ Y)
{
    __shared__ __align__(16) float Ws[8][132];   // [k][m]
    __shared__ __align__(16) float Xs[8][132];   // [k][n]
    const int t  = threadIdx.x;
    const int s0 = blockIdx.x * 128;
    const int o0 = blockIdx.y * 128;
    const int b  = blockIdx.z;
    const int warp = t >> 5, lane = t & 31;
    const int gid = lane >> 2, tig = lane & 3;
    const int mrow = (warp >> 2) * 64;
    const int ncol = (warp & 3) * 32;
    const float* Xb = X + (size_t)b * NC * NHW;

    const int wi = t >> 1, wk = (t & 1) * 4;
    const int xr = t >> 5, xc = (t & 31) * 4;

    float c[4][4][4];
#pragma unroll
    for (int i = 0; i < 4; i++)
#pragma unroll
        for (int j = 0; j < 4; j++)
#pragma unroll
            for (int q = 0; q < 4; q++) c[i][j][q] = 0.f;

    for (int kc = 0; kc < 256; kc += 8) {
        float4 w4 = *(const float4*)&W[(o0 + wi) * 256 + kc + wk];
        float4 x4 = *(const float4*)&Xb[(size_t)(kc + xr) * NHW + s0 + xc];
        __syncthreads();
        Ws[wk + 0][wi] = w4.x; Ws[wk + 1][wi] = w4.y;
        Ws[wk + 2][wi] = w4.z; Ws[wk + 3][wi] = w4.w;
        *(float4*)&Xs[xr][xc] = x4;
        __syncthreads();

        uint32_t afr[4][4], bfr[4][2];
#pragma unroll
        for (int mt = 0; mt < 4; mt++) {
            int m0 = mrow + mt * 16;
            afr[mt][0] = f2tf32(Ws[tig][m0 + gid]);
            afr[mt][1] = f2tf32(Ws[tig][m0 + gid + 8]);
            afr[mt][2] = f2tf32(Ws[tig + 4][m0 + gid]);
            afr[mt][3] = f2tf32(Ws[tig + 4][m0 + gid + 8]);
        }
#pragma unroll
        for (int nt = 0; nt < 4; nt++) {
            int n0 = ncol + nt * 8;
            bfr[nt][0] = f2tf32(Xs[tig][n0 + gid]);
            bfr[nt][1] = f2tf32(Xs[tig + 4][n0 + gid]);
        }
#pragma unroll
        for (int mt = 0; mt < 4; mt++)
#pragma unroll
            for (int nt = 0; nt < 4; nt++)
                mma_tf32(c[mt][nt], afr[mt], bfr[nt]);
    }

#pragma unroll
    for (int mt = 0; mt < 4; mt++) {
        int oa = o0 + mrow + mt * 16 + gid;
        int ob = oa + 8;
        float ba  = bias ? bias[oa] : 0.f;
        float bb_ = bias ? bias[ob] : 0.f;
        float* ya = Y + (size_t)(b * NC + oa) * NHW + s0;
        float* yb = Y + (size_t)(b * NC + ob) * NHW + s0;
#pragma unroll
        for (int nt = 0; nt < 4; nt++) {
            int sc = ncol + nt * 8 + tig * 2;
            *(float2*)&ya[sc] = make_float2(c[mt][nt][0] + ba,  c[mt][nt][1] + ba);
            *(float2*)&yb[sc] = make_float2(c[mt][nt][2] + bb_, c[mt][nt][3] + bb_);
        }
    }
}

// ---------------- reversed copy ----------------------------------------------
__global__ void __launch_bounds__(256) k_revx(const float* __restrict__ X)
{
    const int ch = blockIdx.x;
    const int seg = blockIdx.y;
    const float* src = X + (size_t)ch * NHW;
    float* dst = g_xrev + (size_t)ch * NHW;
    int s = seg * 1024 + threadIdx.x;
#pragma unroll
    for (int i = 0; i < 4; i++, s += 256) {
        int y = s / 96, x = s - y * 96;
        int ry = (y == 0) ? 0 : 96 - y;
        int rx = (x == 0) ? 0 : 96 - x;
        dst[s] = src[ry * 96 + rx];
    }
}

// ---------------- m[b][c] = sum_s x[b][c][s] ----------------
__global__ void __launch_bounds__(256) k_xsum(const float* __restrict__ X)
{
    const int bc = blockIdx.x;
    const float4* x4 = (const float4*)(X + (size_t)bc * NHW);
    float s = 0.f;
    for (int i = threadIdx.x; i < NHW / 4; i += 256) {
        float4 a = x4[i]; s += a.x + a.y + a.z + a.w;
    }
#pragma unroll
    for (int o = 16; o; o >>= 1) s += __shfl_xor_sync(0xffffffff, s, o);
    __shared__ float sb[8];
    int w = threadIdx.x >> 5;
    if ((threadIdx.x & 31) == 0) sb[w] = s;
    __syncthreads();
    if (threadIdx.x == 0) {
        float a = 0.f;
        for (int i = 0; i < 8; i++) a += sb[i];
        g_m[bc] = a;
    }
}

// ---------------- Gram GEMM (tf32 mma), partial tiles ------------------------
__global__ void __launch_bounds__(256) k_gram4(const float* __restrict__ X)
{
    const int sch = blockIdx.x, pr = blockIdx.y;
    const int b = blockIdx.z >> 1, mat = blockIdx.z & 1;
    const int ci = (pr == 2) ? 1 : 0;
    const int dj = (pr == 0) ? 0 : 1;
    __shared__ __align__(16) float xa[8][132];   // [k][m]
    __shared__ __align__(16) float xd[8][132];   // [k][n]
    const float* Xa = X + (size_t)b * NC * NHW;
    const float* Xd = (mat ? g_xrev : X) + (size_t)b * NC * NHW;
    const int t = threadIdx.x;
    const int warp = t >> 5, lane = t & 31;
    const int gid = lane >> 2, tig = lane & 3;
    const int mrow = (warp >> 2) * 64;
    const int ncol = (warp & 3) * 32;
    const int r2 = t >> 1, h4 = (t & 1) * 4;

    float c[4][4][4];
#pragma unroll
    for (int i = 0; i < 4; i++)
#pragma unroll
        for (int j = 0; j < 4; j++)
#pragma unroll
            for (int q = 0; q < 4; q++) c[i][j][q] = 0.f;

    for (int ks = 0; ks < NHW / (KCH * 8); ks++) {
        const int s0 = sch * (NHW / KCH) + ks * 8;
        float4 av = *(const float4*)&Xa[(size_t)(ci * 128 + r2) * NHW + s0 + h4];
        float4 dv = *(const float4*)&Xd[(size_t)(dj * 128 + r2) * NHW + s0 + h4];
        __syncthreads();
        xa[h4 + 0][r2] = av.x; xa[h4 + 1][r2] = av.y;
        xa[h4 + 2][r2] = av.z; xa[h4 + 3][r2] = av.w;
        xd[h4 + 0][r2] = dv.x; xd[h4 + 1][r2] = dv.y;
        xd[h4 + 2][r2] = dv.z; xd[h4 + 3][r2] = dv.w;
        __syncthreads();

        uint32_t afr[4][4], bfr[4][2];
#pragma unroll
        for (int mt = 0; mt < 4; mt++) {
            int m0 = mrow + mt * 16;
            afr[mt][0] = f2tf32(xa[tig][m0 + gid]);
            afr[mt][1] = f2tf32(xa[tig][m0 + gid + 8]);
            afr[mt][2] = f2tf32(xa[tig + 4][m0 + gid]);
            afr[mt][3] = f2tf32(xa[tig + 4][m0 + gid + 8]);
        }
#pragma unroll
        for (int nt = 0; nt < 4; nt++) {
            int n0 = ncol + nt * 8;
            bfr[nt][0] = f2tf32(xd[tig][n0 + gid]);
            bfr[nt][1] = f2tf32(xd[tig + 4][n0 + gid]);
        }
#pragma unroll
        for (int mt = 0; mt < 4; mt++)
#pragma unroll
            for (int nt = 0; nt < 4; nt++)
                mma_tf32(c[mt][nt], afr[mt], bfr[nt]);
    }

    float* Out = g_gp + ((size_t)(blockIdx.z * 3 + pr) * KCH + sch) * 16384;
#pragma unroll
    for (int mt = 0; mt < 4; mt++) {
        int ra = mrow + mt * 16 + gid;
        int rb = ra + 8;
#pragma unroll
        for (int nt = 0; nt < 4; nt++) {
            int col = ncol + nt * 8 + tig * 2;
            *(float2*)&Out[ra * 128 + col] = make_float2(c[mt][nt][0], c[mt][nt][1]);
            *(float2*)&Out[rb * 128 + col] = make_float2(c[mt][nt][2], c[mt][nt][3]);
        }
    }
}

// ---------------- reduce partials into S / M --------------------------------
__global__ void __launch_bounds__(256) k_gred()
{
    const int pr = blockIdx.y, bm = blockIdx.z;
    const int b = bm >> 1, mat = bm & 1;
    const int ci = (pr == 2) ? 1 : 0;
    const int dj = (pr == 0) ? 0 : 1;
    const int off = blockIdx.x * 256 + threadIdx.x;
    const float* Pp = g_gp + (size_t)(bm * 3 + pr) * KCH * 16384 + off;
    float s = 0.f;
#pragma unroll
    for (int c = 0; c < KCH; c++) s += Pp[c * 16384];
    int il = off >> 7, jl = off & 127;
    float* Out = (mat ? g_M : g_S) + b * 65536;
    Out[(ci * 128 + il) * 256 + dj * 128 + jl] = s;
}

// ---------------- mirror lower-left 128x128 block ---------------------------
__global__ void k_mirror()
{
    const int bm = blockIdx.y;
    float* Out = (bm & 1 ? g_M : g_S) + (bm >> 1) * 65536;
    int idx = blockIdx.x * 256 + threadIdx.x;
    int i = idx >> 7, jl = idx & 127;
    Out[(128 + jl) * 256 + i] = Out[i * 256 + 128 + jl];
}

// ---------------- P[b] = M[b] * W2^T ----------------------------------------
__global__ void __launch_bounds__(256) k_mmA(const float* __restrict__ Wg)
{
    const int j0 = blockIdx.x * 64, i0 = blockIdx.y * 64, b = blockIdx.z;
    const float* A = g_M + b * 65536;
    float* C = g_P + b * 65536;
    __shared__ float As[16][68];
    __shared__ float Bs[16][68];
    const int t = threadIdx.x;
    const int it = (t >> 4) * 4, jt = (t & 15) * 4;
    float acc[4][4];
#pragma unroll
    for (int i = 0; i < 4; i++)
#pragma unroll
        for (int j = 0; j < 4; j++) acc[i][j] = 0.f;
    for (int kc = 0; kc < 256; kc += 16) {
        __syncthreads();
#pragma unroll
        for (int i = 0; i < 4; i++) {
            int idx = i * 256 + t;
            int r = idx >> 4, kk = idx & 15;
            As[kk][r] = A[(i0 + r) * 256 + kc + kk];
            Bs[kk][r] = Wg[(j0 + r) * 256 + kc + kk];
        }
        __syncthreads();
#pragma unroll
        for (int kk = 0; kk < 16; kk++) {
            float a[4], bb[4];
            *(float4*)a  = *(float4*)&As[kk][it];
            *(float4*)bb = *(float4*)&Bs[kk][jt];
#pragma unroll
            for (int i = 0; i < 4; i++)
#pragma unroll
                for (int j = 0; j < 4; j++) acc[i][j] += a[i] * bb[j];
        }
    }
#pragma unroll
    for (int i = 0; i < 4; i++)
#pragma unroll
        for (int j = 0; j < 4; j++)
            C[(i0 + it + i) * 256 + j0 + jt + j] = acc[i][j];
}

// ---------------- C[b] = Ag * B[b] ------------------------------------------
__global__ void __launch_bounds__(256) k_mmB(
    const float* __restrict__ Ag, const float* __restrict__ Bb, float* __restrict__ Cb)
{
    const int j0 = blockIdx.x * 64, i0 = blockIdx.y * 64, b = blockIdx.z;
    const float* B = Bb + b * 65536;
    float* C = Cb + b * 65536;
    __shared__ float As[16][68];
    __shared__ float Bs[16][68];
    const int t = threadIdx.x;
    const int it = (t >> 4) * 4, jt = (t & 15) * 4;
    float acc[4][4];
#pragma unroll
    for (int i = 0; i < 4; i++)
#pragma unroll
        for (int j = 0; j < 4; j++) acc[i][j] = 0.f;
    for (int kc = 0; kc < 256; kc += 16) {
        __syncthreads();
#pragma unroll
        for (int i = 0; i < 4; i++) {
            int idx = i * 256 + t;
            int r = idx >> 4, kk = idx & 15;
            As[kk][r] = Ag[(i0 + r) * 256 + kc + kk];
        }
#pragma unroll
        for (int i = 0; i < 4; i++) {
            int idx = i * 256 + t;
            int kk = idx >> 6, j = idx & 63;
            Bs[kk][j] = B[(kc + kk) * 256 + j0 + j];
        }
        __syncthreads();
#pragma unroll
        for (int kk = 0; kk < 16; kk++) {
            float a[4], bb[4];
            *(float4*)a  = *(float4*)&As[kk][it];
            *(float4*)bb = *(float4*)&Bs[kk][jt];
#pragma unroll
            for (int i = 0; i < 4; i++)
#pragma unroll
                for (int j = 0; j < 4; j++) acc[i][j] += a[i] * bb[j];
        }
    }
#pragma unroll
    for (int i = 0; i < 4; i++)
#pragma unroll
        for (int j = 0; j < 4; j++)
            C[(i0 + it + i) * 256 + j0 + jt + j] = acc[i][j];
}

// ---------------- row-dot: norms + W*m --------------------------------------
__global__ void __launch_bounds__(256) k_rowdot(
    const float* __restrict__ U, const float* __restrict__ W,
    const float* __restrict__ bias, float* __restrict__ outN, float* __restrict__ outWM)
{
    const int bC = blockIdx.x;
    const int b = bC >> 8, C = bC & 255;
    const int t = threadIdx.x;
    float wv = W[C * 256 + t];
    float un = U[(size_t)b * 65536 + C * 256 + t] * wv;
    float wm = wv * g_m[b * 256 + t];
#pragma unroll
    for (int o = 16; o; o >>= 1) {
        un += __shfl_xor_sync(0xffffffff, un, o);
        wm += __shfl_xor_sync(0xffffffff, wm, o);
    }
    __shared__ float s1[8], s2[8];
    int w = t >> 5;
    if ((t & 31) == 0) { s1[w] = un; s2[w] = wm; }
    __syncthreads();
    if (t == 0) {
        float a = 0.f, c = 0.f;
        for (int i = 0; i < 8; i++) { a += s1[i]; c += s2[i]; }
        float bc = bias[C];
        outWM[bC] = c;
        outN[bC] = a + 2.f * bc * c + 9216.f * bc * bc;
    }
}

// ---------------- attn: logits, softmax, build Chat -------------------------
__global__ void __launch_bounds__(256) k_attn2(
    const float* __restrict__ b1, const float* __restrict__ b2,
    const float* __restrict__ temperature)
{
    const int bh = blockIdx.x;
    const int b = bh >> 3, h = bh & 7;
    const int ch0 = h * 32;
    __shared__ float A[32][33];
    __shared__ float rq[32], rk[32], sw1m[32], sw2m[32], sb1[32], sb2[32];
    __shared__ float2 tab[32];
    const int t = threadIdx.x;
    if (t < 32) {
        int C = b * 256 + ch0 + t;
        rq[t] = rsqrtf(g_nq[C]);
        rk[t] = rsqrtf(g_nk[C]);
        sw1m[t] = g_w1m[C];
        sw2m[t] = g_w2m[C];
        sb1[t] = b1[ch0 + t];
        sb2[t] = b2[ch0 + t];
        float ang = 6.283185307179586f * (float)t / 32.0f;
        tab[t] = make_float2(cosf(ang), sinf(ang));
    }
    __syncthreads();
    const float ts = temperature[h];
    const int w = t >> 5, lane = t & 31;
    for (int r = w; r < 32; r += 8) {
        float Gv = g_Gf[(size_t)b * 65536 + (ch0 + r) * 256 + ch0 + lane];
        float L = (Gv + sw1m[r] * sb2[lane] + sb1[r] * sw2m[lane]
                   + 9216.f * sb1[r] * sb2[lane]) * rq[r] * rk[lane] * ts;
        float m = L;
#pragma unroll
        for (int o = 16; o; o >>= 1) m = fmaxf(m, __shfl_xor_sync(0xffffffff, m, o));
        float e = expf(L - m);
        float s = e;
#pragma unroll
        for (int o = 16; o; o >>= 1) s += __shfl_xor_sync(0xffffffff, s, o);
        A[r][lane] = e / s;
    }
    __syncthreads();
    for (int idx = t; idx < 1024; idx += 256) {
        int e = idx >> 5, d = idx & 31;
        float re = 0.f, im = 0.f;
#pragma unroll 8
        for (int c = 0; c < 32; c++) {
            float a = A[c][d];
            float2 tb = tab[(c * e) & 31];
            re += a * tb.x; im += a * tb.y;
        }
        re *= (1.0f / 32.0f); im *= (1.0f / 32.0f);
        if (e == 0) im += (1.0f / 32.0f);
        g_Chat[bh * 1024 + idx] = make_float2(re, im);
    }
}

// ---------------- g table (stable half-angle form) ----------------
__global__ void k_gtab()
{
    int idx = blockIdx.x * 256 + threadIdx.x;
    if (idx >= 96 * 96) return;
    int hr = idx / 96, tt = idx - hr * 96;
    float2 g;
    if (hr == 0) {
        g = make_float2(tt == 0 ? 1.f : 0.f, 0.f);
    } else {
        const float PI = 3.14159265358979323846f;
        float h1 = PI * (float)hr / 96.0f;
        float h2 = PI * (96.0f * (float)tt + (float)hr) / 9216.0f;
        float r = sinf(h1) / (96.0f * sinf(h2));
        float psi = h1 - h2;
        g = make_float2(r * cosf(psi), r * sinf(psi));
    }
    g_gtab[idx] = g;
}

// ---------------- v -> Tt directly (fused transpose) ------------------------
__global__ void __launch_bounds__(256) k_vtrans2()
{
    const int ch0 = blockIdx.x * 2, r0 = blockIdx.y * 32;
    __shared__ float  vsm[2 * 32 * 96];
    __shared__ float2 gsm[32 * 96];
    const int t = threadIdx.x;
#pragma unroll
    for (int i = 0; i < 6; i++) {
        int idx = i * 256 + t;
        int row = idx / 24, c4 = idx % 24;
        int ch = row >> 5, rr = row & 31;
        float4 v = *(const float4*)&g_v[(size_t)(ch0 + ch) * NHW + (r0 + rr) * 96 + c4 * 4];
        *(float4*)&vsm[(ch * 32 + rr) * 96 + c4 * 4] = v;
    }
#pragma unroll
    for (int i = 0; i < 12; i++) {
        int idx = i * 256 + t;
        int rr = idx / 96, c = idx % 96;
        gsm[rr * 96 + c] = g_gtab[(r0 + rr) * 96 + c];
    }
    __syncthreads();
    const int lane = t & 31, a0 = (t >> 5) * 12;
    float ar[2][12], ai[2][12];
#pragma unroll
    for (int c = 0; c < 2; c++)
#pragma unroll
        for (int j = 0; j < 12; j++) { ar[c][j] = 0.f; ai[c][j] = 0.f; }

    const float*  v0p = &vsm[lane * 96];
    const float*  v1p = &vsm[(32 + lane) * 96];
    const float2* gp  = &gsm[lane * 96];
    for (int w0 = 0; w0 < 96; w0++) {
        int we = w0 + lane; if (we >= 96) we -= 96;
        float v0 = v0p[we], v1 = v1p[we];
        int base = a0 - we; if (base < 0) base += 96;
#pragma unroll
        for (int j = 0; j < 12; j++) {
            int ii = base + j; if (ii >= 96) ii -= 96;
            float2 g = gp[ii];
            ar[0][j] += v0 * g.x; ai[0][j] += v0 * g.y;
            ar[1][j] += v1 * g.x; ai[1][j] += v1 * g.y;
        }
    }
#pragma unroll
    for (int c = 0; c < 2; c++)
#pragma unroll
        for (int j = 0; j < 12; j++)
            g_Tt[(size_t)(ch0 + c) * NHW + (a0 + j) * 96 + r0 + lane] =
                make_float2(ar[c][j], ai[c][j]);
}

// ---------------- mix: R[bh*32+e][s] = | sum_d Chat[e][d] * Tt[bh*32+d][s] |
__global__ void __launch_bounds__(256) k_mix()
{
    const int s0 = blockIdx.x * 128;
    const int bh = blockIdx.y;
    __shared__ float2 Ch[1024];
    __shared__ float2 Ts[32][128];
    const int t = threadIdx.x;
    for (int i = t; i < 1024; i += 256) Ch[i] = g_Chat[bh * 1024 + i];
    for (int i = t; i < 4096; i += 256) {
        int d = i >> 7, j = i & 127;
        Ts[d][j] = g_Tt[(size_t)(bh * 32 + d) * NHW + s0 + j];
    }
    __syncthreads();
    const int sl = t & 63, eg = t >> 6;
    float ar0[8], ai0[8], ar1[8], ai1[8];
#pragma unroll
    for (int i = 0; i < 8; i++) { ar0[i] = ai0[i] = ar1[i] = ai1[i] = 0.f; }

    for (int d = 0; d < 32; d++) {
        float2 t0 = Ts[d][sl];
        float2 t1 = Ts[d][sl + 64];
#pragma unroll
        for (int i = 0; i < 8; i++) {
            float2 c = Ch[(eg * 8 + i) * 32 + d];
            ar0[i] += c.x * t0.x - c.y * t0.y;
            ai0[i] += c.x * t0.y + c.y * t0.x;
            ar1[i] += c.x * t1.x - c.y * t1.y;
            ai1[i] += c.x * t1.y + c.y * t1.x;
        }
    }
#pragma unroll
    for (int i = 0; i < 8; i++) {
        int row = bh * 32 + eg * 8 + i;
        g_R[(size_t)row * NHW + s0 + sl]      = sqrtf(ar0[i] * ar0[i] + ai0[i] * ai0[i]);
        g_R[(size_t)row * NHW + s0 + sl + 64] = sqrtf(ar1[i] * ar1[i] + ai1[i] * ai1[i]);
    }
}

// ---------------- launch ----------------
extern "C" void kernel_launch(void* const* d_in, const int* in_sizes, int n_in,
                              void* d_out, int out_size)
{
    const float* x    = (const float*)d_in[0];
    const float* w1   = (const float*)d_in[1];
    const float* b1   = (const float*)d_in[2];
    const float* w2   = (const float*)d_in[3];
    const float* b2   = (const float*)d_in[4];
    const float* w3   = (const float*)d_in[5];
    const float* b3   = (const float*)d_in[6];
    const float* wo   = (const float*)d_in[7];
    const float* temp = (const float*)d_in[8];
    float* out = (float*)d_out;

    float *vp = nullptr, *Rp = nullptr, *Pp = nullptr, *Sp = nullptr, *Gfp = nullptr;
    float *nqp = nullptr, *nkp = nullptr, *w1mp = nullptr, *w2mp = nullptr;
    cudaGetSymbolAddress((void**)&vp,  g_v);
    cudaGetSymbolAddress((void**)&Rp,  g_R);
    cudaGetSymbolAddress((void**)&Pp,  g_P);
    cudaGetSymbolAddress((void**)&Sp,  g_S);
    cudaGetSymbolAddress((void**)&Gfp, g_Gf);
    cudaGetSymbolAddress((void**)&nqp,  g_nq);
    cudaGetSymbolAddress((void**)&nkp,  g_nk);
    cudaGetSymbolAddress((void**)&w1mp, g_w1m);
    cudaGetSymbolAddress((void**)&w2mp, g_w2m);

    dim3 gg(72, 2, 8);
    dim3 gm(4, 4, 8);

    k_gemm_tf32<<<gg, 256>>>(x, w3, b3, vp);            // v
    k_revx   <<<dim3(2048, 9), 256>>>(x);
    k_xsum   <<<2048, 256>>>(x);
    k_gram4  <<<dim3(KCH, 3, 16), 256>>>(x);            // partial tiles (tf32)
    k_gred   <<<dim3(64, 3, 16), 256>>>();              // -> S, M
    k_mirror <<<dim3(64, 16), 256>>>();
    k_mmA    <<<gm, 256>>>(w2);                         // P = M * W2^T
    k_mmB    <<<gm, 256>>>(w1, Pp, Gfp);                // Gf = W1 * P
    k_mmB    <<<gm, 256>>>(w1, Sp, Pp);                 // U1 = W1 * S
    k_rowdot <<<2048, 256>>>(Pp, w1, b1, nqp, w1mp);
    k_mmB    <<<gm, 256>>>(w2, Sp, Pp);                 // U2 = W2 * S
    k_rowdot <<<2048, 256>>>(Pp, w2, b2, nkp, w2mp);
    k_gtab   <<<36, 256>>>();
    k_attn2  <<<64, 256>>>(b1, b2, temp);
    k_vtrans2<<<dim3(1024, 3), 256>>>();
    k_mix    <<<dim3(72, 64), 256>>>();
    k_gemm_tf32<<<gg, 256>>>(Rp, wo, nullptr, out);
}

// round 9
// speedup vs baseline: 2.3241x; 1.2044x over previous
#include <cuda_runtime.h>
#include <math.h>
#include <stdint.h>

#define NB 8
#define NC 256
#define NHW 9216
#define NHEAD 8
#define KCH 24            // gram split-K chunks

// ---------------- scratch (device globals; no allocation anywhere) ----------
__device__ float  g_v[NB*NC*NHW];         // 75.5 MB
__device__ float  g_xrev[NB*NC*NHW];      // 75.5 MB (xrev, later reused as Rp)
__device__ float  g_gp[KCH*3*16*128*128]; // 75.5 MB gram partials
__device__ float  g_S[NB*256*256];
__device__ float  g_M[NB*256*256];
__device__ float  g_P[NB*256*256];
__device__ float  g_Gf[NB*256*256];
__device__ float  g_m[NB*256];
__device__ float  g_nq[NB*256], g_nk[NB*256];
__device__ float  g_w1m[NB*256], g_w2m[NB*256];
__device__ float2 g_Chat[64*1024];
__device__ float2 g_gtab[96*96];
__device__ float  g_gcre[96*96*96];       // circulant conv tables
__device__ float  g_gcim[96*96*96];
__device__ float2 g_Tt[NB*NC*NHW];        // 151 MB, layout [ch][r][a]
__device__ float  g_R [NB*NC*NHW];

// ---------------- tf32 helpers ----------------------------------------------
__device__ __forceinline__ uint32_t f2tf32(float x) {
    uint32_t r;
    asm("cvt.rna.tf32.f32 %0, %1;" : "=r"(r) : "f"(x));
    return r;
}
__device__ __forceinline__ void mma_tf32(float* c, const uint32_t* a, const uint32_t* b) {
    asm volatile(
        "mma.sync.aligned.m16n8k8.row.col.f32.tf32.tf32.f32 "
        "{%0,%1,%2,%3}, {%4,%5,%6,%7}, {%8,%9}, {%0,%1,%2,%3};"
        : "+f"(c[0]), "+f"(c[1]), "+f"(c[2]), "+f"(c[3])
        : "r"(a[0]), "r"(a[1]), "r"(a[2]), "r"(a[3]), "r"(b[0]), "r"(b[1]));
}

// ---------------- tf32 GEMM: Y[b][o][s] = sum_c W[o][c] X[b][c][s] (+bias) ---
// 128 threads, 4 warps 2x2, warp tile 64x64, block tile 128x128, K-chunk 8.
__global__ void __launch_bounds__(128) k_gemm_tf32(
    const float* __restrict__ X, const float* __restrict__ W,
    const float* __restrict__ bias, float* __restrict__ Y)
{
    __shared__ __align__(16) uint32_t Ws[8][136];   // [k][m]
    __shared__ __align__(16) uint32_t Xs[8][136];   // [k][n]
    const int t  = threadIdx.x;
    const int s0 = blockIdx.x * 128;
    const int o0 = blockIdx.y * 128;
    const int b  = blockIdx.z;
    const int warp = t >> 5, lane = t & 31;
    const int gid = lane >> 2, tig = lane & 3;
    const int mrow = (warp >> 1) * 64;
    const int ncol = (warp & 1) * 64;
    const float* Xb = X + (size_t)b * NC * NHW;

    const int xr = t >> 4, xc = (t & 15) * 8;       // X load: row k, 8 cols

    float c[4][8][4];
#pragma unroll
    for (int i = 0; i < 4; i++)
#pragma unroll
        for (int j = 0; j < 8; j++)
#pragma unroll
            for (int q = 0; q < 4; q++) c[i][j][q] = 0.f;

    float4 wA, wB, xA, xB;
    {
        const float* wp = &W[(o0 + t) * 256];
        wA = *(const float4*)&wp[0];
        wB = *(const float4*)&wp[4];
        const float* xp = &Xb[(size_t)xr * NHW + s0 + xc];
        xA = *(const float4*)&xp[0];
        xB = *(const float4*)&xp[4];
    }

    for (int kc = 0; kc < 256; kc += 8) {
        __syncthreads();
        Ws[0][t] = f2tf32(wA.x); Ws[1][t] = f2tf32(wA.y);
        Ws[2][t] = f2tf32(wA.z); Ws[3][t] = f2tf32(wA.w);
        Ws[4][t] = f2tf32(wB.x); Ws[5][t] = f2tf32(wB.y);
        Ws[6][t] = f2tf32(wB.z); Ws[7][t] = f2tf32(wB.w);
        uint4 u0 = make_uint4(f2tf32(xA.x), f2tf32(xA.y), f2tf32(xA.z), f2tf32(xA.w));
        uint4 u1 = make_uint4(f2tf32(xB.x), f2tf32(xB.y), f2tf32(xB.z), f2tf32(xB.w));
        *(uint4*)&Xs[xr][xc]     = u0;
        *(uint4*)&Xs[xr][xc + 4] = u1;
        __syncthreads();

        int kn = (kc + 8 < 256) ? kc + 8 : 0;
        {
            const float* wp = &W[(o0 + t) * 256 + kn];
            wA = *(const float4*)&wp[0];
            wB = *(const float4*)&wp[4];
            const float* xp = &Xb[(size_t)(kn + xr) * NHW + s0 + xc];
            xA = *(const float4*)&xp[0];
            xB = *(const float4*)&xp[4];
        }

        uint32_t afr[4][4], bfr[8][2];
#pragma unroll
        for (int mt = 0; mt < 4; mt++) {
            int m0 = mrow + mt * 16;
            afr[mt][0] = Ws[tig][m0 + gid];
            afr[mt][1] = Ws[tig][m0 + gid + 8];
            afr[mt][2] = Ws[tig + 4][m0 + gid];
            afr[mt][3] = Ws[tig + 4][m0 + gid + 8];
        }
#pragma unroll
        for (int nt = 0; nt < 8; nt++) {
            int n0 = ncol + nt * 8;
            bfr[nt][0] = Xs[tig][n0 + gid];
            bfr[nt][1] = Xs[tig + 4][n0 + gid];
        }
#pragma unroll
        for (int mt = 0; mt < 4; mt++)
#pragma unroll
            for (int nt = 0; nt < 8; nt++)
                mma_tf32(c[mt][nt], afr[mt], bfr[nt]);
    }

#pragma unroll
    for (int mt = 0; mt < 4; mt++) {
        int oa = o0 + mrow + mt * 16 + gid;
        int ob = oa + 8;
        float ba  = bias ? bias[oa] : 0.f;
        float bb_ = bias ? bias[ob] : 0.f;
        float* ya = Y + (size_t)(b * NC + oa) * NHW + s0;
        float* yb = Y + (size_t)(b * NC + ob) * NHW + s0;
#pragma unroll
        for (int nt = 0; nt < 8; nt++) {
            int sc = ncol + nt * 8 + tig * 2;
            *(float2*)&ya[sc] = make_float2(c[mt][nt][0] + ba,  c[mt][nt][1] + ba);
            *(float2*)&yb[sc] = make_float2(c[mt][nt][2] + bb_, c[mt][nt][3] + bb_);
        }
    }
}

// ---------------- reversed copy ----------------------------------------------
__global__ void __launch_bounds__(256) k_revx(const float* __restrict__ X)
{
    const int ch = blockIdx.x;
    const int seg = blockIdx.y;
    const float* src = X + (size_t)ch * NHW;
    float* dst = g_xrev + (size_t)ch * NHW;
    int s = seg * 1024 + threadIdx.x;
#pragma unroll
    for (int i = 0; i < 4; i++, s += 256) {
        int y = s / 96, x = s - y * 96;
        int ry = (y == 0) ? 0 : 96 - y;
        int rx = (x == 0) ? 0 : 96 - x;
        dst[s] = src[ry * 96 + rx];
    }
}

// ---------------- m[b][c] = sum_s x[b][c][s] ----------------
__global__ void __launch_bounds__(256) k_xsum(const float* __restrict__ X)
{
    const int bc = blockIdx.x;
    const float4* x4 = (const float4*)(X + (size_t)bc * NHW);
    float s = 0.f;
    for (int i = threadIdx.x; i < NHW / 4; i += 256) {
        float4 a = x4[i]; s += a.x + a.y + a.z + a.w;
    }
#pragma unroll
    for (int o = 16; o; o >>= 1) s += __shfl_xor_sync(0xffffffff, s, o);
    __shared__ float sb[8];
    int w = threadIdx.x >> 5;
    if ((threadIdx.x & 31) == 0) sb[w] = s;
    __syncthreads();
    if (threadIdx.x == 0) {
        float a = 0.f;
        for (int i = 0; i < 8; i++) a += sb[i];
        g_m[bc] = a;
    }
}

// ---------------- Gram GEMM (tf32, 64x64 warp tiles), partial tiles ----------
__global__ void __launch_bounds__(128) k_gram5(const float* __restrict__ X)
{
    const int sch = blockIdx.x, pr = blockIdx.y;
    const int b = blockIdx.z >> 1, mat = blockIdx.z & 1;
    const int ci = (pr == 2) ? 1 : 0;
    const int dj = (pr == 0) ? 0 : 1;
    __shared__ __align__(16) uint32_t xa[8][136];   // [k][m]
    __shared__ __align__(16) uint32_t xd[8][136];   // [k][n]
    const float* Xa = X + (size_t)b * NC * NHW;
    const float* Xd = (mat ? g_xrev : X) + (size_t)b * NC * NHW;
    const int t = threadIdx.x;
    const int warp = t >> 5, lane = t & 31;
    const int gid = lane >> 2, tig = lane & 3;
    const int mrow = (warp >> 1) * 64;
    const int ncol = (warp & 1) * 64;
    const int base = sch * (NHW / KCH);

    float c[4][8][4];
#pragma unroll
    for (int i = 0; i < 4; i++)
#pragma unroll
        for (int j = 0; j < 8; j++)
#pragma unroll
            for (int q = 0; q < 4; q++) c[i][j][q] = 0.f;

    float4 aA, aB, dA, dB;
    {
        const float* ap = &Xa[(size_t)(ci * 128 + t) * NHW + base];
        aA = *(const float4*)&ap[0]; aB = *(const float4*)&ap[4];
        const float* dp = &Xd[(size_t)(dj * 128 + t) * NHW + base];
        dA = *(const float4*)&dp[0]; dB = *(const float4*)&dp[4];
    }

    const int NKS = NHW / (KCH * 8);
    for (int ks = 0; ks < NKS; ks++) {
        __syncthreads();
        xa[0][t] = f2tf32(aA.x); xa[1][t] = f2tf32(aA.y);
        xa[2][t] = f2tf32(aA.z); xa[3][t] = f2tf32(aA.w);
        xa[4][t] = f2tf32(aB.x); xa[5][t] = f2tf32(aB.y);
        xa[6][t] = f2tf32(aB.z); xa[7][t] = f2tf32(aB.w);
        xd[0][t] = f2tf32(dA.x); xd[1][t] = f2tf32(dA.y);
        xd[2][t] = f2tf32(dA.z); xd[3][t] = f2tf32(dA.w);
        xd[4][t] = f2tf32(dB.x); xd[5][t] = f2tf32(dB.y);
        xd[6][t] = f2tf32(dB.z); xd[7][t] = f2tf32(dB.w);
        __syncthreads();

        int s0 = base + ((ks + 1 < NKS) ? (ks + 1) * 8 : 0);
        {
            const float* ap = &Xa[(size_t)(ci * 128 + t) * NHW + s0];
            aA = *(const float4*)&ap[0]; aB = *(const float4*)&ap[4];
            const float* dp = &Xd[(size_t)(dj * 128 + t) * NHW + s0];
            dA = *(const float4*)&dp[0]; dB = *(const float4*)&dp[4];
        }

        uint32_t afr[4][4], bfr[8][2];
#pragma unroll
        for (int mt = 0; mt < 4; mt++) {
            int m0 = mrow + mt * 16;
            afr[mt][0] = xa[tig][m0 + gid];
            afr[mt][1] = xa[tig][m0 + gid + 8];
            afr[mt][2] = xa[tig + 4][m0 + gid];
            afr[mt][3] = xa[tig + 4][m0 + gid + 8];
        }
#pragma unroll
        for (int nt = 0; nt < 8; nt++) {
            int n0 = ncol + nt * 8;
            bfr[nt][0] = xd[tig][n0 + gid];
            bfr[nt][1] = xd[tig + 4][n0 + gid];
        }
#pragma unroll
        for (int mt = 0; mt < 4; mt++)
#pragma unroll
            for (int nt = 0; nt < 8; nt++)
                mma_tf32(c[mt][nt], afr[mt], bfr[nt]);
    }

    float* Out = g_gp + ((size_t)(blockIdx.z * 3 + pr) * KCH + sch) * 16384;
#pragma unroll
    for (int mt = 0; mt < 4; mt++) {
        int ra = mrow + mt * 16 + gid;
        int rb = ra + 8;
#pragma unroll
        for (int nt = 0; nt < 8; nt++) {
            int col = ncol + nt * 8 + tig * 2;
            *(float2*)&Out[ra * 128 + col] = make_float2(c[mt][nt][0], c[mt][nt][1]);
            *(float2*)&Out[rb * 128 + col] = make_float2(c[mt][nt][2], c[mt][nt][3]);
        }
    }
}

// ---------------- reduce partials into S / M --------------------------------
__global__ void __launch_bounds__(256) k_gred()
{
    const int pr = blockIdx.y, bm = blockIdx.z;
    const int b = bm >> 1, mat = bm & 1;
    const int ci = (pr == 2) ? 1 : 0;
    const int dj = (pr == 0) ? 0 : 1;
    const int off = blockIdx.x * 256 + threadIdx.x;
    const float* Pp = g_gp + (size_t)(bm * 3 + pr) * KCH * 16384 + off;
    float s = 0.f;
#pragma unroll
    for (int c = 0; c < KCH; c++) s += Pp[c * 16384];
    int il = off >> 7, jl = off & 127;
    float* Out = (mat ? g_M : g_S) + b * 65536;
    Out[(ci * 128 + il) * 256 + dj * 128 + jl] = s;
}

// ---------------- mirror lower-left 128x128 block ---------------------------
__global__ void k_mirror()
{
    const int bm = blockIdx.y;
    float* Out = (bm & 1 ? g_M : g_S) + (bm >> 1) * 65536;
    int idx = blockIdx.x * 256 + threadIdx.x;
    int i = idx >> 7, jl = idx & 127;
    Out[(128 + jl) * 256 + i] = Out[i * 256 + 128 + jl];
}

// ---------------- P[b] = M[b] * W2^T ----------------------------------------
__global__ void __launch_bounds__(256) k_mmA(const float* __restrict__ Wg)
{
    const int j0 = blockIdx.x * 64, i0 = blockIdx.y * 64, b = blockIdx.z;
    const float* A = g_M + b * 65536;
    float* C = g_P + b * 65536;
    __shared__ float As[16][68];
    __shared__ float Bs[16][68];
    const int t = threadIdx.x;
    const int it = (t >> 4) * 4, jt = (t & 15) * 4;
    float acc[4][4];
#pragma unroll
    for (int i = 0; i < 4; i++)
#pragma unroll
        for (int j = 0; j < 4; j++) acc[i][j] = 0.f;
    for (int kc = 0; kc < 256; kc += 16) {
        __syncthreads();
#pragma unroll
        for (int i = 0; i < 4; i++) {
            int idx = i * 256 + t;
            int r = idx >> 4, kk = idx & 15;
            As[kk][r] = A[(i0 + r) * 256 + kc + kk];
            Bs[kk][r] = Wg[(j0 + r) * 256 + kc + kk];
        }
        __syncthreads();
#pragma unroll
        for (int kk = 0; kk < 16; kk++) {
            float a[4], bb[4];
            *(float4*)a  = *(float4*)&As[kk][it];
            *(float4*)bb = *(float4*)&Bs[kk][jt];
#pragma unroll
            for (int i = 0; i < 4; i++)
#pragma unroll
                for (int j = 0; j < 4; j++) acc[i][j] += a[i] * bb[j];
        }
    }
#pragma unroll
    for (int i = 0; i < 4; i++)
#pragma unroll
        for (int j = 0; j < 4; j++)
            C[(i0 + it + i) * 256 + j0 + jt + j] = acc[i][j];
}

// ---------------- C[b] = Ag * B[b] ------------------------------------------
__global__ void __launch_bounds__(256) k_mmB(
    const float* __restrict__ Ag, const float* __restrict__ Bb, float* __restrict__ Cb)
{
    const int j0 = blockIdx.x * 64, i0 = blockIdx.y * 64, b = blockIdx.z;
    const float* B = Bb + b * 65536;
    float* C = Cb + b * 65536;
    __shared__ float As[16][68];
    __shared__ float Bs[16][68];
    const int t = threadIdx.x;
    const int it = (t >> 4) * 4, jt = (t & 15) * 4;
    float acc[4][4];
#pragma unroll
    for (int i = 0; i < 4; i++)
#pragma unroll
        for (int j = 0; j < 4; j++) acc[i][j] = 0.f;
    for (int kc = 0; kc < 256; kc += 16) {
        __syncthreads();
#pragma unroll
        for (int i = 0; i < 4; i++) {
            int idx = i * 256 + t;
            int r = idx >> 4, kk = idx & 15;
            As[kk][r] = Ag[(i0 + r) * 256 + kc + kk];
        }
#pragma unroll
        for (int i = 0; i < 4; i++) {
            int idx = i * 256 + t;
            int kk = idx >> 6, j = idx & 63;
            Bs[kk][j] = B[(kc + kk) * 256 + j0 + j];
        }
        __syncthreads();
#pragma unroll
        for (int kk = 0; kk < 16; kk++) {
            float a[4], bb[4];
            *(float4*)a  = *(float4*)&As[kk][it];
            *(float4*)bb = *(float4*)&Bs[kk][jt];
#pragma unroll
            for (int i = 0; i < 4; i++)
#pragma unroll
                for (int j = 0; j < 4; j++) acc[i][j] += a[i] * bb[j];
        }
    }
#pragma unroll
    for (int i = 0; i < 4; i++)
#pragma unroll
        for (int j = 0; j < 4; j++)
            C[(i0 + it + i) * 256 + j0 + jt + j] = acc[i][j];
}

// ---------------- row-dot: norms + W*m --------------------------------------
__global__ void __launch_bounds__(256) k_rowdot(
    const float* __restrict__ U, const float* __restrict__ W,
    const float* __restrict__ bias, float* __restrict__ outN, float* __restrict__ outWM)
{
    const int bC = blockIdx.x;
    const int b = bC >> 8, C = bC & 255;
    const int t = threadIdx.x;
    float wv = W[C * 256 + t];
    float un = U[(size_t)b * 65536 + C * 256 + t] * wv;
    float wm = wv * g_m[b * 256 + t];
#pragma unroll
    for (int o = 16; o; o >>= 1) {
        un += __shfl_xor_sync(0xffffffff, un, o);
        wm += __shfl_xor_sync(0xffffffff, wm, o);
    }
    __shared__ float s1[8], s2[8];
    int w = t >> 5;
    if ((t & 31) == 0) { s1[w] = un; s2[w] = wm; }
    __syncthreads();
    if (t == 0) {
        float a = 0.f, c = 0.f;
        for (int i = 0; i < 8; i++) { a += s1[i]; c += s2[i]; }
        float bc = bias[C];
        outWM[bC] = c;
        outN[bC] = a + 2.f * bc * c + 9216.f * bc * bc;
    }
}

// ---------------- attn: logits, softmax, build Chat -------------------------
__global__ void __launch_bounds__(256) k_attn2(
    const float* __restrict__ b1, const float* __restrict__ b2,
    const float* __restrict__ temperature)
{
    const int bh = blockIdx.x;
    const int b = bh >> 3, h = bh & 7;
    const int ch0 = h * 32;
    __shared__ float A[32][33];
    __shared__ float rq[32], rk[32], sw1m[32], sw2m[32], sb1[32], sb2[32];
    __shared__ float2 tab[32];
    const int t = threadIdx.x;
    if (t < 32) {
        int C = b * 256 + ch0 + t;
        rq[t] = rsqrtf(g_nq[C]);
        rk[t] = rsqrtf(g_nk[C]);
        sw1m[t] = g_w1m[C];
        sw2m[t] = g_w2m[C];
        sb1[t] = b1[ch0 + t];
        sb2[t] = b2[ch0 + t];
        float ang = 6.283185307179586f * (float)t / 32.0f;
        tab[t] = make_float2(cosf(ang), sinf(ang));
    }
    __syncthreads();
    const float ts = temperature[h];
    const int w = t >> 5, lane = t & 31;
    for (int r = w; r < 32; r += 8) {
        float Gv = g_Gf[(size_t)b * 65536 + (ch0 + r) * 256 + ch0 + lane];
        float L = (Gv + sw1m[r] * sb2[lane] + sb1[r] * sw2m[lane]
                   + 9216.f * sb1[r] * sb2[lane]) * rq[r] * rk[lane] * ts;
        float m = L;
#pragma unroll
        for (int o = 16; o; o >>= 1) m = fmaxf(m, __shfl_xor_sync(0xffffffff, m, o));
        float e = expf(L - m);
        float s = e;
#pragma unroll
        for (int o = 16; o; o >>= 1) s += __shfl_xor_sync(0xffffffff, s, o);
        A[r][lane] = e / s;
    }
    __syncthreads();
    for (int idx = t; idx < 1024; idx += 256) {
        int e = idx >> 5, d = idx & 31;
        float re = 0.f, im = 0.f;
#pragma unroll 8
        for (int c = 0; c < 32; c++) {
            float a = A[c][d];
            float2 tb = tab[(c * e) & 31];
            re += a * tb.x; im += a * tb.y;
        }
        re *= (1.0f / 32.0f); im *= (1.0f / 32.0f);
        if (e == 0) im += (1.0f / 32.0f);
        g_Chat[bh * 1024 + idx] = make_float2(re, im);
    }
}

// ---------------- g table (stable half-angle form) ----------------
__global__ void k_gtab()
{
    int idx = blockIdx.x * 256 + threadIdx.x;
    if (idx >= 96 * 96) return;
    int hr = idx / 96, tt = idx - hr * 96;
    float2 g;
    if (hr == 0) {
        g = make_float2(tt == 0 ? 1.f : 0.f, 0.f);
    } else {
        const float PI = 3.14159265358979323846f;
        float h1 = PI * (float)hr / 96.0f;
        float h2 = PI * (96.0f * (float)tt + (float)hr) / 9216.0f;
        float r = sinf(h1) / (96.0f * sinf(h2));
        float psi = h1 - h2;
        g = make_float2(r * cosf(psi), r * sinf(psi));
    }
    g_gtab[idx] = g;
}

// ---------------- circulant tables: gc[r][w][a] = g[r][(a-w)%96] -------------
__global__ void k_gtab2()
{
    int idx = blockIdx.x * 256 + threadIdx.x;   // grid 3456 -> 884736
    int r = idx / 9216;
    int rem = idx - r * 9216;
    int w = rem / 96, a = rem - w * 96;
    int tt = a - w; if (tt < 0) tt += 96;
    float2 g = g_gtab[r * 96 + tt];
    g_gcre[idx] = g.x;
    g_gcim[idx] = g.y;
}

// ---------------- conv as batched tf32 GEMM ---------------------------------
// For each r: T[ch][a] = sum_w v[ch][r*96+w] * gc[r][w][a]  (complex B)
// Block: 64 ch x 96 a, 4 warps 2x2, warp 32x48. Output [ch][r][a] (coalesced).
__global__ void __launch_bounds__(128) k_vconv()
{
    const int r = blockIdx.x;
    const int ch0 = blockIdx.y * 64;
    __shared__ __align__(16) uint32_t As[8][72];    // [w][ch]
    __shared__ __align__(16) uint32_t Br[8][104];   // [w][a]
    __shared__ __align__(16) uint32_t Bi[8][104];
    const int t = threadIdx.x;
    const int warp = t >> 5, lane = t & 31;
    const int gid = lane >> 2, tig = lane & 3;
    const int mrow = (warp >> 1) * 32;
    const int ncol = (warp & 1) * 48;
    // A load: ch = t>>1, 4 w's; B load: w = t>>4, 6 a's per plane
    const int ach = t >> 1, aw4 = (t & 1) * 4;
    const int bw = t >> 4, ba0 = (t & 15) * 6;

    float cre[2][6][4], cim[2][6][4];
#pragma unroll
    for (int i = 0; i < 2; i++)
#pragma unroll
        for (int j = 0; j < 6; j++)
#pragma unroll
            for (int q = 0; q < 4; q++) { cre[i][j][q] = 0.f; cim[i][j][q] = 0.f; }

    float4 av;
    float br[6], bi[6];
    av = *(const float4*)&g_v[(size_t)(ch0 + ach) * NHW + r * 96 + aw4];
    {
        const float* pr_ = &g_gcre[(size_t)r * 9216 + bw * 96 + ba0];
        const float* pi_ = &g_gcim[(size_t)r * 9216 + bw * 96 + ba0];
#pragma unroll
        for (int i = 0; i < 6; i++) { br[i] = pr_[i]; bi[i] = pi_[i]; }
    }

    for (int ks = 0; ks < 12; ks++) {
        __syncthreads();
        As[aw4 + 0][ach] = f2tf32(av.x);
        As[aw4 + 1][ach] = f2tf32(av.y);
        As[aw4 + 2][ach] = f2tf32(av.z);
        As[aw4 + 3][ach] = f2tf32(av.w);
#pragma unroll
        for (int i = 0; i < 6; i++) {
            Br[bw][ba0 + i] = f2tf32(br[i]);
            Bi[bw][ba0 + i] = f2tf32(bi[i]);
        }
        __syncthreads();

        int w0n = (ks + 1 < 12) ? (ks + 1) * 8 : 0;
        av = *(const float4*)&g_v[(size_t)(ch0 + ach) * NHW + r * 96 + w0n + aw4];
        {
            const float* pr_ = &g_gcre[(size_t)r * 9216 + (w0n + bw) * 96 + ba0];
            const float* pi_ = &g_gcim[(size_t)r * 9216 + (w0n + bw) * 96 + ba0];
#pragma unroll
            for (int i = 0; i < 6; i++) { br[i] = pr_[i]; bi[i] = pi_[i]; }
        }

        uint32_t afr[2][4], bre[6][2], bim[6][2];
#pragma unroll
        for (int mt = 0; mt < 2; mt++) {
            int m0 = mrow + mt * 16;
            afr[mt][0] = As[tig][m0 + gid];
            afr[mt][1] = As[tig][m0 + gid + 8];
            afr[mt][2] = As[tig + 4][m0 + gid];
            afr[mt][3] = As[tig + 4][m0 + gid + 8];
        }
#pragma unroll
        for (int nt = 0; nt < 6; nt++) {
            int n0 = ncol + nt * 8;
            bre[nt][0] = Br[tig][n0 + gid];
            bre[nt][1] = Br[tig + 4][n0 + gid];
            bim[nt][0] = Bi[tig][n0 + gid];
            bim[nt][1] = Bi[tig + 4][n0 + gid];
        }
#pragma unroll
        for (int mt = 0; mt < 2; mt++)
#pragma unroll
            for (int nt = 0; nt < 6; nt++) {
                mma_tf32(cre[mt][nt], afr[mt], bre[nt]);
                mma_tf32(cim[mt][nt], afr[mt], bim[nt]);
            }
    }

#pragma unroll
    for (int mt = 0; mt < 2; mt++) {
        int r0 = ch0 + mrow + mt * 16 + gid;
        int r1 = r0 + 8;
        float2* p0 = &g_Tt[(size_t)r0 * NHW + r * 96];
        float2* p1 = &g_Tt[(size_t)r1 * NHW + r * 96];
#pragma unroll
        for (int nt = 0; nt < 6; nt++) {
            int a = ncol + nt * 8 + tig * 2;
            p0[a]     = make_float2(cre[mt][nt][0], cim[mt][nt][0]);
            p0[a + 1] = make_float2(cre[mt][nt][1], cim[mt][nt][1]);
            p1[a]     = make_float2(cre[mt][nt][2], cim[mt][nt][2]);
            p1[a + 1] = make_float2(cre[mt][nt][3], cim[mt][nt][3]);
        }
    }
}

// ---------------- mix: Rp[bh*32+e][s] = | sum_d Chat[e][d] * T[bh*32+d][s] |
// (s here is the permuted r*96+a index; Rp written into g_xrev scratch)
__global__ void __launch_bounds__(256) k_mix()
{
    const int s0 = blockIdx.x * 128;
    const int bh = blockIdx.y;
    __shared__ float2 Ch[1024];
    __shared__ float2 Ts[32][128];
    const int t = threadIdx.x;
    for (int i = t; i < 1024; i += 256) Ch[i] = g_Chat[bh * 1024 + i];
    for (int i = t; i < 4096; i += 256) {
        int d = i >> 7, j = i & 127;
        Ts[d][j] = g_Tt[(size_t)(bh * 32 + d) * NHW + s0 + j];
    }
    __syncthreads();
    const int sl = t & 63, eg = t >> 6;
    float ar0[8], ai0[8], ar1[8], ai1[8];
#pragma unroll
    for (int i = 0; i < 8; i++) { ar0[i] = ai0[i] = ar1[i] = ai1[i] = 0.f; }

    for (int d = 0; d < 32; d++) {
        float2 t0 = Ts[d][sl];
        float2 t1 = Ts[d][sl + 64];
#pragma unroll
        for (int i = 0; i < 8; i++) {
            float2 c = Ch[(eg * 8 + i) * 32 + d];
            ar0[i] += c.x * t0.x - c.y * t0.y;
            ai0[i] += c.x * t0.y + c.y * t0.x;
            ar1[i] += c.x * t1.x - c.y * t1.y;
            ai1[i] += c.x * t1.y + c.y * t1.x;
        }
    }
#pragma unroll
    for (int i = 0; i < 8; i++) {
        int row = bh * 32 + eg * 8 + i;
        g_xrev[(size_t)row * NHW + s0 + sl]      = sqrtf(ar0[i] * ar0[i] + ai0[i] * ai0[i]);
        g_xrev[(size_t)row * NHW + s0 + sl + 64] = sqrtf(ar1[i] * ar1[i] + ai1[i] * ai1[i]);
    }
}

// ---------------- real transpose: R[ch][a*96+r] = Rp[ch][r*96+a] -------------
__global__ void __launch_bounds__(256) k_trR()
{
    const int ch = blockIdx.x;
    const int tile = blockIdx.y;
    const int tr = (tile / 3) * 32;
    const int tc = (tile % 3) * 32;
    __shared__ float s[32][33];
    const int t = threadIdx.x;
    const size_t base = (size_t)ch * NHW;
#pragma unroll
    for (int i = 0; i < 4; i++) {
        int idx = i * 256 + t;
        int r = idx >> 5, c = idx & 31;
        s[r][c] = g_xrev[base + (size_t)(tr + r) * 96 + tc + c];
    }
    __syncthreads();
#pragma unroll
    for (int i = 0; i < 4; i++) {
        int idx = i * 256 + t;
        int r = idx >> 5, c = idx & 31;
        g_R[base + (size_t)(tc + r) * 96 + tr + c] = s[c][r];
    }
}

// ---------------- launch ----------------
extern "C" void kernel_launch(void* const* d_in, const int* in_sizes, int n_in,
                              void* d_out, int out_size)
{
    const float* x    = (const float*)d_in[0];
    const float* w1   = (const float*)d_in[1];
    const float* b1   = (const float*)d_in[2];
    const float* w2   = (const float*)d_in[3];
    const float* b2   = (const float*)d_in[4];
    const float* w3   = (const float*)d_in[5];
    const float* b3   = (const float*)d_in[6];
    const float* wo   = (const float*)d_in[7];
    const float* temp = (const float*)d_in[8];
    float* out = (float*)d_out;

    float *vp = nullptr, *Rp = nullptr, *Pp = nullptr, *Sp = nullptr, *Gfp = nullptr;
    float *nqp = nullptr, *nkp = nullptr, *w1mp = nullptr, *w2mp = nullptr;
    cudaGetSymbolAddress((void**)&vp,  g_v);
    cudaGetSymbolAddress((void**)&Rp,  g_R);
    cudaGetSymbolAddress((void**)&Pp,  g_P);
    cudaGetSymbolAddress((void**)&Sp,  g_S);
    cudaGetSymbolAddress((void**)&Gfp, g_Gf);
    cudaGetSymbolAddress((void**)&nqp,  g_nq);
    cudaGetSymbolAddress((void**)&nkp,  g_nk);
    cudaGetSymbolAddress((void**)&w1mp, g_w1m);
    cudaGetSymbolAddress((void**)&w2mp, g_w2m);

    dim3 gg(72, 2, 8);
    dim3 gm(4, 4, 8);

    k_gemm_tf32<<<gg, 128>>>(x, w3, b3, vp);            // v
    k_revx   <<<dim3(2048, 9), 256>>>(x);
    k_xsum   <<<2048, 256>>>(x);
    k_gram5  <<<dim3(KCH, 3, 16), 128>>>(x);            // partial tiles (tf32)
    k_gred   <<<dim3(64, 3, 16), 256>>>();              // -> S, M
    k_mirror <<<dim3(64, 16), 256>>>();
    k_mmA    <<<gm, 256>>>(w2);                         // P = M * W2^T
    k_mmB    <<<gm, 256>>>(w1, Pp, Gfp);                // Gf = W1 * P
    k_mmB    <<<gm, 256>>>(w1, Sp, Pp);                 // U1 = W1 * S
    k_rowdot <<<2048, 256>>>(Pp, w1, b1, nqp, w1mp);
    k_mmB    <<<gm, 256>>>(w2, Sp, Pp);                 // U2 = W2 * S
    k_rowdot <<<2048, 256>>>(Pp, w2, b2, nkp, w2mp);
    k_gtab   <<<36, 256>>>();
    k_gtab2  <<<3456, 256>>>();
    k_attn2  <<<64, 256>>>(b1, b2, temp);
    k_vconv  <<<dim3(96, 32), 128>>>();                 // conv via tensor cores
    k_mix    <<<dim3(72, 64), 256>>>();                 // -> Rp (g_xrev)
    k_trR    <<<dim3(2048, 9), 256>>>();                // -> R
    k_gemm_tf32<<<gg, 128>>>(Rp, wo, nullptr, out);
}

// round 10
// speedup vs baseline: 2.3371x; 1.0056x over previous
#include <cuda_runtime.h>
#include <math.h>
#include <stdint.h>

#define NB 8
#define NC 256
#define NHW 9216
#define NHEAD 8
#define KCH 24            // gram split-K chunks

// ---------------- scratch (device globals; no allocation anywhere) ----------
__device__ float  g_v[NB*NC*NHW];         // 75.5 MB
__device__ float  g_xrev[NB*NC*NHW];      // 75.5 MB (xrev, later reused as Rp)
__device__ float  g_gp[KCH*3*16*128*128]; // 75.5 MB gram partials
__device__ float  g_S[NB*256*256];
__device__ float  g_M[NB*256*256];
__device__ float  g_P[NB*256*256];
__device__ float  g_Gf[NB*256*256];
__device__ float  g_m[NB*256];
__device__ float  g_nq[NB*256], g_nk[NB*256];
__device__ float  g_w1m[NB*256], g_w2m[NB*256];
__device__ float2 g_Chat[64*1024];
__device__ float2 g_gtab[96*96];
__device__ float  g_gcre[96*96*96];       // circulant conv tables
__device__ float  g_gcim[96*96*96];
__device__ float2 g_Tt[NB*NC*NHW];        // 151 MB, layout [ch][r][a]
__device__ float  g_R [NB*NC*NHW];

// ---------------- tf32 / cp.async helpers ------------------------------------
__device__ __forceinline__ uint32_t f2tf32(float x) {
    uint32_t r;
    asm("cvt.rna.tf32.f32 %0, %1;" : "=r"(r) : "f"(x));
    return r;
}
__device__ __forceinline__ void mma_tf32(float* c, const uint32_t* a, const uint32_t* b) {
    asm volatile(
        "mma.sync.aligned.m16n8k8.row.col.f32.tf32.tf32.f32 "
        "{%0,%1,%2,%3}, {%4,%5,%6,%7}, {%8,%9}, {%0,%1,%2,%3};"
        : "+f"(c[0]), "+f"(c[1]), "+f"(c[2]), "+f"(c[3])
        : "r"(a[0]), "r"(a[1]), "r"(a[2]), "r"(a[3]), "r"(b[0]), "r"(b[1]));
}
__device__ __forceinline__ void cpa16(void* dst, const void* src) {
    uint32_t d = (uint32_t)__cvta_generic_to_shared(dst);
    asm volatile("cp.async.cg.shared.global [%0], [%1], 16;" :: "r"(d), "l"(src));
}
#define CP_COMMIT() asm volatile("cp.async.commit_group;")
#define CP_WAIT0()  asm volatile("cp.async.wait_group 0;")

// ---------------- tf32 GEMM: Y[b][o][s] = sum_c W[o][c] X[b][c][s] (+bias) ---
// 128 threads, 4 warps 2x2, warp tile 64x64, K-chunk 8, cp.async 2-stage.
__global__ void __launch_bounds__(128) k_gemm_tf32(
    const float* __restrict__ X, const float* __restrict__ W,
    const float* __restrict__ bias, float* __restrict__ Y)
{
    __shared__ __align__(16) float Wm[2][128][12];   // [m][k], stride 12 (bank-clean)
    __shared__ __align__(16) float Xs[2][8][136];    // [k][n]
    const int t  = threadIdx.x;
    const int s0 = blockIdx.x * 128;
    const int o0 = blockIdx.y * 128;
    const int b  = blockIdx.z;
    const int warp = t >> 5, lane = t & 31;
    const int gid = lane >> 2, tig = lane & 3;
    const int mrow = (warp >> 1) * 64;
    const int ncol = (warp & 1) * 64;
    const float* Xb = X + (size_t)b * NC * NHW;
    const int xr = t >> 4, xc = (t & 15) * 8;

    float c[4][8][4];
#pragma unroll
    for (int i = 0; i < 4; i++)
#pragma unroll
        for (int j = 0; j < 8; j++)
#pragma unroll
            for (int q = 0; q < 4; q++) c[i][j][q] = 0.f;

    // prologue: fill stage 0 with chunk 0
    cpa16(&Wm[0][t][0], &W[(o0 + t) * 256 + 0]);
    cpa16(&Wm[0][t][4], &W[(o0 + t) * 256 + 4]);
    cpa16(&Xs[0][xr][xc],     &Xb[(size_t)xr * NHW + s0 + xc]);
    cpa16(&Xs[0][xr][xc + 4], &Xb[(size_t)xr * NHW + s0 + xc + 4]);
    CP_COMMIT();

    for (int i = 0; i < 32; i++) {
        const int st = i & 1;
        CP_WAIT0();
        __syncthreads();
        uint32_t afr[4][4], bfr[8][2];
#pragma unroll
        for (int mt = 0; mt < 4; mt++) {
            int m0 = mrow + mt * 16;
            afr[mt][0] = f2tf32(Wm[st][m0 + gid][tig]);
            afr[mt][1] = f2tf32(Wm[st][m0 + gid + 8][tig]);
            afr[mt][2] = f2tf32(Wm[st][m0 + gid][tig + 4]);
            afr[mt][3] = f2tf32(Wm[st][m0 + gid + 8][tig + 4]);
        }
#pragma unroll
        for (int nt = 0; nt < 8; nt++) {
            int n0 = ncol + nt * 8;
            bfr[nt][0] = f2tf32(Xs[st][tig][n0 + gid]);
            bfr[nt][1] = f2tf32(Xs[st][tig + 4][n0 + gid]);
        }
        __syncthreads();
        if (i + 1 < 32) {
            const int kc = (i + 1) * 8, sn = st ^ 1;
            cpa16(&Wm[sn][t][0], &W[(o0 + t) * 256 + kc]);
            cpa16(&Wm[sn][t][4], &W[(o0 + t) * 256 + kc + 4]);
            cpa16(&Xs[sn][xr][xc],     &Xb[(size_t)(kc + xr) * NHW + s0 + xc]);
            cpa16(&Xs[sn][xr][xc + 4], &Xb[(size_t)(kc + xr) * NHW + s0 + xc + 4]);
        }
        CP_COMMIT();
#pragma unroll
        for (int mt = 0; mt < 4; mt++)
#pragma unroll
            for (int nt = 0; nt < 8; nt++)
                mma_tf32(c[mt][nt], afr[mt], bfr[nt]);
    }

#pragma unroll
    for (int mt = 0; mt < 4; mt++) {
        int oa = o0 + mrow + mt * 16 + gid;
        int ob = oa + 8;
        float ba  = bias ? bias[oa] : 0.f;
        float bb_ = bias ? bias[ob] : 0.f;
        float* ya = Y + (size_t)(b * NC + oa) * NHW + s0;
        float* yb = Y + (size_t)(b * NC + ob) * NHW + s0;
#pragma unroll
        for (int nt = 0; nt < 8; nt++) {
            int sc = ncol + nt * 8 + tig * 2;
            *(float2*)&ya[sc] = make_float2(c[mt][nt][0] + ba,  c[mt][nt][1] + ba);
            *(float2*)&yb[sc] = make_float2(c[mt][nt][2] + bb_, c[mt][nt][3] + bb_);
        }
    }
}

// ---------------- reversed copy ----------------------------------------------
__global__ void __launch_bounds__(256) k_revx(const float* __restrict__ X)
{
    const int ch = blockIdx.x;
    const int seg = blockIdx.y;
    const float* src = X + (size_t)ch * NHW;
    float* dst = g_xrev + (size_t)ch * NHW;
    int s = seg * 1024 + threadIdx.x;
#pragma unroll
    for (int i = 0; i < 4; i++, s += 256) {
        int y = s / 96, x = s - y * 96;
        int ry = (y == 0) ? 0 : 96 - y;
        int rx = (x == 0) ? 0 : 96 - x;
        dst[s] = src[ry * 96 + rx];
    }
}

// ---------------- m[b][c] = sum_s x[b][c][s] ----------------
__global__ void __launch_bounds__(256) k_xsum(const float* __restrict__ X)
{
    const int bc = blockIdx.x;
    const float4* x4 = (const float4*)(X + (size_t)bc * NHW);
    float s = 0.f;
    for (int i = threadIdx.x; i < NHW / 4; i += 256) {
        float4 a = x4[i]; s += a.x + a.y + a.z + a.w;
    }
#pragma unroll
    for (int o = 16; o; o >>= 1) s += __shfl_xor_sync(0xffffffff, s, o);
    __shared__ float sb[8];
    int w = threadIdx.x >> 5;
    if ((threadIdx.x & 31) == 0) sb[w] = s;
    __syncthreads();
    if (threadIdx.x == 0) {
        float a = 0.f;
        for (int i = 0; i < 8; i++) a += sb[i];
        g_m[bc] = a;
    }
}

// ---------------- Gram GEMM (tf32, cp.async 2-stage), partial tiles ----------
__global__ void __launch_bounds__(128) k_gram6(const float* __restrict__ X)
{
    const int sch = blockIdx.x, pr = blockIdx.y;
    const int b = blockIdx.z >> 1, mat = blockIdx.z & 1;
    const int ci = (pr == 2) ? 1 : 0;
    const int dj = (pr == 0) ? 0 : 1;
    __shared__ __align__(16) float Am[2][128][12];   // [m][k]
    __shared__ __align__(16) float Dm[2][128][12];   // [n][k]
    const float* Xa = X + (size_t)b * NC * NHW;
    const float* Xd = (mat ? g_xrev : X) + (size_t)b * NC * NHW;
    const int t = threadIdx.x;
    const int warp = t >> 5, lane = t & 31;
    const int gid = lane >> 2, tig = lane & 3;
    const int mrow = (warp >> 1) * 64;
    const int ncol = (warp & 1) * 64;
    const int base = sch * (NHW / KCH);
    const float* arow = &Xa[(size_t)(ci * 128 + t) * NHW + base];
    const float* drow = &Xd[(size_t)(dj * 128 + t) * NHW + base];

    float c[4][8][4];
#pragma unroll
    for (int i = 0; i < 4; i++)
#pragma unroll
        for (int j = 0; j < 8; j++)
#pragma unroll
            for (int q = 0; q < 4; q++) c[i][j][q] = 0.f;

    cpa16(&Am[0][t][0], &arow[0]);
    cpa16(&Am[0][t][4], &arow[4]);
    cpa16(&Dm[0][t][0], &drow[0]);
    cpa16(&Dm[0][t][4], &drow[4]);
    CP_COMMIT();

    const int NKS = NHW / (KCH * 8);   // 48
    for (int i = 0; i < NKS; i++) {
        const int st = i & 1;
        CP_WAIT0();
        __syncthreads();
        uint32_t afr[4][4], bfr[8][2];
#pragma unroll
        for (int mt = 0; mt < 4; mt++) {
            int m0 = mrow + mt * 16;
            afr[mt][0] = f2tf32(Am[st][m0 + gid][tig]);
            afr[mt][1] = f2tf32(Am[st][m0 + gid + 8][tig]);
            afr[mt][2] = f2tf32(Am[st][m0 + gid][tig + 4]);
            afr[mt][3] = f2tf32(Am[st][m0 + gid + 8][tig + 4]);
        }
#pragma unroll
        for (int nt = 0; nt < 8; nt++) {
            int n0 = ncol + nt * 8;
            bfr[nt][0] = f2tf32(Dm[st][n0 + gid][tig]);
            bfr[nt][1] = f2tf32(Dm[st][n0 + gid][tig + 4]);
        }
        __syncthreads();
        if (i + 1 < NKS) {
            const int ko = (i + 1) * 8, sn = st ^ 1;
            cpa16(&Am[sn][t][0], &arow[ko]);
            cpa16(&Am[sn][t][4], &arow[ko + 4]);
            cpa16(&Dm[sn][t][0], &drow[ko]);
            cpa16(&Dm[sn][t][4], &drow[ko + 4]);
        }
        CP_COMMIT();
#pragma unroll
        for (int mt = 0; mt < 4; mt++)
#pragma unroll
            for (int nt = 0; nt < 8; nt++)
                mma_tf32(c[mt][nt], afr[mt], bfr[nt]);
    }

    float* Out = g_gp + ((size_t)(blockIdx.z * 3 + pr) * KCH + sch) * 16384;
#pragma unroll
    for (int mt = 0; mt < 4; mt++) {
        int ra = mrow + mt * 16 + gid;
        int rb = ra + 8;
#pragma unroll
        for (int nt = 0; nt < 8; nt++) {
            int col = ncol + nt * 8 + tig * 2;
            *(float2*)&Out[ra * 128 + col] = make_float2(c[mt][nt][0], c[mt][nt][1]);
            *(float2*)&Out[rb * 128 + col] = make_float2(c[mt][nt][2], c[mt][nt][3]);
        }
    }
}

// ---------------- reduce partials into S / M --------------------------------
__global__ void __launch_bounds__(256) k_gred()
{
    const int pr = blockIdx.y, bm = blockIdx.z;
    const int b = bm >> 1, mat = bm & 1;
    const int ci = (pr == 2) ? 1 : 0;
    const int dj = (pr == 0) ? 0 : 1;
    const int off = blockIdx.x * 256 + threadIdx.x;
    const float* Pp = g_gp + (size_t)(bm * 3 + pr) * KCH * 16384 + off;
    float s = 0.f;
#pragma unroll
    for (int c = 0; c < KCH; c++) s += Pp[c * 16384];
    int il = off >> 7, jl = off & 127;
    float* Out = (mat ? g_M : g_S) + b * 65536;
    Out[(ci * 128 + il) * 256 + dj * 128 + jl] = s;
}

// ---------------- mirror lower-left 128x128 block ---------------------------
__global__ void k_mirror()
{
    const int bm = blockIdx.y;
    float* Out = (bm & 1 ? g_M : g_S) + (bm >> 1) * 65536;
    int idx = blockIdx.x * 256 + threadIdx.x;
    int i = idx >> 7, jl = idx & 127;
    Out[(128 + jl) * 256 + i] = Out[i * 256 + 128 + jl];
}

// ---------------- P[b] = M[b] * W2^T ----------------------------------------
__global__ void __launch_bounds__(256) k_mmA(const float* __restrict__ Wg)
{
    const int j0 = blockIdx.x * 64, i0 = blockIdx.y * 64, b = blockIdx.z;
    const float* A = g_M + b * 65536;
    float* C = g_P + b * 65536;
    __shared__ float As[16][68];
    __shared__ float Bs[16][68];
    const int t = threadIdx.x;
    const int it = (t >> 4) * 4, jt = (t & 15) * 4;
    float acc[4][4];
#pragma unroll
    for (int i = 0; i < 4; i++)
#pragma unroll
        for (int j = 0; j < 4; j++) acc[i][j] = 0.f;
    for (int kc = 0; kc < 256; kc += 16) {
        __syncthreads();
#pragma unroll
        for (int i = 0; i < 4; i++) {
            int idx = i * 256 + t;
            int r = idx >> 4, kk = idx & 15;
            As[kk][r] = A[(i0 + r) * 256 + kc + kk];
            Bs[kk][r] = Wg[(j0 + r) * 256 + kc + kk];
        }
        __syncthreads();
#pragma unroll
        for (int kk = 0; kk < 16; kk++) {
            float a[4], bb[4];
            *(float4*)a  = *(float4*)&As[kk][it];
            *(float4*)bb = *(float4*)&Bs[kk][jt];
#pragma unroll
            for (int i = 0; i < 4; i++)
#pragma unroll
                for (int j = 0; j < 4; j++) acc[i][j] += a[i] * bb[j];
        }
    }
#pragma unroll
    for (int i = 0; i < 4; i++)
#pragma unroll
        for (int j = 0; j < 4; j++)
            C[(i0 + it + i) * 256 + j0 + jt + j] = acc[i][j];
}

// ---------------- C[b] = Ag * B[b] ------------------------------------------
__global__ void __launch_bounds__(256) k_mmB(
    const float* __restrict__ Ag, const float* __restrict__ Bb, float* __restrict__ Cb)
{
    const int j0 = blockIdx.x * 64, i0 = blockIdx.y * 64, b = blockIdx.z;
    const float* B = Bb + b * 65536;
    float* C = Cb + b * 65536;
    __shared__ float As[16][68];
    __shared__ float Bs[16][68];
    const int t = threadIdx.x;
    const int it = (t >> 4) * 4, jt = (t & 15) * 4;
    float acc[4][4];
#pragma unroll
    for (int i = 0; i < 4; i++)
#pragma unroll
        for (int j = 0; j < 4; j++) acc[i][j] = 0.f;
    for (int kc = 0; kc < 256; kc += 16) {
        __syncthreads();
#pragma unroll
        for (int i = 0; i < 4; i++) {
            int idx = i * 256 + t;
            int r = idx >> 4, kk = idx & 15;
            As[kk][r] = Ag[(i0 + r) * 256 + kc + kk];
        }
#pragma unroll
        for (int i = 0; i < 4; i++) {
            int idx = i * 256 + t;
            int kk = idx >> 6, j = idx & 63;
            Bs[kk][j] = B[(kc + kk) * 256 + j0 + j];
        }
        __syncthreads();
#pragma unroll
        for (int kk = 0; kk < 16; kk++) {
            float a[4], bb[4];
            *(float4*)a  = *(float4*)&As[kk][it];
            *(float4*)bb = *(float4*)&Bs[kk][jt];
#pragma unroll
            for (int i = 0; i < 4; i++)
#pragma unroll
                for (int j = 0; j < 4; j++) acc[i][j] += a[i] * bb[j];
        }
    }
#pragma unroll
    for (int i = 0; i < 4; i++)
#pragma unroll
        for (int j = 0; j < 4; j++)
            C[(i0 + it + i) * 256 + j0 + jt + j] = acc[i][j];
}

// ---------------- row-dot: norms + W*m --------------------------------------
__global__ void __launch_bounds__(256) k_rowdot(
    const float* __restrict__ U, const float* __restrict__ W,
    const float* __restrict__ bias, float* __restrict__ outN, float* __restrict__ outWM)
{
    const int bC = blockIdx.x;
    const int b = bC >> 8, C = bC & 255;
    const int t = threadIdx.x;
    float wv = W[C * 256 + t];
    float un = U[(size_t)b * 65536 + C * 256 + t] * wv;
    float wm = wv * g_m[b * 256 + t];
#pragma unroll
    for (int o = 16; o; o >>= 1) {
        un += __shfl_xor_sync(0xffffffff, un, o);
        wm += __shfl_xor_sync(0xffffffff, wm, o);
    }
    __shared__ float s1[8], s2[8];
    int w = t >> 5;
    if ((t & 31) == 0) { s1[w] = un; s2[w] = wm; }
    __syncthreads();
    if (t == 0) {
        float a = 0.f, c = 0.f;
        for (int i = 0; i < 8; i++) { a += s1[i]; c += s2[i]; }
        float bc = bias[C];
        outWM[bC] = c;
        outN[bC] = a + 2.f * bc * c + 9216.f * bc * bc;
    }
}

// ---------------- attn: logits, softmax, build Chat -------------------------
__global__ void __launch_bounds__(256) k_attn2(
    const float* __restrict__ b1, const float* __restrict__ b2,
    const float* __restrict__ temperature)
{
    const int bh = blockIdx.x;
    const int b = bh >> 3, h = bh & 7;
    const int ch0 = h * 32;
    __shared__ float A[32][33];
    __shared__ float rq[32], rk[32], sw1m[32], sw2m[32], sb1[32], sb2[32];
    __shared__ float2 tab[32];
    const int t = threadIdx.x;
    if (t < 32) {
        int C = b * 256 + ch0 + t;
        rq[t] = rsqrtf(g_nq[C]);
        rk[t] = rsqrtf(g_nk[C]);
        sw1m[t] = g_w1m[C];
        sw2m[t] = g_w2m[C];
        sb1[t] = b1[ch0 + t];
        sb2[t] = b2[ch0 + t];
        float ang = 6.283185307179586f * (float)t / 32.0f;
        tab[t] = make_float2(cosf(ang), sinf(ang));
    }
    __syncthreads();
    const float ts = temperature[h];
    const int w = t >> 5, lane = t & 31;
    for (int r = w; r < 32; r += 8) {
        float Gv = g_Gf[(size_t)b * 65536 + (ch0 + r) * 256 + ch0 + lane];
        float L = (Gv + sw1m[r] * sb2[lane] + sb1[r] * sw2m[lane]
                   + 9216.f * sb1[r] * sb2[lane]) * rq[r] * rk[lane] * ts;
        float m = L;
#pragma unroll
        for (int o = 16; o; o >>= 1) m = fmaxf(m, __shfl_xor_sync(0xffffffff, m, o));
        float e = expf(L - m);
        float s = e;
#pragma unroll
        for (int o = 16; o; o >>= 1) s += __shfl_xor_sync(0xffffffff, s, o);
        A[r][lane] = e / s;
    }
    __syncthreads();
    for (int idx = t; idx < 1024; idx += 256) {
        int e = idx >> 5, d = idx & 31;
        float re = 0.f, im = 0.f;
#pragma unroll 8
        for (int c = 0; c < 32; c++) {
            float a = A[c][d];
            float2 tb = tab[(c * e) & 31];
            re += a * tb.x; im += a * tb.y;
        }
        re *= (1.0f / 32.0f); im *= (1.0f / 32.0f);
        if (e == 0) im += (1.0f / 32.0f);
        g_Chat[bh * 1024 + idx] = make_float2(re, im);
    }
}

// ---------------- g table (stable half-angle form) ----------------
__global__ void k_gtab()
{
    int idx = blockIdx.x * 256 + threadIdx.x;
    if (idx >= 96 * 96) return;
    int hr = idx / 96, tt = idx - hr * 96;
    float2 g;
    if (hr == 0) {
        g = make_float2(tt == 0 ? 1.f : 0.f, 0.f);
    } else {
        const float PI = 3.14159265358979323846f;
        float h1 = PI * (float)hr / 96.0f;
        float h2 = PI * (96.0f * (float)tt + (float)hr) / 9216.0f;
        float r = sinf(h1) / (96.0f * sinf(h2));
        float psi = h1 - h2;
        g = make_float2(r * cosf(psi), r * sinf(psi));
    }
    g_gtab[idx] = g;
}

// ---------------- circulant tables: gc[r][w][a] = g[r][(a-w)%96] -------------
__global__ void k_gtab2()
{
    int idx = blockIdx.x * 256 + threadIdx.x;
    int r = idx / 9216;
    int rem = idx - r * 9216;
    int w = rem / 96, a = rem - w * 96;
    int tt = a - w; if (tt < 0) tt += 96;
    float2 g = g_gtab[r * 96 + tt];
    g_gcre[idx] = g.x;
    g_gcim[idx] = g.y;
}

// ---------------- conv as batched tf32 GEMM ---------------------------------
__global__ void __launch_bounds__(128) k_vconv()
{
    const int r = blockIdx.x;
    const int ch0 = blockIdx.y * 64;
    __shared__ __align__(16) uint32_t As[8][72];
    __shared__ __align__(16) uint32_t Br[8][104];
    __shared__ __align__(16) uint32_t Bi[8][104];
    const int t = threadIdx.x;
    const int warp = t >> 5, lane = t & 31;
    const int gid = lane >> 2, tig = lane & 3;
    const int mrow = (warp >> 1) * 32;
    const int ncol = (warp & 1) * 48;
    const int ach = t >> 1, aw4 = (t & 1) * 4;
    const int bw = t >> 4, ba0 = (t & 15) * 6;

    float cre[2][6][4], cim[2][6][4];
#pragma unroll
    for (int i = 0; i < 2; i++)
#pragma unroll
        for (int j = 0; j < 6; j++)
#pragma unroll
            for (int q = 0; q < 4; q++) { cre[i][j][q] = 0.f; cim[i][j][q] = 0.f; }

    float4 av;
    float br[6], bi[6];
    av = *(const float4*)&g_v[(size_t)(ch0 + ach) * NHW + r * 96 + aw4];
    {
        const float* pr_ = &g_gcre[(size_t)r * 9216 + bw * 96 + ba0];
        const float* pi_ = &g_gcim[(size_t)r * 9216 + bw * 96 + ba0];
#pragma unroll
        for (int i = 0; i < 6; i++) { br[i] = pr_[i]; bi[i] = pi_[i]; }
    }

    for (int ks = 0; ks < 12; ks++) {
        __syncthreads();
        As[aw4 + 0][ach] = f2tf32(av.x);
        As[aw4 + 1][ach] = f2tf32(av.y);
        As[aw4 + 2][ach] = f2tf32(av.z);
        As[aw4 + 3][ach] = f2tf32(av.w);
#pragma unroll
        for (int i = 0; i < 6; i++) {
            Br[bw][ba0 + i] = f2tf32(br[i]);
            Bi[bw][ba0 + i] = f2tf32(bi[i]);
        }
        __syncthreads();

        int w0n = (ks + 1 < 12) ? (ks + 1) * 8 : 0;
        av = *(const float4*)&g_v[(size_t)(ch0 + ach) * NHW + r * 96 + w0n + aw4];
        {
            const float* pr_ = &g_gcre[(size_t)r * 9216 + (w0n + bw) * 96 + ba0];
            const float* pi_ = &g_gcim[(size_t)r * 9216 + (w0n + bw) * 96 + ba0];
#pragma unroll
            for (int i = 0; i < 6; i++) { br[i] = pr_[i]; bi[i] = pi_[i]; }
        }

        uint32_t afr[2][4], bre[6][2], bim[6][2];
#pragma unroll
        for (int mt = 0; mt < 2; mt++) {
            int m0 = mrow + mt * 16;
            afr[mt][0] = As[tig][m0 + gid];
            afr[mt][1] = As[tig][m0 + gid + 8];
            afr[mt][2] = As[tig + 4][m0 + gid];
            afr[mt][3] = As[tig + 4][m0 + gid + 8];
        }
#pragma unroll
        for (int nt = 0; nt < 6; nt++) {
            int n0 = ncol + nt * 8;
            bre[nt][0] = Br[tig][n0 + gid];
            bre[nt][1] = Br[tig + 4][n0 + gid];
            bim[nt][0] = Bi[tig][n0 + gid];
            bim[nt][1] = Bi[tig + 4][n0 + gid];
        }
#pragma unroll
        for (int mt = 0; mt < 2; mt++)
#pragma unroll
            for (int nt = 0; nt < 6; nt++) {
                mma_tf32(cre[mt][nt], afr[mt], bre[nt]);
                mma_tf32(cim[mt][nt], afr[mt], bim[nt]);
            }
    }

#pragma unroll
    for (int mt = 0; mt < 2; mt++) {
        int r0 = ch0 + mrow + mt * 16 + gid;
        int r1 = r0 + 8;
        float2* p0 = &g_Tt[(size_t)r0 * NHW + r * 96];
        float2* p1 = &g_Tt[(size_t)r1 * NHW + r * 96];
#pragma unroll
        for (int nt = 0; nt < 6; nt++) {
            int a = ncol + nt * 8 + tig * 2;
            p0[a]     = make_float2(cre[mt][nt][0], cim[mt][nt][0]);
            p0[a + 1] = make_float2(cre[mt][nt][1], cim[mt][nt][1]);
            p1[a]     = make_float2(cre[mt][nt][2], cim[mt][nt][2]);
            p1[a + 1] = make_float2(cre[mt][nt][3], cim[mt][nt][3]);
        }
    }
}

// ---------------- mix: Rp[bh*32+e][s] = | sum_d Chat[e][d] * T[bh*32+d][s] |
__global__ void __launch_bounds__(256) k_mix()
{
    const int s0 = blockIdx.x * 128;
    const int bh = blockIdx.y;
    __shared__ float2 Ch[1024];
    __shared__ float2 Ts[32][128];
    const int t = threadIdx.x;
    for (int i = t; i < 1024; i += 256) Ch[i] = g_Chat[bh * 1024 + i];
    for (int i = t; i < 4096; i += 256) {
        int d = i >> 7, j = i & 127;
        Ts[d][j] = g_Tt[(size_t)(bh * 32 + d) * NHW + s0 + j];
    }
    __syncthreads();
    const int sl = t & 63, eg = t >> 6;
    float ar0[8], ai0[8], ar1[8], ai1[8];
#pragma unroll
    for (int i = 0; i < 8; i++) { ar0[i] = ai0[i] = ar1[i] = ai1[i] = 0.f; }

    for (int d = 0; d < 32; d++) {
        float2 t0 = Ts[d][sl];
        float2 t1 = Ts[d][sl + 64];
#pragma unroll
        for (int i = 0; i < 8; i++) {
            float2 c = Ch[(eg * 8 + i) * 32 + d];
            ar0[i] += c.x * t0.x - c.y * t0.y;
            ai0[i] += c.x * t0.y + c.y * t0.x;
            ar1[i] += c.x * t1.x - c.y * t1.y;
            ai1[i] += c.x * t1.y + c.y * t1.x;
        }
    }
#pragma unroll
    for (int i = 0; i < 8; i++) {
        int row = bh * 32 + eg * 8 + i;
        g_xrev[(size_t)row * NHW + s0 + sl]      = sqrtf(ar0[i] * ar0[i] + ai0[i] * ai0[i]);
        g_xrev[(size_t)row * NHW + s0 + sl + 64] = sqrtf(ar1[i] * ar1[i] + ai1[i] * ai1[i]);
    }
}

// ---------------- real transpose: R[ch][a*96+r] = Rp[ch][r*96+a] -------------
__global__ void __launch_bounds__(256) k_trR()
{
    const int ch = blockIdx.x;
    const int tile = blockIdx.y;
    const int tr = (tile / 3) * 32;
    const int tc = (tile % 3) * 32;
    __shared__ float s[32][33];
    const int t = threadIdx.x;
    const size_t base = (size_t)ch * NHW;
#pragma unroll
    for (int i = 0; i < 4; i++) {
        int idx = i * 256 + t;
        int r = idx >> 5, c = idx & 31;
        s[r][c] = g_xrev[base + (size_t)(tr + r) * 96 + tc + c];
    }
    __syncthreads();
#pragma unroll
    for (int i = 0; i < 4; i++) {
        int idx = i * 256 + t;
        int r = idx >> 5, c = idx & 31;
        g_R[base + (size_t)(tc + r) * 96 + tr + c] = s[c][r];
    }
}

// ---------------- launch ----------------
extern "C" void kernel_launch(void* const* d_in, const int* in_sizes, int n_in,
                              void* d_out, int out_size)
{
    const float* x    = (const float*)d_in[0];
    const float* w1   = (const float*)d_in[1];
    const float* b1   = (const float*)d_in[2];
    const float* w2   = (const float*)d_in[3];
    const float* b2   = (const float*)d_in[4];
    const float* w3   = (const float*)d_in[5];
    const float* b3   = (const float*)d_in[6];
    const float* wo   = (const float*)d_in[7];
    const float* temp = (const float*)d_in[8];
    float* out = (float*)d_out;

    float *vp = nullptr, *Rp = nullptr, *Pp = nullptr, *Sp = nullptr, *Gfp = nullptr;
    float *nqp = nullptr, *nkp = nullptr, *w1mp = nullptr, *w2mp = nullptr;
    cudaGetSymbolAddress((void**)&vp,  g_v);
    cudaGetSymbolAddress((void**)&Rp,  g_R);
    cudaGetSymbolAddress((void**)&Pp,  g_P);
    cudaGetSymbolAddress((void**)&Sp,  g_S);
    cudaGetSymbolAddress((void**)&Gfp, g_Gf);
    cudaGetSymbolAddress((void**)&nqp,  g_nq);
    cudaGetSymbolAddress((void**)&nkp,  g_nk);
    cudaGetSymbolAddress((void**)&w1mp, g_w1m);
    cudaGetSymbolAddress((void**)&w2mp, g_w2m);

    dim3 gg(72, 2, 8);
    dim3 gm(4, 4, 8);

    k_gemm_tf32<<<gg, 128>>>(x, w3, b3, vp);            // v
    k_revx   <<<dim3(2048, 9), 256>>>(x);
    k_xsum   <<<2048, 256>>>(x);
    k_gram6  <<<dim3(KCH, 3, 16), 128>>>(x);            // partial tiles (tf32 + cp.async)
    k_gred   <<<dim3(64, 3, 16), 256>>>();              // -> S, M
    k_mirror <<<dim3(64, 16), 256>>>();
    k_mmA    <<<gm, 256>>>(w2);                         // P = M * W2^T
    k_mmB    <<<gm, 256>>>(w1, Pp, Gfp);                // Gf = W1 * P
    k_mmB    <<<gm, 256>>>(w1, Sp, Pp);                 // U1 = W1 * S
    k_rowdot <<<2048, 256>>>(Pp, w1, b1, nqp, w1mp);
    k_mmB    <<<gm, 256>>>(w2, Sp, Pp);                 // U2 = W2 * S
    k_rowdot <<<2048, 256>>>(Pp, w2, b2, nkp, w2mp);
    k_gtab   <<<36, 256>>>();
    k_gtab2  <<<3456, 256>>>();
    k_attn2  <<<64, 256>>>(b1, b2, temp);
    k_vconv  <<<dim3(96, 32), 128>>>();                 // conv via tensor cores
    k_mix    <<<dim3(72, 64), 256>>>();                 // -> Rp (g_xrev)
    k_trR    <<<dim3(2048, 9), 256>>>();                // -> R
    k_gemm_tf32<<<gg, 128>>>(Rp, wo, nullptr, out);
}

// round 11
// speedup vs baseline: 2.5799x; 1.1039x over previous
#include <cuda_runtime.h>
#include <math.h>
#include <stdint.h>

#define NB 8
#define NC 256
#define NHW 9216
#define NHEAD 8
#define KCH 24            // gram split-K chunks

// ---------------- scratch (device globals; no allocation anywhere) ----------
__device__ float  g_v[NB*NC*NHW];         // 75.5 MB
__device__ float  g_xrev[NB*NC*NHW];      // 75.5 MB
__device__ float  g_gp[KCH*3*16*128*128]; // 75.5 MB gram partials; first 2MB reused as U2
__device__ float  g_S[NB*256*256];
__device__ float  g_M[NB*256*256];
__device__ float  g_P[NB*256*256];
__device__ float  g_Gf[NB*256*256];
__device__ float  g_m[NB*256];
__device__ float  g_nq[NB*256], g_nk[NB*256];
__device__ float  g_w1m[NB*256], g_w2m[NB*256];
__device__ float2 g_Chat[64*1024];
__device__ float  g_gcre[96*96*96];       // circulant conv tables
__device__ float  g_gcim[96*96*96];
__device__ float2 g_Tt[NB*NC*NHW];        // 151 MB, layout [ch][r][a]
__device__ float  g_R [NB*NC*NHW];

// ---------------- tf32 / cp.async helpers ------------------------------------
__device__ __forceinline__ uint32_t f2tf32(float x) {
    uint32_t r;
    asm("cvt.rna.tf32.f32 %0, %1;" : "=r"(r) : "f"(x));
    return r;
}
__device__ __forceinline__ void mma_tf32(float* c, const uint32_t* a, const uint32_t* b) {
    asm volatile(
        "mma.sync.aligned.m16n8k8.row.col.f32.tf32.tf32.f32 "
        "{%0,%1,%2,%3}, {%4,%5,%6,%7}, {%8,%9}, {%0,%1,%2,%3};"
        : "+f"(c[0]), "+f"(c[1]), "+f"(c[2]), "+f"(c[3])
        : "r"(a[0]), "r"(a[1]), "r"(a[2]), "r"(a[3]), "r"(b[0]), "r"(b[1]));
}
__device__ __forceinline__ void cpa16(void* dst, const void* src) {
    uint32_t d = (uint32_t)__cvta_generic_to_shared(dst);
    asm volatile("cp.async.cg.shared.global [%0], [%1], 16;" :: "r"(d), "l"(src));
}
#define CP_COMMIT() asm volatile("cp.async.commit_group;")
#define CP_WAIT0()  asm volatile("cp.async.wait_group 0;")

// ---------------- tf32 GEMM: Y[b][o][s] = sum_c W[o][c] X[b][c][s] (+bias) ---
__global__ void __launch_bounds__(128) k_gemm_tf32(
    const float* __restrict__ X, const float* __restrict__ W,
    const float* __restrict__ bias, float* __restrict__ Y)
{
    __shared__ __align__(16) float Wm[2][128][12];
    __shared__ __align__(16) float Xs[2][8][136];
    const int t  = threadIdx.x;
    const int s0 = blockIdx.x * 128;
    const int o0 = blockIdx.y * 128;
    const int b  = blockIdx.z;
    const int warp = t >> 5, lane = t & 31;
    const int gid = lane >> 2, tig = lane & 3;
    const int mrow = (warp >> 1) * 64;
    const int ncol = (warp & 1) * 64;
    const float* Xb = X + (size_t)b * NC * NHW;
    const int xr = t >> 4, xc = (t & 15) * 8;

    float c[4][8][4];
#pragma unroll
    for (int i = 0; i < 4; i++)
#pragma unroll
        for (int j = 0; j < 8; j++)
#pragma unroll
            for (int q = 0; q < 4; q++) c[i][j][q] = 0.f;

    cpa16(&Wm[0][t][0], &W[(o0 + t) * 256 + 0]);
    cpa16(&Wm[0][t][4], &W[(o0 + t) * 256 + 4]);
    cpa16(&Xs[0][xr][xc],     &Xb[(size_t)xr * NHW + s0 + xc]);
    cpa16(&Xs[0][xr][xc + 4], &Xb[(size_t)xr * NHW + s0 + xc + 4]);
    CP_COMMIT();

    for (int i = 0; i < 32; i++) {
        const int st = i & 1;
        CP_WAIT0();
        __syncthreads();
        uint32_t afr[4][4], bfr[8][2];
#pragma unroll
        for (int mt = 0; mt < 4; mt++) {
            int m0 = mrow + mt * 16;
            afr[mt][0] = f2tf32(Wm[st][m0 + gid][tig]);
            afr[mt][1] = f2tf32(Wm[st][m0 + gid + 8][tig]);
            afr[mt][2] = f2tf32(Wm[st][m0 + gid][tig + 4]);
            afr[mt][3] = f2tf32(Wm[st][m0 + gid + 8][tig + 4]);
        }
#pragma unroll
        for (int nt = 0; nt < 8; nt++) {
            int n0 = ncol + nt * 8;
            bfr[nt][0] = f2tf32(Xs[st][tig][n0 + gid]);
            bfr[nt][1] = f2tf32(Xs[st][tig + 4][n0 + gid]);
        }
        __syncthreads();
        if (i + 1 < 32) {
            const int kc = (i + 1) * 8, sn = st ^ 1;
            cpa16(&Wm[sn][t][0], &W[(o0 + t) * 256 + kc]);
            cpa16(&Wm[sn][t][4], &W[(o0 + t) * 256 + kc + 4]);
            cpa16(&Xs[sn][xr][xc],     &Xb[(size_t)(kc + xr) * NHW + s0 + xc]);
            cpa16(&Xs[sn][xr][xc + 4], &Xb[(size_t)(kc + xr) * NHW + s0 + xc + 4]);
        }
        CP_COMMIT();
#pragma unroll
        for (int mt = 0; mt < 4; mt++)
#pragma unroll
            for (int nt = 0; nt < 8; nt++)
                mma_tf32(c[mt][nt], afr[mt], bfr[nt]);
    }

#pragma unroll
    for (int mt = 0; mt < 4; mt++) {
        int oa = o0 + mrow + mt * 16 + gid;
        int ob = oa + 8;
        float ba  = bias ? bias[oa] : 0.f;
        float bb_ = bias ? bias[ob] : 0.f;
        float* ya = Y + (size_t)(b * NC + oa) * NHW + s0;
        float* yb = Y + (size_t)(b * NC + ob) * NHW + s0;
#pragma unroll
        for (int nt = 0; nt < 8; nt++) {
            int sc = ncol + nt * 8 + tig * 2;
            *(float2*)&ya[sc] = make_float2(c[mt][nt][0] + ba,  c[mt][nt][1] + ba);
            *(float2*)&yb[sc] = make_float2(c[mt][nt][2] + bb_, c[mt][nt][3] + bb_);
        }
    }
}

// ---------------- zero g_m ----------------------------------------------------
__global__ void k_zm() { g_m[blockIdx.x * 256 + threadIdx.x] = 0.f; }

// ---------------- reversed copy + fused channel sum --------------------------
__global__ void __launch_bounds__(256) k_revx(const float* __restrict__ X)
{
    const int ch = blockIdx.x;
    const int seg = blockIdx.y;
    const float* src = X + (size_t)ch * NHW;
    float* dst = g_xrev + (size_t)ch * NHW;
    int s = seg * 1024 + threadIdx.x;
    float lsum = 0.f;
#pragma unroll
    for (int i = 0; i < 4; i++, s += 256) {
        int y = s / 96, x = s - y * 96;
        int ry = (y == 0) ? 0 : 96 - y;
        int rx = (x == 0) ? 0 : 96 - x;
        float v = src[ry * 96 + rx];
        dst[s] = v;
        lsum += v;
    }
#pragma unroll
    for (int o = 16; o; o >>= 1) lsum += __shfl_xor_sync(0xffffffff, lsum, o);
    __shared__ float sb[8];
    int w = threadIdx.x >> 5;
    if ((threadIdx.x & 31) == 0) sb[w] = lsum;
    __syncthreads();
    if (threadIdx.x == 0) {
        float a = 0.f;
        for (int i = 0; i < 8; i++) a += sb[i];
        atomicAdd(&g_m[ch], a);
    }
}

// ---------------- Gram GEMM (tf32, cp.async 2-stage), partial tiles ----------
__global__ void __launch_bounds__(128) k_gram6(const float* __restrict__ X)
{
    const int sch = blockIdx.x, pr = blockIdx.y;
    const int b = blockIdx.z >> 1, mat = blockIdx.z & 1;
    const int ci = (pr == 2) ? 1 : 0;
    const int dj = (pr == 0) ? 0 : 1;
    __shared__ __align__(16) float Am[2][128][12];
    __shared__ __align__(16) float Dm[2][128][12];
    const float* Xa = X + (size_t)b * NC * NHW;
    const float* Xd = (mat ? g_xrev : X) + (size_t)b * NC * NHW;
    const int t = threadIdx.x;
    const int warp = t >> 5, lane = t & 31;
    const int gid = lane >> 2, tig = lane & 3;
    const int mrow = (warp >> 1) * 64;
    const int ncol = (warp & 1) * 64;
    const int base = sch * (NHW / KCH);
    const float* arow = &Xa[(size_t)(ci * 128 + t) * NHW + base];
    const float* drow = &Xd[(size_t)(dj * 128 + t) * NHW + base];

    float c[4][8][4];
#pragma unroll
    for (int i = 0; i < 4; i++)
#pragma unroll
        for (int j = 0; j < 8; j++)
#pragma unroll
            for (int q = 0; q < 4; q++) c[i][j][q] = 0.f;

    cpa16(&Am[0][t][0], &arow[0]);
    cpa16(&Am[0][t][4], &arow[4]);
    cpa16(&Dm[0][t][0], &drow[0]);
    cpa16(&Dm[0][t][4], &drow[4]);
    CP_COMMIT();

    const int NKS = NHW / (KCH * 8);   // 48
    for (int i = 0; i < NKS; i++) {
        const int st = i & 1;
        CP_WAIT0();
        __syncthreads();
        uint32_t afr[4][4], bfr[8][2];
#pragma unroll
        for (int mt = 0; mt < 4; mt++) {
            int m0 = mrow + mt * 16;
            afr[mt][0] = f2tf32(Am[st][m0 + gid][tig]);
            afr[mt][1] = f2tf32(Am[st][m0 + gid + 8][tig]);
            afr[mt][2] = f2tf32(Am[st][m0 + gid][tig + 4]);
            afr[mt][3] = f2tf32(Am[st][m0 + gid + 8][tig + 4]);
        }
#pragma unroll
        for (int nt = 0; nt < 8; nt++) {
            int n0 = ncol + nt * 8;
            bfr[nt][0] = f2tf32(Dm[st][n0 + gid][tig]);
            bfr[nt][1] = f2tf32(Dm[st][n0 + gid][tig + 4]);
        }
        __syncthreads();
        if (i + 1 < NKS) {
            const int ko = (i + 1) * 8, sn = st ^ 1;
            cpa16(&Am[sn][t][0], &arow[ko]);
            cpa16(&Am[sn][t][4], &arow[ko + 4]);
            cpa16(&Dm[sn][t][0], &drow[ko]);
            cpa16(&Dm[sn][t][4], &drow[ko + 4]);
        }
        CP_COMMIT();
#pragma unroll
        for (int mt = 0; mt < 4; mt++)
#pragma unroll
            for (int nt = 0; nt < 8; nt++)
                mma_tf32(c[mt][nt], afr[mt], bfr[nt]);
    }

    float* Out = g_gp + ((size_t)(blockIdx.z * 3 + pr) * KCH + sch) * 16384;
#pragma unroll
    for (int mt = 0; mt < 4; mt++) {
        int ra = mrow + mt * 16 + gid;
        int rb = ra + 8;
#pragma unroll
        for (int nt = 0; nt < 8; nt++) {
            int col = ncol + nt * 8 + tig * 2;
            *(float2*)&Out[ra * 128 + col] = make_float2(c[mt][nt][0], c[mt][nt][1]);
            *(float2*)&Out[rb * 128 + col] = make_float2(c[mt][nt][2], c[mt][nt][3]);
        }
    }
}

// ---------------- reduce partials into S / M --------------------------------
__global__ void __launch_bounds__(256) k_gred()
{
    const int pr = blockIdx.y, bm = blockIdx.z;
    const int b = bm >> 1, mat = bm & 1;
    const int ci = (pr == 2) ? 1 : 0;
    const int dj = (pr == 0) ? 0 : 1;
    const int off = blockIdx.x * 256 + threadIdx.x;
    const float* Pp = g_gp + (size_t)(bm * 3 + pr) * KCH * 16384 + off;
    float s = 0.f;
#pragma unroll
    for (int c = 0; c < KCH; c++) s += Pp[c * 16384];
    int il = off >> 7, jl = off & 127;
    float* Out = (mat ? g_M : g_S) + b * 65536;
    Out[(ci * 128 + il) * 256 + dj * 128 + jl] = s;
}

// ---------------- mirror lower-left 128x128 block ---------------------------
__global__ void k_mirror()
{
    const int bm = blockIdx.y;
    float* Out = (bm & 1 ? g_M : g_S) + (bm >> 1) * 65536;
    int idx = blockIdx.x * 256 + threadIdx.x;
    int i = idx >> 7, jl = idx & 127;
    Out[(128 + jl) * 256 + i] = Out[i * 256 + 128 + jl];
}

// ---------------- P[b] = M[b] * W2^T ----------------------------------------
__global__ void __launch_bounds__(256) k_mmA(const float* __restrict__ Wg)
{
    const int j0 = blockIdx.x * 64, i0 = blockIdx.y * 64, b = blockIdx.z;
    const float* A = g_M + b * 65536;
    float* C = g_P + b * 65536;
    __shared__ float As[16][68];
    __shared__ float Bs[16][68];
    const int t = threadIdx.x;
    const int it = (t >> 4) * 4, jt = (t & 15) * 4;
    float acc[4][4];
#pragma unroll
    for (int i = 0; i < 4; i++)
#pragma unroll
        for (int j = 0; j < 4; j++) acc[i][j] = 0.f;
    for (int kc = 0; kc < 256; kc += 16) {
        __syncthreads();
#pragma unroll
        for (int i = 0; i < 4; i++) {
            int idx = i * 256 + t;
            int r = idx >> 4, kk = idx & 15;
            As[kk][r] = A[(i0 + r) * 256 + kc + kk];
            Bs[kk][r] = Wg[(j0 + r) * 256 + kc + kk];
        }
        __syncthreads();
#pragma unroll
        for (int kk = 0; kk < 16; kk++) {
            float a[4], bb[4];
            *(float4*)a  = *(float4*)&As[kk][it];
            *(float4*)bb = *(float4*)&Bs[kk][jt];
#pragma unroll
            for (int i = 0; i < 4; i++)
#pragma unroll
                for (int j = 0; j < 4; j++) acc[i][j] += a[i] * bb[j];
        }
    }
#pragma unroll
    for (int i = 0; i < 4; i++)
#pragma unroll
        for (int j = 0; j < 4; j++)
            C[(i0 + it + i) * 256 + j0 + jt + j] = acc[i][j];
}

// ---------------- C[b] = Ag * B[b]  (generic, used for Gf) -------------------
__global__ void __launch_bounds__(256) k_mmB(
    const float* __restrict__ Ag, const float* __restrict__ Bb, float* __restrict__ Cb)
{
    const int j0 = blockIdx.x * 64, i0 = blockIdx.y * 64, b = blockIdx.z;
    const float* B = Bb + b * 65536;
    float* C = Cb + b * 65536;
    __shared__ float As[16][68];
    __shared__ float Bs[16][68];
    const int t = threadIdx.x;
    const int it = (t >> 4) * 4, jt = (t & 15) * 4;
    float acc[4][4];
#pragma unroll
    for (int i = 0; i < 4; i++)
#pragma unroll
        for (int j = 0; j < 4; j++) acc[i][j] = 0.f;
    for (int kc = 0; kc < 256; kc += 16) {
        __syncthreads();
#pragma unroll
        for (int i = 0; i < 4; i++) {
            int idx = i * 256 + t;
            int r = idx >> 4, kk = idx & 15;
            As[kk][r] = Ag[(i0 + r) * 256 + kc + kk];
        }
#pragma unroll
        for (int i = 0; i < 4; i++) {
            int idx = i * 256 + t;
            int kk = idx >> 6, j = idx & 63;
            Bs[kk][j] = B[(kc + kk) * 256 + j0 + j];
        }
        __syncthreads();
#pragma unroll
        for (int kk = 0; kk < 16; kk++) {
            float a[4], bb[4];
            *(float4*)a  = *(float4*)&As[kk][it];
            *(float4*)bb = *(float4*)&Bs[kk][jt];
#pragma unroll
            for (int i = 0; i < 4; i++)
#pragma unroll
                for (int j = 0; j < 4; j++) acc[i][j] += a[i] * bb[j];
        }
    }
#pragma unroll
    for (int i = 0; i < 4; i++)
#pragma unroll
        for (int j = 0; j < 4; j++)
            C[(i0 + it + i) * 256 + j0 + jt + j] = acc[i][j];
}

// ---------------- batched U = W{1,2} * S  (z = b*2 + which) ------------------
__global__ void __launch_bounds__(256) k_mmU(
    const float* __restrict__ W1, const float* __restrict__ W2)
{
    const int j0 = blockIdx.x * 64, i0 = blockIdx.y * 64;
    const int b = blockIdx.z >> 1, which = blockIdx.z & 1;
    const float* Ag = which ? W2 : W1;
    const float* B = g_S + b * 65536;
    float* C = (which ? g_gp : g_P) + b * 65536;
    __shared__ float As[16][68];
    __shared__ float Bs[16][68];
    const int t = threadIdx.x;
    const int it = (t >> 4) * 4, jt = (t & 15) * 4;
    float acc[4][4];
#pragma unroll
    for (int i = 0; i < 4; i++)
#pragma unroll
        for (int j = 0; j < 4; j++) acc[i][j] = 0.f;
    for (int kc = 0; kc < 256; kc += 16) {
        __syncthreads();
#pragma unroll
        for (int i = 0; i < 4; i++) {
            int idx = i * 256 + t;
            int r = idx >> 4, kk = idx & 15;
            As[kk][r] = Ag[(i0 + r) * 256 + kc + kk];
        }
#pragma unroll
        for (int i = 0; i < 4; i++) {
            int idx = i * 256 + t;
            int kk = idx >> 6, j = idx & 63;
            Bs[kk][j] = B[(kc + kk) * 256 + j0 + j];
        }
        __syncthreads();
#pragma unroll
        for (int kk = 0; kk < 16; kk++) {
            float a[4], bb[4];
            *(float4*)a  = *(float4*)&As[kk][it];
            *(float4*)bb = *(float4*)&Bs[kk][jt];
#pragma unroll
            for (int i = 0; i < 4; i++)
#pragma unroll
                for (int j = 0; j < 4; j++) acc[i][j] += a[i] * bb[j];
        }
    }
#pragma unroll
    for (int i = 0; i < 4; i++)
#pragma unroll
        for (int j = 0; j < 4; j++)
            C[(i0 + it + i) * 256 + j0 + jt + j] = acc[i][j];
}

// ---------------- batched row-dot: norms + W*m (y = which) -------------------
__global__ void __launch_bounds__(256) k_rowdot2(
    const float* __restrict__ W1, const float* __restrict__ W2,
    const float* __restrict__ b1, const float* __restrict__ b2)
{
    const int bC = blockIdx.x;
    const int which = blockIdx.y;
    const int b = bC >> 8, C = bC & 255;
    const float* U = (which ? g_gp : g_P);
    const float* W = which ? W2 : W1;
    const float* bias = which ? b2 : b1;
    const int t = threadIdx.x;
    float wv = W[C * 256 + t];
    float un = U[(size_t)b * 65536 + C * 256 + t] * wv;
    float wm = wv * g_m[b * 256 + t];
#pragma unroll
    for (int o = 16; o; o >>= 1) {
        un += __shfl_xor_sync(0xffffffff, un, o);
        wm += __shfl_xor_sync(0xffffffff, wm, o);
    }
    __shared__ float s1[8], s2[8];
    int w = t >> 5;
    if ((t & 31) == 0) { s1[w] = un; s2[w] = wm; }
    __syncthreads();
    if (t == 0) {
        float a = 0.f, c = 0.f;
        for (int i = 0; i < 8; i++) { a += s1[i]; c += s2[i]; }
        float bc = bias[C];
        float nf = a + 2.f * bc * c + 9216.f * bc * bc;
        if (which) { g_nk[bC] = nf; g_w2m[bC] = c; }
        else       { g_nq[bC] = nf; g_w1m[bC] = c; }
    }
}

// ---------------- attn: logits, softmax, build Chat -------------------------
__global__ void __launch_bounds__(256) k_attn2(
    const float* __restrict__ b1, const float* __restrict__ b2,
    const float* __restrict__ temperature)
{
    const int bh = blockIdx.x;
    const int b = bh >> 3, h = bh & 7;
    const int ch0 = h * 32;
    __shared__ float A[32][33];
    __shared__ float rq[32], rk[32], sw1m[32], sw2m[32], sb1[32], sb2[32];
    __shared__ float2 tab[32];
    const int t = threadIdx.x;
    if (t < 32) {
        int C = b * 256 + ch0 + t;
        rq[t] = rsqrtf(g_nq[C]);
        rk[t] = rsqrtf(g_nk[C]);
        sw1m[t] = g_w1m[C];
        sw2m[t] = g_w2m[C];
        sb1[t] = b1[ch0 + t];
        sb2[t] = b2[ch0 + t];
        float ang = 6.283185307179586f * (float)t / 32.0f;
        tab[t] = make_float2(cosf(ang), sinf(ang));
    }
    __syncthreads();
    const float ts = temperature[h];
    const int w = t >> 5, lane = t & 31;
    for (int r = w; r < 32; r += 8) {
        float Gv = g_Gf[(size_t)b * 65536 + (ch0 + r) * 256 + ch0 + lane];
        float L = (Gv + sw1m[r] * sb2[lane] + sb1[r] * sw2m[lane]
                   + 9216.f * sb1[r] * sb2[lane]) * rq[r] * rk[lane] * ts;
        float m = L;
#pragma unroll
        for (int o = 16; o; o >>= 1) m = fmaxf(m, __shfl_xor_sync(0xffffffff, m, o));
        float e = expf(L - m);
        float s = e;
#pragma unroll
        for (int o = 16; o; o >>= 1) s += __shfl_xor_sync(0xffffffff, s, o);
        A[r][lane] = e / s;
    }
    __syncthreads();
    for (int idx = t; idx < 1024; idx += 256) {
        int e = idx >> 5, d = idx & 31;
        float re = 0.f, im = 0.f;
#pragma unroll 8
        for (int c = 0; c < 32; c++) {
            float a = A[c][d];
            float2 tb = tab[(c * e) & 31];
            re += a * tb.x; im += a * tb.y;
        }
        re *= (1.0f / 32.0f); im *= (1.0f / 32.0f);
        if (e == 0) im += (1.0f / 32.0f);
        g_Chat[bh * 1024 + idx] = make_float2(re, im);
    }
}

// ---------------- circulant tables (trig inline): gc[r][w][a] ----------------
__global__ void k_gtab2()
{
    int idx = blockIdx.x * 256 + threadIdx.x;
    int r = idx / 9216;
    int rem = idx - r * 9216;
    int w = rem / 96, a = rem - w * 96;
    int tt = a - w; if (tt < 0) tt += 96;
    float2 g;
    if (r == 0) {
        g = make_float2(tt == 0 ? 1.f : 0.f, 0.f);
    } else {
        const float PI = 3.14159265358979323846f;
        float h1 = PI * (float)r / 96.0f;
        float h2 = PI * (96.0f * (float)tt + (float)r) / 9216.0f;
        float rr = sinf(h1) / (96.0f * sinf(h2));
        float psi = h1 - h2;
        g = make_float2(rr * cosf(psi), rr * sinf(psi));
    }
    g_gcre[idx] = g.x;
    g_gcim[idx] = g.y;
}

// ---------------- conv as batched tf32 GEMM ---------------------------------
__global__ void __launch_bounds__(128) k_vconv()
{
    const int r = blockIdx.x;
    const int ch0 = blockIdx.y * 64;
    __shared__ __align__(16) uint32_t As[8][72];
    __shared__ __align__(16) uint32_t Br[8][104];
    __shared__ __align__(16) uint32_t Bi[8][104];
    const int t = threadIdx.x;
    const int warp = t >> 5, lane = t & 31;
    const int gid = lane >> 2, tig = lane & 3;
    const int mrow = (warp >> 1) * 32;
    const int ncol = (warp & 1) * 48;
    const int ach = t >> 1, aw4 = (t & 1) * 4;
    const int bw = t >> 4, ba0 = (t & 15) * 6;

    float cre[2][6][4], cim[2][6][4];
#pragma unroll
    for (int i = 0; i < 2; i++)
#pragma unroll
        for (int j = 0; j < 6; j++)
#pragma unroll
            for (int q = 0; q < 4; q++) { cre[i][j][q] = 0.f; cim[i][j][q] = 0.f; }

    float4 av;
    float br[6], bi[6];
    av = *(const float4*)&g_v[(size_t)(ch0 + ach) * NHW + r * 96 + aw4];
    {
        const float* pr_ = &g_gcre[(size_t)r * 9216 + bw * 96 + ba0];
        const float* pi_ = &g_gcim[(size_t)r * 9216 + bw * 96 + ba0];
#pragma unroll
        for (int i = 0; i < 6; i++) { br[i] = pr_[i]; bi[i] = pi_[i]; }
    }

    for (int ks = 0; ks < 12; ks++) {
        __syncthreads();
        As[aw4 + 0][ach] = f2tf32(av.x);
        As[aw4 + 1][ach] = f2tf32(av.y);
        As[aw4 + 2][ach] = f2tf32(av.z);
        As[aw4 + 3][ach] = f2tf32(av.w);
#pragma unroll
        for (int i = 0; i < 6; i++) {
            Br[bw][ba0 + i] = f2tf32(br[i]);
            Bi[bw][ba0 + i] = f2tf32(bi[i]);
        }
        __syncthreads();

        int w0n = (ks + 1 < 12) ? (ks + 1) * 8 : 0;
        av = *(const float4*)&g_v[(size_t)(ch0 + ach) * NHW + r * 96 + w0n + aw4];
        {
            const float* pr_ = &g_gcre[(size_t)r * 9216 + (w0n + bw) * 96 + ba0];
            const float* pi_ = &g_gcim[(size_t)r * 9216 + (w0n + bw) * 96 + ba0];
#pragma unroll
            for (int i = 0; i < 6; i++) { br[i] = pr_[i]; bi[i] = pi_[i]; }
        }

        uint32_t afr[2][4], bre[6][2], bim[6][2];
#pragma unroll
        for (int mt = 0; mt < 2; mt++) {
            int m0 = mrow + mt * 16;
            afr[mt][0] = As[tig][m0 + gid];
            afr[mt][1] = As[tig][m0 + gid + 8];
            afr[mt][2] = As[tig + 4][m0 + gid];
            afr[mt][3] = As[tig + 4][m0 + gid + 8];
        }
#pragma unroll
        for (int nt = 0; nt < 6; nt++) {
            int n0 = ncol + nt * 8;
            bre[nt][0] = Br[tig][n0 + gid];
            bre[nt][1] = Br[tig + 4][n0 + gid];
            bim[nt][0] = Bi[tig][n0 + gid];
            bim[nt][1] = Bi[tig + 4][n0 + gid];
        }
#pragma unroll
        for (int mt = 0; mt < 2; mt++)
#pragma unroll
            for (int nt = 0; nt < 6; nt++) {
                mma_tf32(cre[mt][nt], afr[mt], bre[nt]);
                mma_tf32(cim[mt][nt], afr[mt], bim[nt]);
            }
    }

#pragma unroll
    for (int mt = 0; mt < 2; mt++) {
        int r0 = ch0 + mrow + mt * 16 + gid;
        int r1 = r0 + 8;
        float2* p0 = &g_Tt[(size_t)r0 * NHW + r * 96];
        float2* p1 = &g_Tt[(size_t)r1 * NHW + r * 96];
#pragma unroll
        for (int nt = 0; nt < 6; nt++) {
            int a = ncol + nt * 8 + tig * 2;
            p0[a]     = make_float2(cre[mt][nt][0], cim[mt][nt][0]);
            p0[a + 1] = make_float2(cre[mt][nt][1], cim[mt][nt][1]);
            p1[a]     = make_float2(cre[mt][nt][2], cim[mt][nt][2]);
            p1[a + 1] = make_float2(cre[mt][nt][3], cim[mt][nt][3]);
        }
    }
}

// ---------------- mix + fused transpose --------------------------------------
// Block tile: (rt: 32 r, at: 4 a) per bh. Reads Tt[ch][r*96+a]; writes
// R[row][a*96+r] directly (8-float aligned runs). Inner math identical to old
// k_mix with s_local = rl*4 + al.
__global__ void __launch_bounds__(256) k_mix2()
{
    const int rt = blockIdx.x % 3;     // r-tile of 32
    const int at = blockIdx.x / 3;     // a-tile of 4 (0..23)
    const int bh = blockIdx.y;
    __shared__ float2 Ch[1024];
    __shared__ float2 Ts[32][128];     // [d][rl*4+al]
    const int t = threadIdx.x;
    for (int i = t; i < 1024; i += 256) Ch[i] = g_Chat[bh * 1024 + i];
    for (int i = t; i < 1024; i += 256) {
        int d = i >> 5, rl = i & 31;
        const float2* src = &g_Tt[(size_t)(bh * 32 + d) * NHW + (rt * 32 + rl) * 96 + at * 4];
        *(float4*)&Ts[d][rl * 4]     = *(const float4*)src;
        *(float4*)&Ts[d][rl * 4 + 2] = *(const float4*)(src + 2);
    }
    __syncthreads();
    const int sl = t & 63, eg = t >> 6;
    float ar0[8], ai0[8], ar1[8], ai1[8];
#pragma unroll
    for (int i = 0; i < 8; i++) { ar0[i] = ai0[i] = ar1[i] = ai1[i] = 0.f; }

    for (int d = 0; d < 32; d++) {
        float2 t0 = Ts[d][sl];
        float2 t1 = Ts[d][sl + 64];
#pragma unroll
        for (int i = 0; i < 8; i++) {
            float2 c = Ch[(eg * 8 + i) * 32 + d];
            ar0[i] += c.x * t0.x - c.y * t0.y;
            ai0[i] += c.x * t0.y + c.y * t0.x;
            ar1[i] += c.x * t1.x - c.y * t1.y;
            ai1[i] += c.x * t1.y + c.y * t1.x;
        }
    }
    // write transposed: s_local -> (rl = s>>2, al = s&3); addr = (at*4+al)*96 + rt*32 + rl
    const int al0 = sl & 3,        rl0 = sl >> 2;
    const int al1 = (sl + 64) & 3, rl1 = (sl + 64) >> 2;
#pragma unroll
    for (int i = 0; i < 8; i++) {
        int row = bh * 32 + eg * 8 + i;
        g_R[(size_t)row * NHW + (at * 4 + al0) * 96 + rt * 32 + rl0] =
            sqrtf(ar0[i] * ar0[i] + ai0[i] * ai0[i]);
        g_R[(size_t)row * NHW + (at * 4 + al1) * 96 + rt * 32 + rl1] =
            sqrtf(ar1[i] * ar1[i] + ai1[i] * ai1[i]);
    }
}

// ---------------- launch ----------------
extern "C" void kernel_launch(void* const* d_in, const int* in_sizes, int n_in,
                              void* d_out, int out_size)
{
    const float* x    = (const float*)d_in[0];
    const float* w1   = (const float*)d_in[1];
    const float* b1   = (const float*)d_in[2];
    const float* w2   = (const float*)d_in[3];
    const float* b2   = (const float*)d_in[4];
    const float* w3   = (const float*)d_in[5];
    const float* b3   = (const float*)d_in[6];
    const float* wo   = (const float*)d_in[7];
    const float* temp = (const float*)d_in[8];
    float* out = (float*)d_out;

    float *vp = nullptr, *Rp = nullptr, *Pp = nullptr, *Gfp = nullptr;
    cudaGetSymbolAddress((void**)&vp,  g_v);
    cudaGetSymbolAddress((void**)&Rp,  g_R);
    cudaGetSymbolAddress((void**)&Pp,  g_P);
    cudaGetSymbolAddress((void**)&Gfp, g_Gf);

    dim3 gg(72, 2, 8);
    dim3 gm(4, 4, 8);

    k_gemm_tf32<<<gg, 128>>>(x, w3, b3, vp);            // v
    k_zm     <<<8, 256>>>();
    k_revx   <<<dim3(2048, 9), 256>>>(x);               // xrev + fused m sum
    k_gram6  <<<dim3(KCH, 3, 16), 128>>>(x);            // partial tiles (tf32 + cp.async)
    k_gred   <<<dim3(64, 3, 16), 256>>>();              // -> S, M
    k_mirror <<<dim3(64, 16), 256>>>();
    k_mmA    <<<gm, 256>>>(w2);                         // P = M * W2^T
    k_mmB    <<<gm, 256>>>(w1, Pp, Gfp);                // Gf = W1 * P
    k_mmU    <<<dim3(4, 4, 16), 256>>>(w1, w2);         // U1 -> g_P, U2 -> g_gp
    k_rowdot2<<<dim3(2048, 2), 256>>>(w1, w2, b1, b2);
    k_gtab2  <<<3456, 256>>>();
    k_attn2  <<<64, 256>>>(b1, b2, temp);
    k_vconv  <<<dim3(96, 32), 128>>>();                 // conv via tensor cores
    k_mix2   <<<dim3(72, 64), 256>>>();                 // mix + transpose -> R
    k_gemm_tf32<<<gg, 128>>>(Rp, wo, nullptr, out);
}

// round 12
// speedup vs baseline: 2.7459x; 1.0644x over previous
#include <cuda_runtime.h>
#include <math.h>
#include <stdint.h>

#define NB 8
#define NC 256
#define NHW 9216
#define NHEAD 8
#define KCH 24            // gram split-K chunks

// ---------------- scratch (device globals; no allocation anywhere) ----------
__device__ float  g_v[NB*NC*NHW];         // 75.5 MB
__device__ float  g_xrev[NB*NC*NHW];      // 75.5 MB
__device__ float  g_gp[KCH*3*16*128*128]; // 75.5 MB gram partials; first 2MB reused as U2
__device__ float  g_S[NB*256*256];
__device__ float  g_M[NB*256*256];
__device__ float  g_P[NB*256*256];
__device__ float  g_Gf[NB*256*256];
__device__ float  g_m[NB*256];
__device__ float  g_nq[NB*256], g_nk[NB*256];
__device__ float  g_w1m[NB*256], g_w2m[NB*256];
__device__ float2 g_Chat[64*1024];
__device__ float  g_gcre[96*96*96];       // circulant conv tables
__device__ float  g_gcim[96*96*96];
__device__ float2 g_Tt[NB*NC*NHW];        // 151 MB, layout [ch][r][a]
__device__ float  g_R [NB*NC*NHW];

// ---------------- tf32 / cp.async / f32x2 helpers ----------------------------
__device__ __forceinline__ uint32_t f2tf32(float x) {
    uint32_t r;
    asm("cvt.rna.tf32.f32 %0, %1;" : "=r"(r) : "f"(x));
    return r;
}
__device__ __forceinline__ void mma_tf32(float* c, const uint32_t* a, const uint32_t* b) {
    asm volatile(
        "mma.sync.aligned.m16n8k8.row.col.f32.tf32.tf32.f32 "
        "{%0,%1,%2,%3}, {%4,%5,%6,%7}, {%8,%9}, {%0,%1,%2,%3};"
        : "+f"(c[0]), "+f"(c[1]), "+f"(c[2]), "+f"(c[3])
        : "r"(a[0]), "r"(a[1]), "r"(a[2]), "r"(a[3]), "r"(b[0]), "r"(b[1]));
}
__device__ __forceinline__ void cpa16(void* dst, const void* src) {
    uint32_t d = (uint32_t)__cvta_generic_to_shared(dst);
    asm volatile("cp.async.cg.shared.global [%0], [%1], 16;" :: "r"(d), "l"(src));
}
#define CP_COMMIT() asm volatile("cp.async.commit_group;")
#define CP_WAIT0()  asm volatile("cp.async.wait_group 0;")

__device__ __forceinline__ unsigned long long pk2(float lo, float hi) {
    unsigned long long r;
    asm("mov.b64 %0, {%1, %2};" : "=l"(r) : "f"(lo), "f"(hi));
    return r;
}
__device__ __forceinline__ void upk2(float& lo, float& hi, unsigned long long v) {
    asm("mov.b64 {%0, %1}, %2;" : "=f"(lo), "=f"(hi) : "l"(v));
}
__device__ __forceinline__ unsigned long long fma2(
    unsigned long long a, unsigned long long b, unsigned long long c) {
    unsigned long long d;
    asm("fma.rn.f32x2 %0, %1, %2, %3;" : "=l"(d) : "l"(a), "l"(b), "l"(c));
    return d;
}

// ---------------- tf32 GEMM: Y[b][o][s] = sum_c W[o][c] X[b][c][s] (+bias) ---
__global__ void __launch_bounds__(128, 3) k_gemm_tf32(
    const float* __restrict__ X, const float* __restrict__ W,
    const float* __restrict__ bias, float* __restrict__ Y)
{
    __shared__ __align__(16) float Wm[2][128][12];
    __shared__ __align__(16) float Xs[2][8][136];
    const int t  = threadIdx.x;
    const int s0 = blockIdx.x * 128;
    const int o0 = blockIdx.y * 128;
    const int b  = blockIdx.z;
    const int warp = t >> 5, lane = t & 31;
    const int gid = lane >> 2, tig = lane & 3;
    const int mrow = (warp >> 1) * 64;
    const int ncol = (warp & 1) * 64;
    const float* Xb = X + (size_t)b * NC * NHW;
    const int xr = t >> 4, xc = (t & 15) * 8;

    float c[4][8][4];
#pragma unroll
    for (int i = 0; i < 4; i++)
#pragma unroll
        for (int j = 0; j < 8; j++)
#pragma unroll
            for (int q = 0; q < 4; q++) c[i][j][q] = 0.f;

    cpa16(&Wm[0][t][0], &W[(o0 + t) * 256 + 0]);
    cpa16(&Wm[0][t][4], &W[(o0 + t) * 256 + 4]);
    cpa16(&Xs[0][xr][xc],     &Xb[(size_t)xr * NHW + s0 + xc]);
    cpa16(&Xs[0][xr][xc + 4], &Xb[(size_t)xr * NHW + s0 + xc + 4]);
    CP_COMMIT();

    for (int i = 0; i < 32; i++) {
        const int st = i & 1;
        CP_WAIT0();
        __syncthreads();
        uint32_t afr[4][4], bfr[8][2];
#pragma unroll
        for (int mt = 0; mt < 4; mt++) {
            int m0 = mrow + mt * 16;
            afr[mt][0] = f2tf32(Wm[st][m0 + gid][tig]);
            afr[mt][1] = f2tf32(Wm[st][m0 + gid + 8][tig]);
            afr[mt][2] = f2tf32(Wm[st][m0 + gid][tig + 4]);
            afr[mt][3] = f2tf32(Wm[st][m0 + gid + 8][tig + 4]);
        }
#pragma unroll
        for (int nt = 0; nt < 8; nt++) {
            int n0 = ncol + nt * 8;
            bfr[nt][0] = f2tf32(Xs[st][tig][n0 + gid]);
            bfr[nt][1] = f2tf32(Xs[st][tig + 4][n0 + gid]);
        }
        __syncthreads();
        if (i + 1 < 32) {
            const int kc = (i + 1) * 8, sn = st ^ 1;
            cpa16(&Wm[sn][t][0], &W[(o0 + t) * 256 + kc]);
            cpa16(&Wm[sn][t][4], &W[(o0 + t) * 256 + kc + 4]);
            cpa16(&Xs[sn][xr][xc],     &Xb[(size_t)(kc + xr) * NHW + s0 + xc]);
            cpa16(&Xs[sn][xr][xc + 4], &Xb[(size_t)(kc + xr) * NHW + s0 + xc + 4]);
        }
        CP_COMMIT();
#pragma unroll
        for (int mt = 0; mt < 4; mt++)
#pragma unroll
            for (int nt = 0; nt < 8; nt++)
                mma_tf32(c[mt][nt], afr[mt], bfr[nt]);
    }

#pragma unroll
    for (int mt = 0; mt < 4; mt++) {
        int oa = o0 + mrow + mt * 16 + gid;
        int ob = oa + 8;
        float ba  = bias ? bias[oa] : 0.f;
        float bb_ = bias ? bias[ob] : 0.f;
        float* ya = Y + (size_t)(b * NC + oa) * NHW + s0;
        float* yb = Y + (size_t)(b * NC + ob) * NHW + s0;
#pragma unroll
        for (int nt = 0; nt < 8; nt++) {
            int sc = ncol + nt * 8 + tig * 2;
            *(float2*)&ya[sc] = make_float2(c[mt][nt][0] + ba,  c[mt][nt][1] + ba);
            *(float2*)&yb[sc] = make_float2(c[mt][nt][2] + bb_, c[mt][nt][3] + bb_);
        }
    }
}

// ---------------- zero g_m ----------------------------------------------------
__global__ void k_zm() { g_m[blockIdx.x * 256 + threadIdx.x] = 0.f; }

// ---------------- reversed copy + fused channel sum --------------------------
__global__ void __launch_bounds__(256) k_revx(const float* __restrict__ X)
{
    const int ch = blockIdx.x;
    const int seg = blockIdx.y;
    const float* src = X + (size_t)ch * NHW;
    float* dst = g_xrev + (size_t)ch * NHW;
    int s = seg * 1024 + threadIdx.x;
    float lsum = 0.f;
#pragma unroll
    for (int i = 0; i < 4; i++, s += 256) {
        int y = s / 96, x = s - y * 96;
        int ry = (y == 0) ? 0 : 96 - y;
        int rx = (x == 0) ? 0 : 96 - x;
        float v = src[ry * 96 + rx];
        dst[s] = v;
        lsum += v;
    }
#pragma unroll
    for (int o = 16; o; o >>= 1) lsum += __shfl_xor_sync(0xffffffff, lsum, o);
    __shared__ float sb[8];
    int w = threadIdx.x >> 5;
    if ((threadIdx.x & 31) == 0) sb[w] = lsum;
    __syncthreads();
    if (threadIdx.x == 0) {
        float a = 0.f;
        for (int i = 0; i < 8; i++) a += sb[i];
        atomicAdd(&g_m[ch], a);
    }
}

// ---------------- Gram GEMM (tf32, cp.async 2-stage), partial tiles ----------
__global__ void __launch_bounds__(128, 3) k_gram6(const float* __restrict__ X)
{
    const int sch = blockIdx.x, pr = blockIdx.y;
    const int b = blockIdx.z >> 1, mat = blockIdx.z & 1;
    const int ci = (pr == 2) ? 1 : 0;
    const int dj = (pr == 0) ? 0 : 1;
    __shared__ __align__(16) float Am[2][128][12];
    __shared__ __align__(16) float Dm[2][128][12];
    const float* Xa = X + (size_t)b * NC * NHW;
    const float* Xd = (mat ? g_xrev : X) + (size_t)b * NC * NHW;
    const int t = threadIdx.x;
    const int warp = t >> 5, lane = t & 31;
    const int gid = lane >> 2, tig = lane & 3;
    const int mrow = (warp >> 1) * 64;
    const int ncol = (warp & 1) * 64;
    const int base = sch * (NHW / KCH);
    const float* arow = &Xa[(size_t)(ci * 128 + t) * NHW + base];
    const float* drow = &Xd[(size_t)(dj * 128 + t) * NHW + base];

    float c[4][8][4];
#pragma unroll
    for (int i = 0; i < 4; i++)
#pragma unroll
        for (int j = 0; j < 8; j++)
#pragma unroll
            for (int q = 0; q < 4; q++) c[i][j][q] = 0.f;

    cpa16(&Am[0][t][0], &arow[0]);
    cpa16(&Am[0][t][4], &arow[4]);
    cpa16(&Dm[0][t][0], &drow[0]);
    cpa16(&Dm[0][t][4], &drow[4]);
    CP_COMMIT();

    const int NKS = NHW / (KCH * 8);   // 48
    for (int i = 0; i < NKS; i++) {
        const int st = i & 1;
        CP_WAIT0();
        __syncthreads();
        uint32_t afr[4][4], bfr[8][2];
#pragma unroll
        for (int mt = 0; mt < 4; mt++) {
            int m0 = mrow + mt * 16;
            afr[mt][0] = f2tf32(Am[st][m0 + gid][tig]);
            afr[mt][1] = f2tf32(Am[st][m0 + gid + 8][tig]);
            afr[mt][2] = f2tf32(Am[st][m0 + gid][tig + 4]);
            afr[mt][3] = f2tf32(Am[st][m0 + gid + 8][tig + 4]);
        }
#pragma unroll
        for (int nt = 0; nt < 8; nt++) {
            int n0 = ncol + nt * 8;
            bfr[nt][0] = f2tf32(Dm[st][n0 + gid][tig]);
            bfr[nt][1] = f2tf32(Dm[st][n0 + gid][tig + 4]);
        }
        __syncthreads();
        if (i + 1 < NKS) {
            const int ko = (i + 1) * 8, sn = st ^ 1;
            cpa16(&Am[sn][t][0], &arow[ko]);
            cpa16(&Am[sn][t][4], &arow[ko + 4]);
            cpa16(&Dm[sn][t][0], &drow[ko]);
            cpa16(&Dm[sn][t][4], &drow[ko + 4]);
        }
        CP_COMMIT();
#pragma unroll
        for (int mt = 0; mt < 4; mt++)
#pragma unroll
            for (int nt = 0; nt < 8; nt++)
                mma_tf32(c[mt][nt], afr[mt], bfr[nt]);
    }

    float* Out = g_gp + ((size_t)(blockIdx.z * 3 + pr) * KCH + sch) * 16384;
#pragma unroll
    for (int mt = 0; mt < 4; mt++) {
        int ra = mrow + mt * 16 + gid;
        int rb = ra + 8;
#pragma unroll
        for (int nt = 0; nt < 8; nt++) {
            int col = ncol + nt * 8 + tig * 2;
            *(float2*)&Out[ra * 128 + col] = make_float2(c[mt][nt][0], c[mt][nt][1]);
            *(float2*)&Out[rb * 128 + col] = make_float2(c[mt][nt][2], c[mt][nt][3]);
        }
    }
}

// ---------------- reduce partials into S / M --------------------------------
__global__ void __launch_bounds__(256) k_gred()
{
    const int pr = blockIdx.y, bm = blockIdx.z;
    const int b = bm >> 1, mat = bm & 1;
    const int ci = (pr == 2) ? 1 : 0;
    const int dj = (pr == 0) ? 0 : 1;
    const int off = blockIdx.x * 256 + threadIdx.x;
    const float* Pp = g_gp + (size_t)(bm * 3 + pr) * KCH * 16384 + off;
    float s = 0.f;
#pragma unroll
    for (int c = 0; c < KCH; c++) s += Pp[c * 16384];
    int il = off >> 7, jl = off & 127;
    float* Out = (mat ? g_M : g_S) + b * 65536;
    Out[(ci * 128 + il) * 256 + dj * 128 + jl] = s;
}

// ---------------- mirror lower-left 128x128 block ---------------------------
__global__ void k_mirror()
{
    const int bm = blockIdx.y;
    float* Out = (bm & 1 ? g_M : g_S) + (bm >> 1) * 65536;
    int idx = blockIdx.x * 256 + threadIdx.x;
    int i = idx >> 7, jl = idx & 127;
    Out[(128 + jl) * 256 + i] = Out[i * 256 + 128 + jl];
}

// ---------------- P[b] = M[b] * W2^T ----------------------------------------
__global__ void __launch_bounds__(256) k_mmA(const float* __restrict__ Wg)
{
    const int j0 = blockIdx.x * 64, i0 = blockIdx.y * 64, b = blockIdx.z;
    const float* A = g_M + b * 65536;
    float* C = g_P + b * 65536;
    __shared__ float As[16][68];
    __shared__ float Bs[16][68];
    const int t = threadIdx.x;
    const int it = (t >> 4) * 4, jt = (t & 15) * 4;
    float acc[4][4];
#pragma unroll
    for (int i = 0; i < 4; i++)
#pragma unroll
        for (int j = 0; j < 4; j++) acc[i][j] = 0.f;
    for (int kc = 0; kc < 256; kc += 16) {
        __syncthreads();
#pragma unroll
        for (int i = 0; i < 4; i++) {
            int idx = i * 256 + t;
            int r = idx >> 4, kk = idx & 15;
            As[kk][r] = A[(i0 + r) * 256 + kc + kk];
            Bs[kk][r] = Wg[(j0 + r) * 256 + kc + kk];
        }
        __syncthreads();
#pragma unroll
        for (int kk = 0; kk < 16; kk++) {
            float a[4], bb[4];
            *(float4*)a  = *(float4*)&As[kk][it];
            *(float4*)bb = *(float4*)&Bs[kk][jt];
#pragma unroll
            for (int i = 0; i < 4; i++)
#pragma unroll
                for (int j = 0; j < 4; j++) acc[i][j] += a[i] * bb[j];
        }
    }
#pragma unroll
    for (int i = 0; i < 4; i++)
#pragma unroll
        for (int j = 0; j < 4; j++)
            C[(i0 + it + i) * 256 + j0 + jt + j] = acc[i][j];
}

// ---------------- C[b] = Ag * B[b]  (generic, used for Gf) -------------------
__global__ void __launch_bounds__(256) k_mmB(
    const float* __restrict__ Ag, const float* __restrict__ Bb, float* __restrict__ Cb)
{
    const int j0 = blockIdx.x * 64, i0 = blockIdx.y * 64, b = blockIdx.z;
    const float* B = Bb + b * 65536;
    float* C = Cb + b * 65536;
    __shared__ float As[16][68];
    __shared__ float Bs[16][68];
    const int t = threadIdx.x;
    const int it = (t >> 4) * 4, jt = (t & 15) * 4;
    float acc[4][4];
#pragma unroll
    for (int i = 0; i < 4; i++)
#pragma unroll
        for (int j = 0; j < 4; j++) acc[i][j] = 0.f;
    for (int kc = 0; kc < 256; kc += 16) {
        __syncthreads();
#pragma unroll
        for (int i = 0; i < 4; i++) {
            int idx = i * 256 + t;
            int r = idx >> 4, kk = idx & 15;
            As[kk][r] = Ag[(i0 + r) * 256 + kc + kk];
        }
#pragma unroll
        for (int i = 0; i < 4; i++) {
            int idx = i * 256 + t;
            int kk = idx >> 6, j = idx & 63;
            Bs[kk][j] = B[(kc + kk) * 256 + j0 + j];
        }
        __syncthreads();
#pragma unroll
        for (int kk = 0; kk < 16; kk++) {
            float a[4], bb[4];
            *(float4*)a  = *(float4*)&As[kk][it];
            *(float4*)bb = *(float4*)&Bs[kk][jt];
#pragma unroll
            for (int i = 0; i < 4; i++)
#pragma unroll
                for (int j = 0; j < 4; j++) acc[i][j] += a[i] * bb[j];
        }
    }
#pragma unroll
    for (int i = 0; i < 4; i++)
#pragma unroll
        for (int j = 0; j < 4; j++)
            C[(i0 + it + i) * 256 + j0 + jt + j] = acc[i][j];
}

// ---------------- batched U = W{1,2} * S  (z = b*2 + which) ------------------
__global__ void __launch_bounds__(256) k_mmU(
    const float* __restrict__ W1, const float* __restrict__ W2)
{
    const int j0 = blockIdx.x * 64, i0 = blockIdx.y * 64;
    const int b = blockIdx.z >> 1, which = blockIdx.z & 1;
    const float* Ag = which ? W2 : W1;
    const float* B = g_S + b * 65536;
    float* C = (which ? g_gp : g_P) + b * 65536;
    __shared__ float As[16][68];
    __shared__ float Bs[16][68];
    const int t = threadIdx.x;
    const int it = (t >> 4) * 4, jt = (t & 15) * 4;
    float acc[4][4];
#pragma unroll
    for (int i = 0; i < 4; i++)
#pragma unroll
        for (int j = 0; j < 4; j++) acc[i][j] = 0.f;
    for (int kc = 0; kc < 256; kc += 16) {
        __syncthreads();
#pragma unroll
        for (int i = 0; i < 4; i++) {
            int idx = i * 256 + t;
            int r = idx >> 4, kk = idx & 15;
            As[kk][r] = Ag[(i0 + r) * 256 + kc + kk];
        }
#pragma unroll
        for (int i = 0; i < 4; i++) {
            int idx = i * 256 + t;
            int kk = idx >> 6, j = idx & 63;
            Bs[kk][j] = B[(kc + kk) * 256 + j0 + j];
        }
        __syncthreads();
#pragma unroll
        for (int kk = 0; kk < 16; kk++) {
            float a[4], bb[4];
            *(float4*)a  = *(float4*)&As[kk][it];
            *(float4*)bb = *(float4*)&Bs[kk][jt];
#pragma unroll
            for (int i = 0; i < 4; i++)
#pragma unroll
                for (int j = 0; j < 4; j++) acc[i][j] += a[i] * bb[j];
        }
    }
#pragma unroll
    for (int i = 0; i < 4; i++)
#pragma unroll
        for (int j = 0; j < 4; j++)
            C[(i0 + it + i) * 256 + j0 + jt + j] = acc[i][j];
}

// ---------------- batched row-dot: norms + W*m (y = which) -------------------
__global__ void __launch_bounds__(256) k_rowdot2(
    const float* __restrict__ W1, const float* __restrict__ W2,
    const float* __restrict__ b1, const float* __restrict__ b2)
{
    const int bC = blockIdx.x;
    const int which = blockIdx.y;
    const int b = bC >> 8, C = bC & 255;
    const float* U = (which ? g_gp : g_P);
    const float* W = which ? W2 : W1;
    const float* bias = which ? b2 : b1;
    const int t = threadIdx.x;
    float wv = W[C * 256 + t];
    float un = U[(size_t)b * 65536 + C * 256 + t] * wv;
    float wm = wv * g_m[b * 256 + t];
#pragma unroll
    for (int o = 16; o; o >>= 1) {
        un += __shfl_xor_sync(0xffffffff, un, o);
        wm += __shfl_xor_sync(0xffffffff, wm, o);
    }
    __shared__ float s1[8], s2[8];
    int w = t >> 5;
    if ((t & 31) == 0) { s1[w] = un; s2[w] = wm; }
    __syncthreads();
    if (t == 0) {
        float a = 0.f, c = 0.f;
        for (int i = 0; i < 8; i++) { a += s1[i]; c += s2[i]; }
        float bc = bias[C];
        float nf = a + 2.f * bc * c + 9216.f * bc * bc;
        if (which) { g_nk[bC] = nf; g_w2m[bC] = c; }
        else       { g_nq[bC] = nf; g_w1m[bC] = c; }
    }
}

// ---------------- attn: logits, softmax, build Chat -------------------------
__global__ void __launch_bounds__(256) k_attn2(
    const float* __restrict__ b1, const float* __restrict__ b2,
    const float* __restrict__ temperature)
{
    const int bh = blockIdx.x;
    const int b = bh >> 3, h = bh & 7;
    const int ch0 = h * 32;
    __shared__ float A[32][33];
    __shared__ float rq[32], rk[32], sw1m[32], sw2m[32], sb1[32], sb2[32];
    __shared__ float2 tab[32];
    const int t = threadIdx.x;
    if (t < 32) {
        int C = b * 256 + ch0 + t;
        rq[t] = rsqrtf(g_nq[C]);
        rk[t] = rsqrtf(g_nk[C]);
        sw1m[t] = g_w1m[C];
        sw2m[t] = g_w2m[C];
        sb1[t] = b1[ch0 + t];
        sb2[t] = b2[ch0 + t];
        float ang = 6.283185307179586f * (float)t / 32.0f;
        tab[t] = make_float2(cosf(ang), sinf(ang));
    }
    __syncthreads();
    const float ts = temperature[h];
    const int w = t >> 5, lane = t & 31;
    for (int r = w; r < 32; r += 8) {
        float Gv = g_Gf[(size_t)b * 65536 + (ch0 + r) * 256 + ch0 + lane];
        float L = (Gv + sw1m[r] * sb2[lane] + sb1[r] * sw2m[lane]
                   + 9216.f * sb1[r] * sb2[lane]) * rq[r] * rk[lane] * ts;
        float m = L;
#pragma unroll
        for (int o = 16; o; o >>= 1) m = fmaxf(m, __shfl_xor_sync(0xffffffff, m, o));
        float e = expf(L - m);
        float s = e;
#pragma unroll
        for (int o = 16; o; o >>= 1) s += __shfl_xor_sync(0xffffffff, s, o);
        A[r][lane] = e / s;
    }
    __syncthreads();
    for (int idx = t; idx < 1024; idx += 256) {
        int e = idx >> 5, d = idx & 31;
        float re = 0.f, im = 0.f;
#pragma unroll 8
        for (int c = 0; c < 32; c++) {
            float a = A[c][d];
            float2 tb = tab[(c * e) & 31];
            re += a * tb.x; im += a * tb.y;
        }
        re *= (1.0f / 32.0f); im *= (1.0f / 32.0f);
        if (e == 0) im += (1.0f / 32.0f);
        g_Chat[bh * 1024 + idx] = make_float2(re, im);
    }
}

// ---------------- circulant tables (trig inline): gc[r][w][a] ----------------
__global__ void k_gtab2()
{
    int idx = blockIdx.x * 256 + threadIdx.x;
    int r = idx / 9216;
    int rem = idx - r * 9216;
    int w = rem / 96, a = rem - w * 96;
    int tt = a - w; if (tt < 0) tt += 96;
    float2 g;
    if (r == 0) {
        g = make_float2(tt == 0 ? 1.f : 0.f, 0.f);
    } else {
        const float PI = 3.14159265358979323846f;
        float h1 = PI * (float)r / 96.0f;
        float h2 = PI * (96.0f * (float)tt + (float)r) / 9216.0f;
        float rr = sinf(h1) / (96.0f * sinf(h2));
        float psi = h1 - h2;
        g = make_float2(rr * cosf(psi), rr * sinf(psi));
    }
    g_gcre[idx] = g.x;
    g_gcim[idx] = g.y;
}

// ---------------- conv as batched tf32 GEMM ---------------------------------
__global__ void __launch_bounds__(128) k_vconv()
{
    const int r = blockIdx.x;
    const int ch0 = blockIdx.y * 64;
    __shared__ __align__(16) uint32_t As[8][72];
    __shared__ __align__(16) uint32_t Br[8][104];
    __shared__ __align__(16) uint32_t Bi[8][104];
    const int t = threadIdx.x;
    const int warp = t >> 5, lane = t & 31;
    const int gid = lane >> 2, tig = lane & 3;
    const int mrow = (warp >> 1) * 32;
    const int ncol = (warp & 1) * 48;
    const int ach = t >> 1, aw4 = (t & 1) * 4;
    const int bw = t >> 4, ba0 = (t & 15) * 6;

    float cre[2][6][4], cim[2][6][4];
#pragma unroll
    for (int i = 0; i < 2; i++)
#pragma unroll
        for (int j = 0; j < 6; j++)
#pragma unroll
            for (int q = 0; q < 4; q++) { cre[i][j][q] = 0.f; cim[i][j][q] = 0.f; }

    float4 av;
    float br[6], bi[6];
    av = *(const float4*)&g_v[(size_t)(ch0 + ach) * NHW + r * 96 + aw4];
    {
        const float* pr_ = &g_gcre[(size_t)r * 9216 + bw * 96 + ba0];
        const float* pi_ = &g_gcim[(size_t)r * 9216 + bw * 96 + ba0];
#pragma unroll
        for (int i = 0; i < 6; i++) { br[i] = pr_[i]; bi[i] = pi_[i]; }
    }

    for (int ks = 0; ks < 12; ks++) {
        __syncthreads();
        As[aw4 + 0][ach] = f2tf32(av.x);
        As[aw4 + 1][ach] = f2tf32(av.y);
        As[aw4 + 2][ach] = f2tf32(av.z);
        As[aw4 + 3][ach] = f2tf32(av.w);
#pragma unroll
        for (int i = 0; i < 6; i++) {
            Br[bw][ba0 + i] = f2tf32(br[i]);
            Bi[bw][ba0 + i] = f2tf32(bi[i]);
        }
        __syncthreads();

        int w0n = (ks + 1 < 12) ? (ks + 1) * 8 : 0;
        av = *(const float4*)&g_v[(size_t)(ch0 + ach) * NHW + r * 96 + w0n + aw4];
        {
            const float* pr_ = &g_gcre[(size_t)r * 9216 + (w0n + bw) * 96 + ba0];
            const float* pi_ = &g_gcim[(size_t)r * 9216 + (w0n + bw) * 96 + ba0];
#pragma unroll
            for (int i = 0; i < 6; i++) { br[i] = pr_[i]; bi[i] = pi_[i]; }
        }

        uint32_t afr[2][4], bre[6][2], bim[6][2];
#pragma unroll
        for (int mt = 0; mt < 2; mt++) {
            int m0 = mrow + mt * 16;
            afr[mt][0] = As[tig][m0 + gid];
            afr[mt][1] = As[tig][m0 + gid + 8];
            afr[mt][2] = As[tig + 4][m0 + gid];
            afr[mt][3] = As[tig + 4][m0 + gid + 8];
        }
#pragma unroll
        for (int nt = 0; nt < 6; nt++) {
            int n0 = ncol + nt * 8;
            bre[nt][0] = Br[tig][n0 + gid];
            bre[nt][1] = Br[tig + 4][n0 + gid];
            bim[nt][0] = Bi[tig][n0 + gid];
            bim[nt][1] = Bi[tig + 4][n0 + gid];
        }
#pragma unroll
        for (int mt = 0; mt < 2; mt++)
#pragma unroll
            for (int nt = 0; nt < 6; nt++) {
                mma_tf32(cre[mt][nt], afr[mt], bre[nt]);
                mma_tf32(cim[mt][nt], afr[mt], bim[nt]);
            }
    }

#pragma unroll
    for (int mt = 0; mt < 2; mt++) {
        int r0 = ch0 + mrow + mt * 16 + gid;
        int r1 = r0 + 8;
        float2* p0 = &g_Tt[(size_t)r0 * NHW + r * 96];
        float2* p1 = &g_Tt[(size_t)r1 * NHW + r * 96];
#pragma unroll
        for (int nt = 0; nt < 6; nt++) {
            int a = ncol + nt * 8 + tig * 2;
            p0[a]     = make_float2(cre[mt][nt][0], cim[mt][nt][0]);
            p0[a + 1] = make_float2(cre[mt][nt][1], cim[mt][nt][1]);
            p1[a]     = make_float2(cre[mt][nt][2], cim[mt][nt][2]);
            p1[a + 1] = make_float2(cre[mt][nt][3], cim[mt][nt][3]);
        }
    }
}

// ---------------- mix + fused transpose, packed f32x2 -------------------------
__global__ void __launch_bounds__(256) k_mix2()
{
    const int rt = blockIdx.x % 3;     // r-tile of 32
    const int at = blockIdx.x / 3;     // a-tile of 4 (0..23)
    const int bh = blockIdx.y;
    __shared__ float2 Ch[1024];
    __shared__ float2 Ts[32][128];     // [d][rl*4+al]
    const int t = threadIdx.x;
    for (int i = t; i < 1024; i += 256) Ch[i] = g_Chat[bh * 1024 + i];
    for (int i = t; i < 1024; i += 256) {
        int d = i >> 5, rl = i & 31;
        const float2* src = &g_Tt[(size_t)(bh * 32 + d) * NHW + (rt * 32 + rl) * 96 + at * 4];
        *(float4*)&Ts[d][rl * 4]     = *(const float4*)src;
        *(float4*)&Ts[d][rl * 4 + 2] = *(const float4*)(src + 2);
    }
    __syncthreads();
    const int sl = t & 63, eg = t >> 6;
    const unsigned long long SGN = 0x8000000080000000ULL;

    // packed accumulators: pair e-outputs (i = 2j, 2j+1)
    unsigned long long ar0p[4], ai0p[4], ar1p[4], ai1p[4];
#pragma unroll
    for (int j = 0; j < 4; j++) { ar0p[j] = ai0p[j] = ar1p[j] = ai1p[j] = 0ULL; }

    for (int d = 0; d < 32; d++) {
        float2 t0 = Ts[d][sl];
        float2 t1 = Ts[d][sl + 64];
        unsigned long long t0x = pk2(t0.x, t0.x), t0y = pk2(t0.y, t0.y);
        unsigned long long t1x = pk2(t1.x, t1.x), t1y = pk2(t1.y, t1.y);
#pragma unroll
        for (int j = 0; j < 4; j++) {
            float2 cA = Ch[(eg * 8 + 2 * j) * 32 + d];
            float2 cB = Ch[(eg * 8 + 2 * j + 1) * 32 + d];
            unsigned long long cx  = pk2(cA.x, cB.x);
            unsigned long long cy  = pk2(cA.y, cB.y);
            unsigned long long cyn = cy ^ SGN;
            ar0p[j] = fma2(cx,  t0x, ar0p[j]);
            ar0p[j] = fma2(cyn, t0y, ar0p[j]);
            ai0p[j] = fma2(cx,  t0y, ai0p[j]);
            ai0p[j] = fma2(cy,  t0x, ai0p[j]);
            ar1p[j] = fma2(cx,  t1x, ar1p[j]);
            ar1p[j] = fma2(cyn, t1y, ar1p[j]);
            ai1p[j] = fma2(cx,  t1y, ai1p[j]);
            ai1p[j] = fma2(cy,  t1x, ai1p[j]);
        }
    }

    const int al0 = sl & 3,        rl0 = sl >> 2;
    const int al1 = (sl + 64) & 3, rl1 = (sl + 64) >> 2;
#pragma unroll
    for (int j = 0; j < 4; j++) {
        float a0, a1, b0, b1, c0, c1, d0, d1;
        upk2(a0, a1, ar0p[j]);   // ar0 for i=2j, 2j+1
        upk2(b0, b1, ai0p[j]);
        upk2(c0, c1, ar1p[j]);
        upk2(d0, d1, ai1p[j]);
        int row0 = bh * 32 + eg * 8 + 2 * j;
        int row1 = row0 + 1;
        g_R[(size_t)row0 * NHW + (at * 4 + al0) * 96 + rt * 32 + rl0] = sqrtf(a0 * a0 + b0 * b0);
        g_R[(size_t)row1 * NHW + (at * 4 + al0) * 96 + rt * 32 + rl0] = sqrtf(a1 * a1 + b1 * b1);
        g_R[(size_t)row0 * NHW + (at * 4 + al1) * 96 + rt * 32 + rl1] = sqrtf(c0 * c0 + d0 * d0);
        g_R[(size_t)row1 * NHW + (at * 4 + al1) * 96 + rt * 32 + rl1] = sqrtf(c1 * c1 + d1 * d1);
    }
}

// ---------------- launch ----------------
extern "C" void kernel_launch(void* const* d_in, const int* in_sizes, int n_in,
                              void* d_out, int out_size)
{
    const float* x    = (const float*)d_in[0];
    const float* w1   = (const float*)d_in[1];
    const float* b1   = (const float*)d_in[2];
    const float* w2   = (const float*)d_in[3];
    const float* b2   = (const float*)d_in[4];
    const float* w3   = (const float*)d_in[5];
    const float* b3   = (const float*)d_in[6];
    const float* wo   = (const float*)d_in[7];
    const float* temp = (const float*)d_in[8];
    float* out = (float*)d_out;

    float *vp = nullptr, *Rp = nullptr, *Pp = nullptr, *Gfp = nullptr;
    cudaGetSymbolAddress((void**)&vp,  g_v);
    cudaGetSymbolAddress((void**)&Rp,  g_R);
    cudaGetSymbolAddress((void**)&Pp,  g_P);
    cudaGetSymbolAddress((void**)&Gfp, g_Gf);

    dim3 gg(72, 2, 8);
    dim3 gm(4, 4, 8);

    k_gemm_tf32<<<gg, 128>>>(x, w3, b3, vp);            // v
    k_zm     <<<8, 256>>>();
    k_revx   <<<dim3(2048, 9), 256>>>(x);               // xrev + fused m sum
    k_gram6  <<<dim3(KCH, 3, 16), 128>>>(x);            // partial tiles (tf32 + cp.async)
    k_gred   <<<dim3(64, 3, 16), 256>>>();              // -> S, M
    k_mirror <<<dim3(64, 16), 256>>>();
    k_mmA    <<<gm, 256>>>(w2);                         // P = M * W2^T
    k_mmB    <<<gm, 256>>>(w1, Pp, Gfp);                // Gf = W1 * P
    k_mmU    <<<dim3(4, 4, 16), 256>>>(w1, w2);         // U1 -> g_P, U2 -> g_gp
    k_rowdot2<<<dim3(2048, 2), 256>>>(w1, w2, b1, b2);
    k_gtab2  <<<3456, 256>>>();
    k_attn2  <<<64, 256>>>(b1, b2, temp);
    k_vconv  <<<dim3(96, 32), 128>>>();                 // conv via tensor cores
    k_mix2   <<<dim3(72, 64), 256>>>();                 // mix + transpose -> R
    k_gemm_tf32<<<gg, 128>>>(Rp, wo, nullptr, out);
}

// round 13
// speedup vs baseline: 2.8033x; 1.0209x over previous
#include <cuda_runtime.h>
#include <math.h>
#include <stdint.h>

#define NB 8
#define NC 256
#define NHW 9216
#define NHEAD 8
#define KCH 36            // gram split-K chunks (grid 1728 = 97% wave eff)

// ---------------- scratch (device globals; no allocation anywhere) ----------
__device__ float  g_v[NB*NC*NHW];         // 75.5 MB
__device__ float  g_xrev[NB*NC*NHW];      // 75.5 MB
__device__ float  g_gp[KCH*3*16*128*128]; // 113 MB gram partials; first 2MB reused as U2
__device__ float  g_S[NB*256*256];
__device__ float  g_M[NB*256*256];
__device__ float  g_P[NB*256*256];
__device__ float  g_Gf[NB*256*256];
__device__ float  g_m[NB*256];
__device__ float  g_nq[NB*256], g_nk[NB*256];
__device__ float  g_w1m[NB*256], g_w2m[NB*256];
__device__ float2 g_Chat[64*1024];
__device__ float  g_gcre[96*96*96];       // circulant conv tables
__device__ float  g_gcim[96*96*96];
__device__ float2 g_Tt[NB*NC*NHW];        // 151 MB, layout [ch][r][a]
__device__ float  g_R [NB*NC*NHW];

// ---------------- tf32 / cp.async / f32x2 helpers ----------------------------
__device__ __forceinline__ uint32_t f2tf32(float x) {
    uint32_t r;
    asm("cvt.rna.tf32.f32 %0, %1;" : "=r"(r) : "f"(x));
    return r;
}
__device__ __forceinline__ void mma_tf32(float* c, const uint32_t* a, const uint32_t* b) {
    asm volatile(
        "mma.sync.aligned.m16n8k8.row.col.f32.tf32.tf32.f32 "
        "{%0,%1,%2,%3}, {%4,%5,%6,%7}, {%8,%9}, {%0,%1,%2,%3};"
        : "+f"(c[0]), "+f"(c[1]), "+f"(c[2]), "+f"(c[3])
        : "r"(a[0]), "r"(a[1]), "r"(a[2]), "r"(a[3]), "r"(b[0]), "r"(b[1]));
}
__device__ __forceinline__ void cpa16(void* dst, const void* src) {
    uint32_t d = (uint32_t)__cvta_generic_to_shared(dst);
    asm volatile("cp.async.cg.shared.global [%0], [%1], 16;" :: "r"(d), "l"(src));
}
#define CP_COMMIT() asm volatile("cp.async.commit_group;")
#define CP_WAIT0()  asm volatile("cp.async.wait_group 0;")

__device__ __forceinline__ unsigned long long pk2(float lo, float hi) {
    unsigned long long r;
    asm("mov.b64 %0, {%1, %2};" : "=l"(r) : "f"(lo), "f"(hi));
    return r;
}
__device__ __forceinline__ void upk2(float& lo, float& hi, unsigned long long v) {
    asm("mov.b64 {%0, %1}, %2;" : "=f"(lo), "=f"(hi) : "l"(v));
}
__device__ __forceinline__ unsigned long long fma2(
    unsigned long long a, unsigned long long b, unsigned long long c) {
    unsigned long long d;
    asm("fma.rn.f32x2 %0, %1, %2, %3;" : "=l"(d) : "l"(a), "l"(b), "l"(c));
    return d;
}

// ---------------- tf32 GEMM: Y[b][o][s] = sum_c W[o][c] X[b][c][s] (+bias) ---
// Single barrier per K-iter; cp.async fill issued before fragment loads.
__global__ void __launch_bounds__(128, 3) k_gemm_tf32(
    const float* __restrict__ X, const float* __restrict__ W,
    const float* __restrict__ bias, float* __restrict__ Y)
{
    __shared__ __align__(16) float Wm[2][128][12];
    __shared__ __align__(16) float Xs[2][8][136];
    const int t  = threadIdx.x;
    const int s0 = blockIdx.x * 128;
    const int o0 = blockIdx.y * 128;
    const int b  = blockIdx.z;
    const int warp = t >> 5, lane = t & 31;
    const int gid = lane >> 2, tig = lane & 3;
    const int mrow = (warp >> 1) * 64;
    const int ncol = (warp & 1) * 64;
    const float* Xb = X + (size_t)b * NC * NHW;
    const int xr = t >> 4, xc = (t & 15) * 8;

    float c[4][8][4];
#pragma unroll
    for (int i = 0; i < 4; i++)
#pragma unroll
        for (int j = 0; j < 8; j++)
#pragma unroll
            for (int q = 0; q < 4; q++) c[i][j][q] = 0.f;

    cpa16(&Wm[0][t][0], &W[(o0 + t) * 256 + 0]);
    cpa16(&Wm[0][t][4], &W[(o0 + t) * 256 + 4]);
    cpa16(&Xs[0][xr][xc],     &Xb[(size_t)xr * NHW + s0 + xc]);
    cpa16(&Xs[0][xr][xc + 4], &Xb[(size_t)xr * NHW + s0 + xc + 4]);
    CP_COMMIT();

    for (int i = 0; i < 32; i++) {
        const int st = i & 1;
        CP_WAIT0();
        __syncthreads();
        // fill next stage (overlaps with fragment loads + mma below)
        if (i + 1 < 32) {
            const int kc = (i + 1) * 8, sn = st ^ 1;
            cpa16(&Wm[sn][t][0], &W[(o0 + t) * 256 + kc]);
            cpa16(&Wm[sn][t][4], &W[(o0 + t) * 256 + kc + 4]);
            cpa16(&Xs[sn][xr][xc],     &Xb[(size_t)(kc + xr) * NHW + s0 + xc]);
            cpa16(&Xs[sn][xr][xc + 4], &Xb[(size_t)(kc + xr) * NHW + s0 + xc + 4]);
        }
        CP_COMMIT();
        uint32_t afr[4][4], bfr[8][2];
#pragma unroll
        for (int mt = 0; mt < 4; mt++) {
            int m0 = mrow + mt * 16;
            afr[mt][0] = f2tf32(Wm[st][m0 + gid][tig]);
            afr[mt][1] = f2tf32(Wm[st][m0 + gid + 8][tig]);
            afr[mt][2] = f2tf32(Wm[st][m0 + gid][tig + 4]);
            afr[mt][3] = f2tf32(Wm[st][m0 + gid + 8][tig + 4]);
        }
#pragma unroll
        for (int nt = 0; nt < 8; nt++) {
            int n0 = ncol + nt * 8;
            bfr[nt][0] = f2tf32(Xs[st][tig][n0 + gid]);
            bfr[nt][1] = f2tf32(Xs[st][tig + 4][n0 + gid]);
        }
#pragma unroll
        for (int mt = 0; mt < 4; mt++)
#pragma unroll
            for (int nt = 0; nt < 8; nt++)
                mma_tf32(c[mt][nt], afr[mt], bfr[nt]);
    }

#pragma unroll
    for (int mt = 0; mt < 4; mt++) {
        int oa = o0 + mrow + mt * 16 + gid;
        int ob = oa + 8;
        float ba  = bias ? bias[oa] : 0.f;
        float bb_ = bias ? bias[ob] : 0.f;
        float* ya = Y + (size_t)(b * NC + oa) * NHW + s0;
        float* yb = Y + (size_t)(b * NC + ob) * NHW + s0;
#pragma unroll
        for (int nt = 0; nt < 8; nt++) {
            int sc = ncol + nt * 8 + tig * 2;
            *(float2*)&ya[sc] = make_float2(c[mt][nt][0] + ba,  c[mt][nt][1] + ba);
            *(float2*)&yb[sc] = make_float2(c[mt][nt][2] + bb_, c[mt][nt][3] + bb_);
        }
    }
}

// ---------------- zero g_m ----------------------------------------------------
__global__ void k_zm() { g_m[blockIdx.x * 256 + threadIdx.x] = 0.f; }

// ---------------- reversed copy + fused channel sum --------------------------
__global__ void __launch_bounds__(256) k_revx(const float* __restrict__ X)
{
    const int ch = blockIdx.x;
    const int seg = blockIdx.y;
    const float* src = X + (size_t)ch * NHW;
    float* dst = g_xrev + (size_t)ch * NHW;
    int s = seg * 1024 + threadIdx.x;
    float lsum = 0.f;
#pragma unroll
    for (int i = 0; i < 4; i++, s += 256) {
        int y = s / 96, x = s - y * 96;
        int ry = (y == 0) ? 0 : 96 - y;
        int rx = (x == 0) ? 0 : 96 - x;
        float v = src[ry * 96 + rx];
        dst[s] = v;
        lsum += v;
    }
#pragma unroll
    for (int o = 16; o; o >>= 1) lsum += __shfl_xor_sync(0xffffffff, lsum, o);
    __shared__ float sb[8];
    int w = threadIdx.x >> 5;
    if ((threadIdx.x & 31) == 0) sb[w] = lsum;
    __syncthreads();
    if (threadIdx.x == 0) {
        float a = 0.f;
        for (int i = 0; i < 8; i++) a += sb[i];
        atomicAdd(&g_m[ch], a);
    }
}

// ---------------- Gram GEMM (tf32, cp.async, 1 barrier/iter) ----------------
__global__ void __launch_bounds__(128, 3) k_gram6(const float* __restrict__ X)
{
    const int sch = blockIdx.x, pr = blockIdx.y;
    const int b = blockIdx.z >> 1, mat = blockIdx.z & 1;
    const int ci = (pr == 2) ? 1 : 0;
    const int dj = (pr == 0) ? 0 : 1;
    __shared__ __align__(16) float Am[2][128][12];
    __shared__ __align__(16) float Dm[2][128][12];
    const float* Xa = X + (size_t)b * NC * NHW;
    const float* Xd = (mat ? g_xrev : X) + (size_t)b * NC * NHW;
    const int t = threadIdx.x;
    const int warp = t >> 5, lane = t & 31;
    const int gid = lane >> 2, tig = lane & 3;
    const int mrow = (warp >> 1) * 64;
    const int ncol = (warp & 1) * 64;
    const int base = sch * (NHW / KCH);
    const float* arow = &Xa[(size_t)(ci * 128 + t) * NHW + base];
    const float* drow = &Xd[(size_t)(dj * 128 + t) * NHW + base];

    float c[4][8][4];
#pragma unroll
    for (int i = 0; i < 4; i++)
#pragma unroll
        for (int j = 0; j < 8; j++)
#pragma unroll
            for (int q = 0; q < 4; q++) c[i][j][q] = 0.f;

    cpa16(&Am[0][t][0], &arow[0]);
    cpa16(&Am[0][t][4], &arow[4]);
    cpa16(&Dm[0][t][0], &drow[0]);
    cpa16(&Dm[0][t][4], &drow[4]);
    CP_COMMIT();

    const int NKS = NHW / (KCH * 8);   // 32
    for (int i = 0; i < NKS; i++) {
        const int st = i & 1;
        CP_WAIT0();
        __syncthreads();
        if (i + 1 < NKS) {
            const int ko = (i + 1) * 8, sn = st ^ 1;
            cpa16(&Am[sn][t][0], &arow[ko]);
            cpa16(&Am[sn][t][4], &arow[ko + 4]);
            cpa16(&Dm[sn][t][0], &drow[ko]);
            cpa16(&Dm[sn][t][4], &drow[ko + 4]);
        }
        CP_COMMIT();
        uint32_t afr[4][4], bfr[8][2];
#pragma unroll
        for (int mt = 0; mt < 4; mt++) {
            int m0 = mrow + mt * 16;
            afr[mt][0] = f2tf32(Am[st][m0 + gid][tig]);
            afr[mt][1] = f2tf32(Am[st][m0 + gid + 8][tig]);
            afr[mt][2] = f2tf32(Am[st][m0 + gid][tig + 4]);
            afr[mt][3] = f2tf32(Am[st][m0 + gid + 8][tig + 4]);
        }
#pragma unroll
        for (int nt = 0; nt < 8; nt++) {
            int n0 = ncol + nt * 8;
            bfr[nt][0] = f2tf32(Dm[st][n0 + gid][tig]);
            bfr[nt][1] = f2tf32(Dm[st][n0 + gid][tig + 4]);
        }
#pragma unroll
        for (int mt = 0; mt < 4; mt++)
#pragma unroll
            for (int nt = 0; nt < 8; nt++)
                mma_tf32(c[mt][nt], afr[mt], bfr[nt]);
    }

    float* Out = g_gp + ((size_t)(blockIdx.z * 3 + pr) * KCH + sch) * 16384;
#pragma unroll
    for (int mt = 0; mt < 4; mt++) {
        int ra = mrow + mt * 16 + gid;
        int rb = ra + 8;
#pragma unroll
        for (int nt = 0; nt < 8; nt++) {
            int col = ncol + nt * 8 + tig * 2;
            *(float2*)&Out[ra * 128 + col] = make_float2(c[mt][nt][0], c[mt][nt][1]);
            *(float2*)&Out[rb * 128 + col] = make_float2(c[mt][nt][2], c[mt][nt][3]);
        }
    }
}

// ---------------- reduce partials into S / M --------------------------------
__global__ void __launch_bounds__(256) k_gred()
{
    const int pr = blockIdx.y, bm = blockIdx.z;
    const int b = bm >> 1, mat = bm & 1;
    const int ci = (pr == 2) ? 1 : 0;
    const int dj = (pr == 0) ? 0 : 1;
    const int off = blockIdx.x * 256 + threadIdx.x;
    const float* Pp = g_gp + (size_t)(bm * 3 + pr) * KCH * 16384 + off;
    float s = 0.f;
#pragma unroll
    for (int c = 0; c < KCH; c++) s += Pp[c * 16384];
    int il = off >> 7, jl = off & 127;
    float* Out = (mat ? g_M : g_S) + b * 65536;
    Out[(ci * 128 + il) * 256 + dj * 128 + jl] = s;
}

// ---------------- mirror lower-left 128x128 block ---------------------------
__global__ void k_mirror()
{
    const int bm = blockIdx.y;
    float* Out = (bm & 1 ? g_M : g_S) + (bm >> 1) * 65536;
    int idx = blockIdx.x * 256 + threadIdx.x;
    int i = idx >> 7, jl = idx & 127;
    Out[(128 + jl) * 256 + i] = Out[i * 256 + 128 + jl];
}

// ---------------- P[b] = M[b] * W2^T ----------------------------------------
__global__ void __launch_bounds__(256) k_mmA(const float* __restrict__ Wg)
{
    const int j0 = blockIdx.x * 64, i0 = blockIdx.y * 64, b = blockIdx.z;
    const float* A = g_M + b * 65536;
    float* C = g_P + b * 65536;
    __shared__ float As[16][68];
    __shared__ float Bs[16][68];
    const int t = threadIdx.x;
    const int it = (t >> 4) * 4, jt = (t & 15) * 4;
    float acc[4][4];
#pragma unroll
    for (int i = 0; i < 4; i++)
#pragma unroll
        for (int j = 0; j < 4; j++) acc[i][j] = 0.f;
    for (int kc = 0; kc < 256; kc += 16) {
        __syncthreads();
#pragma unroll
        for (int i = 0; i < 4; i++) {
            int idx = i * 256 + t;
            int r = idx >> 4, kk = idx & 15;
            As[kk][r] = A[(i0 + r) * 256 + kc + kk];
            Bs[kk][r] = Wg[(j0 + r) * 256 + kc + kk];
        }
        __syncthreads();
#pragma unroll
        for (int kk = 0; kk < 16; kk++) {
            float a[4], bb[4];
            *(float4*)a  = *(float4*)&As[kk][it];
            *(float4*)bb = *(float4*)&Bs[kk][jt];
#pragma unroll
            for (int i = 0; i < 4; i++)
#pragma unroll
                for (int j = 0; j < 4; j++) acc[i][j] += a[i] * bb[j];
        }
    }
#pragma unroll
    for (int i = 0; i < 4; i++)
#pragma unroll
        for (int j = 0; j < 4; j++)
            C[(i0 + it + i) * 256 + j0 + jt + j] = acc[i][j];
}

// ---------------- C[b] = Ag * B[b]  (generic, used for Gf) -------------------
__global__ void __launch_bounds__(256) k_mmB(
    const float* __restrict__ Ag, const float* __restrict__ Bb, float* __restrict__ Cb)
{
    const int j0 = blockIdx.x * 64, i0 = blockIdx.y * 64, b = blockIdx.z;
    const float* B = Bb + b * 65536;
    float* C = Cb + b * 65536;
    __shared__ float As[16][68];
    __shared__ float Bs[16][68];
    const int t = threadIdx.x;
    const int it = (t >> 4) * 4, jt = (t & 15) * 4;
    float acc[4][4];
#pragma unroll
    for (int i = 0; i < 4; i++)
#pragma unroll
        for (int j = 0; j < 4; j++) acc[i][j] = 0.f;
    for (int kc = 0; kc < 256; kc += 16) {
        __syncthreads();
#pragma unroll
        for (int i = 0; i < 4; i++) {
            int idx = i * 256 + t;
            int r = idx >> 4, kk = idx & 15;
            As[kk][r] = Ag[(i0 + r) * 256 + kc + kk];
        }
#pragma unroll
        for (int i = 0; i < 4; i++) {
            int idx = i * 256 + t;
            int kk = idx >> 6, j = idx & 63;
            Bs[kk][j] = B[(kc + kk) * 256 + j0 + j];
        }
        __syncthreads();
#pragma unroll
        for (int kk = 0; kk < 16; kk++) {
            float a[4], bb[4];
            *(float4*)a  = *(float4*)&As[kk][it];
            *(float4*)bb = *(float4*)&Bs[kk][jt];
#pragma unroll
            for (int i = 0; i < 4; i++)
#pragma unroll
                for (int j = 0; j < 4; j++) acc[i][j] += a[i] * bb[j];
        }
    }
#pragma unroll
    for (int i = 0; i < 4; i++)
#pragma unroll
        for (int j = 0; j < 4; j++)
            C[(i0 + it + i) * 256 + j0 + jt + j] = acc[i][j];
}

// ---------------- batched U = W{1,2} * S  (z = b*2 + which) ------------------
__global__ void __launch_bounds__(256) k_mmU(
    const float* __restrict__ W1, const float* __restrict__ W2)
{
    const int j0 = blockIdx.x * 64, i0 = blockIdx.y * 64;
    const int b = blockIdx.z >> 1, which = blockIdx.z & 1;
    const float* Ag = which ? W2 : W1;
    const float* B = g_S + b * 65536;
    float* C = (which ? g_gp : g_P) + b * 65536;
    __shared__ float As[16][68];
    __shared__ float Bs[16][68];
    const int t = threadIdx.x;
    const int it = (t >> 4) * 4, jt = (t & 15) * 4;
    float acc[4][4];
#pragma unroll
    for (int i = 0; i < 4; i++)
#pragma unroll
        for (int j = 0; j < 4; j++) acc[i][j] = 0.f;
    for (int kc = 0; kc < 256; kc += 16) {
        __syncthreads();
#pragma unroll
        for (int i = 0; i < 4; i++) {
            int idx = i * 256 + t;
            int r = idx >> 4, kk = idx & 15;
            As[kk][r] = Ag[(i0 + r) * 256 + kc + kk];
        }
#pragma unroll
        for (int i = 0; i < 4; i++) {
            int idx = i * 256 + t;
            int kk = idx >> 6, j = idx & 63;
            Bs[kk][j] = B[(kc + kk) * 256 + j0 + j];
        }
        __syncthreads();
#pragma unroll
        for (int kk = 0; kk < 16; kk++) {
            float a[4], bb[4];
            *(float4*)a  = *(float4*)&As[kk][it];
            *(float4*)bb = *(float4*)&Bs[kk][jt];
#pragma unroll
            for (int i = 0; i < 4; i++)
#pragma unroll
                for (int j = 0; j < 4; j++) acc[i][j] += a[i] * bb[j];
        }
    }
#pragma unroll
    for (int i = 0; i < 4; i++)
#pragma unroll
        for (int j = 0; j < 4; j++)
            C[(i0 + it + i) * 256 + j0 + jt + j] = acc[i][j];
}

// ---------------- batched row-dot: norms + W*m (y = which) -------------------
__global__ void __launch_bounds__(256) k_rowdot2(
    const float* __restrict__ W1, const float* __restrict__ W2,
    const float* __restrict__ b1, const float* __restrict__ b2)
{
    const int bC = blockIdx.x;
    const int which = blockIdx.y;
    const int b = bC >> 8, C = bC & 255;
    const float* U = (which ? g_gp : g_P);
    const float* W = which ? W2 : W1;
    const float* bias = which ? b2 : b1;
    const int t = threadIdx.x;
    float wv = W[C * 256 + t];
    float un = U[(size_t)b * 65536 + C * 256 + t] * wv;
    float wm = wv * g_m[b * 256 + t];
#pragma unroll
    for (int o = 16; o; o >>= 1) {
        un += __shfl_xor_sync(0xffffffff, un, o);
        wm += __shfl_xor_sync(0xffffffff, wm, o);
    }
    __shared__ float s1[8], s2[8];
    int w = t >> 5;
    if ((t & 31) == 0) { s1[w] = un; s2[w] = wm; }
    __syncthreads();
    if (t == 0) {
        float a = 0.f, c = 0.f;
        for (int i = 0; i < 8; i++) { a += s1[i]; c += s2[i]; }
        float bc = bias[C];
        float nf = a + 2.f * bc * c + 9216.f * bc * bc;
        if (which) { g_nk[bC] = nf; g_w2m[bC] = c; }
        else       { g_nq[bC] = nf; g_w1m[bC] = c; }
    }
}

// ---------------- attn: logits, softmax, build Chat -------------------------
__global__ void __launch_bounds__(256) k_attn2(
    const float* __restrict__ b1, const float* __restrict__ b2,
    const float* __restrict__ temperature)
{
    const int bh = blockIdx.x;
    const int b = bh >> 3, h = bh & 7;
    const int ch0 = h * 32;
    __shared__ float A[32][33];
    __shared__ float rq[32], rk[32], sw1m[32], sw2m[32], sb1[32], sb2[32];
    __shared__ float2 tab[32];
    const int t = threadIdx.x;
    if (t < 32) {
        int C = b * 256 + ch0 + t;
        rq[t] = rsqrtf(g_nq[C]);
        rk[t] = rsqrtf(g_nk[C]);
        sw1m[t] = g_w1m[C];
        sw2m[t] = g_w2m[C];
        sb1[t] = b1[ch0 + t];
        sb2[t] = b2[ch0 + t];
        float ang = 6.283185307179586f * (float)t / 32.0f;
        tab[t] = make_float2(cosf(ang), sinf(ang));
    }
    __syncthreads();
    const float ts = temperature[h];
    const int w = t >> 5, lane = t & 31;
    for (int r = w; r < 32; r += 8) {
        float Gv = g_Gf[(size_t)b * 65536 + (ch0 + r) * 256 + ch0 + lane];
        float L = (Gv + sw1m[r] * sb2[lane] + sb1[r] * sw2m[lane]
                   + 9216.f * sb1[r] * sb2[lane]) * rq[r] * rk[lane] * ts;
        float m = L;
#pragma unroll
        for (int o = 16; o; o >>= 1) m = fmaxf(m, __shfl_xor_sync(0xffffffff, m, o));
        float e = expf(L - m);
        float s = e;
#pragma unroll
        for (int o = 16; o; o >>= 1) s += __shfl_xor_sync(0xffffffff, s, o);
        A[r][lane] = e / s;
    }
    __syncthreads();
    for (int idx = t; idx < 1024; idx += 256) {
        int e = idx >> 5, d = idx & 31;
        float re = 0.f, im = 0.f;
#pragma unroll 8
        for (int c = 0; c < 32; c++) {
            float a = A[c][d];
            float2 tb = tab[(c * e) & 31];
            re += a * tb.x; im += a * tb.y;
        }
        re *= (1.0f / 32.0f); im *= (1.0f / 32.0f);
        if (e == 0) im += (1.0f / 32.0f);
        g_Chat[bh * 1024 + idx] = make_float2(re, im);
    }
}

// ---------------- circulant tables (trig inline): gc[r][w][a] ----------------
__global__ void k_gtab2()
{
    int idx = blockIdx.x * 256 + threadIdx.x;
    int r = idx / 9216;
    int rem = idx - r * 9216;
    int w = rem / 96, a = rem - w * 96;
    int tt = a - w; if (tt < 0) tt += 96;
    float2 g;
    if (r == 0) {
        g = make_float2(tt == 0 ? 1.f : 0.f, 0.f);
    } else {
        const float PI = 3.14159265358979323846f;
        float h1 = PI * (float)r / 96.0f;
        float h2 = PI * (96.0f * (float)tt + (float)r) / 9216.0f;
        float rr = sinf(h1) / (96.0f * sinf(h2));
        float psi = h1 - h2;
        g = make_float2(rr * cosf(psi), rr * sinf(psi));
    }
    g_gcre[idx] = g.x;
    g_gcim[idx] = g.y;
}

// ---------------- conv as batched tf32 GEMM (double-buffered, 1 bar/iter) ----
__global__ void __launch_bounds__(128) k_vconv()
{
    const int r = blockIdx.x;
    const int ch0 = blockIdx.y * 64;
    __shared__ __align__(16) uint32_t As[2][8][72];
    __shared__ __align__(16) uint32_t Br[2][8][104];
    __shared__ __align__(16) uint32_t Bi[2][8][104];
    const int t = threadIdx.x;
    const int warp = t >> 5, lane = t & 31;
    const int gid = lane >> 2, tig = lane & 3;
    const int mrow = (warp >> 1) * 32;
    const int ncol = (warp & 1) * 48;
    const int ach = t >> 1, aw4 = (t & 1) * 4;
    const int bw = t >> 4, ba0 = (t & 15) * 6;

    float cre[2][6][4], cim[2][6][4];
#pragma unroll
    for (int i = 0; i < 2; i++)
#pragma unroll
        for (int j = 0; j < 6; j++)
#pragma unroll
            for (int q = 0; q < 4; q++) { cre[i][j][q] = 0.f; cim[i][j][q] = 0.f; }

    float4 av;
    float br[6], bi[6];
    av = *(const float4*)&g_v[(size_t)(ch0 + ach) * NHW + r * 96 + aw4];
    {
        const float* pr_ = &g_gcre[(size_t)r * 9216 + bw * 96 + ba0];
        const float* pi_ = &g_gcim[(size_t)r * 9216 + bw * 96 + ba0];
#pragma unroll
        for (int i = 0; i < 6; i++) { br[i] = pr_[i]; bi[i] = pi_[i]; }
    }

    for (int ks = 0; ks < 12; ks++) {
        const int st = ks & 1;
        As[st][aw4 + 0][ach] = f2tf32(av.x);
        As[st][aw4 + 1][ach] = f2tf32(av.y);
        As[st][aw4 + 2][ach] = f2tf32(av.z);
        As[st][aw4 + 3][ach] = f2tf32(av.w);
#pragma unroll
        for (int i = 0; i < 6; i++) {
            Br[st][bw][ba0 + i] = f2tf32(br[i]);
            Bi[st][bw][ba0 + i] = f2tf32(bi[i]);
        }
        __syncthreads();

        int w0n = (ks + 1 < 12) ? (ks + 1) * 8 : 0;
        av = *(const float4*)&g_v[(size_t)(ch0 + ach) * NHW + r * 96 + w0n + aw4];
        {
            const float* pr_ = &g_gcre[(size_t)r * 9216 + (w0n + bw) * 96 + ba0];
            const float* pi_ = &g_gcim[(size_t)r * 9216 + (w0n + bw) * 96 + ba0];
#pragma unroll
            for (int i = 0; i < 6; i++) { br[i] = pr_[i]; bi[i] = pi_[i]; }
        }

        uint32_t afr[2][4], bre[6][2], bim[6][2];
#pragma unroll
        for (int mt = 0; mt < 2; mt++) {
            int m0 = mrow + mt * 16;
            afr[mt][0] = As[st][tig][m0 + gid];
            afr[mt][1] = As[st][tig][m0 + gid + 8];
            afr[mt][2] = As[st][tig + 4][m0 + gid];
            afr[mt][3] = As[st][tig + 4][m0 + gid + 8];
        }
#pragma unroll
        for (int nt = 0; nt < 6; nt++) {
            int n0 = ncol + nt * 8;
            bre[nt][0] = Br[st][tig][n0 + gid];
            bre[nt][1] = Br[st][tig + 4][n0 + gid];
            bim[nt][0] = Bi[st][tig][n0 + gid];
            bim[nt][1] = Bi[st][tig + 4][n0 + gid];
        }
#pragma unroll
        for (int mt = 0; mt < 2; mt++)
#pragma unroll
            for (int nt = 0; nt < 6; nt++) {
                mma_tf32(cre[mt][nt], afr[mt], bre[nt]);
                mma_tf32(cim[mt][nt], afr[mt], bim[nt]);
            }
    }

#pragma unroll
    for (int mt = 0; mt < 2; mt++) {
        int r0 = ch0 + mrow + mt * 16 + gid;
        int r1 = r0 + 8;
        float2* p0 = &g_Tt[(size_t)r0 * NHW + r * 96];
        float2* p1 = &g_Tt[(size_t)r1 * NHW + r * 96];
#pragma unroll
        for (int nt = 0; nt < 6; nt++) {
            int a = ncol + nt * 8 + tig * 2;
            p0[a]     = make_float2(cre[mt][nt][0], cim[mt][nt][0]);
            p0[a + 1] = make_float2(cre[mt][nt][1], cim[mt][nt][1]);
            p1[a]     = make_float2(cre[mt][nt][2], cim[mt][nt][2]);
            p1[a + 1] = make_float2(cre[mt][nt][3], cim[mt][nt][3]);
        }
    }
}

// ---------------- mix + fused transpose, packed f32x2 -------------------------
__global__ void __launch_bounds__(256) k_mix2()
{
    const int rt = blockIdx.x % 3;     // r-tile of 32
    const int at = blockIdx.x / 3;     // a-tile of 4 (0..23)
    const int bh = blockIdx.y;
    __shared__ float2 Ch[1024];
    __shared__ float2 Ts[32][128];     // [d][rl*4+al]
    const int t = threadIdx.x;
    for (int i = t; i < 1024; i += 256) Ch[i] = g_Chat[bh * 1024 + i];
    for (int i = t; i < 1024; i += 256) {
        int d = i >> 5, rl = i & 31;
        const float2* src = &g_Tt[(size_t)(bh * 32 + d) * NHW + (rt * 32 + rl) * 96 + at * 4];
        *(float4*)&Ts[d][rl * 4]     = *(const float4*)src;
        *(float4*)&Ts[d][rl * 4 + 2] = *(const float4*)(src + 2);
    }
    __syncthreads();
    const int sl = t & 63, eg = t >> 6;
    const unsigned long long SGN = 0x8000000080000000ULL;

    unsigned long long ar0p[4], ai0p[4], ar1p[4], ai1p[4];
#pragma unroll
    for (int j = 0; j < 4; j++) { ar0p[j] = ai0p[j] = ar1p[j] = ai1p[j] = 0ULL; }

    for (int d = 0; d < 32; d++) {
        float2 t0 = Ts[d][sl];
        float2 t1 = Ts[d][sl + 64];
        unsigned long long t0x = pk2(t0.x, t0.x), t0y = pk2(t0.y, t0.y);
        unsigned long long t1x = pk2(t1.x, t1.x), t1y = pk2(t1.y, t1.y);
#pragma unroll
        for (int j = 0; j < 4; j++) {
            float2 cA = Ch[(eg * 8 + 2 * j) * 32 + d];
            float2 cB = Ch[(eg * 8 + 2 * j + 1) * 32 + d];
            unsigned long long cx  = pk2(cA.x, cB.x);
            unsigned long long cy  = pk2(cA.y, cB.y);
            unsigned long long cyn = cy ^ SGN;
            ar0p[j] = fma2(cx,  t0x, ar0p[j]);
            ar0p[j] = fma2(cyn, t0y, ar0p[j]);
            ai0p[j] = fma2(cx,  t0y, ai0p[j]);
            ai0p[j] = fma2(cy,  t0x, ai0p[j]);
            ar1p[j] = fma2(cx,  t1x, ar1p[j]);
            ar1p[j] = fma2(cyn, t1y, ar1p[j]);
            ai1p[j] = fma2(cx,  t1y, ai1p[j]);
            ai1p[j] = fma2(cy,  t1x, ai1p[j]);
        }
    }

    const int al0 = sl & 3,        rl0 = sl >> 2;
    const int al1 = (sl + 64) & 3, rl1 = (sl + 64) >> 2;
#pragma unroll
    for (int j = 0; j < 4; j++) {
        float a0, a1, b0, b1, c0, c1, d0, d1;
        upk2(a0, a1, ar0p[j]);
        upk2(b0, b1, ai0p[j]);
        upk2(c0, c1, ar1p[j]);
        upk2(d0, d1, ai1p[j]);
        int row0 = bh * 32 + eg * 8 + 2 * j;
        int row1 = row0 + 1;
        g_R[(size_t)row0 * NHW + (at * 4 + al0) * 96 + rt * 32 + rl0] = sqrtf(a0 * a0 + b0 * b0);
        g_R[(size_t)row1 * NHW + (at * 4 + al0) * 96 + rt * 32 + rl0] = sqrtf(a1 * a1 + b1 * b1);
        g_R[(size_t)row0 * NHW + (at * 4 + al1) * 96 + rt * 32 + rl1] = sqrtf(c0 * c0 + d0 * d0);
        g_R[(size_t)row1 * NHW + (at * 4 + al1) * 96 + rt * 32 + rl1] = sqrtf(c1 * c1 + d1 * d1);
    }
}

// ---------------- launch ----------------
extern "C" void kernel_launch(void* const* d_in, const int* in_sizes, int n_in,
                              void* d_out, int out_size)
{
    const float* x    = (const float*)d_in[0];
    const float* w1   = (const float*)d_in[1];
    const float* b1   = (const float*)d_in[2];
    const float* w2   = (const float*)d_in[3];
    const float* b2   = (const float*)d_in[4];
    const float* w3   = (const float*)d_in[5];
    const float* b3   = (const float*)d_in[6];
    const float* wo   = (const float*)d_in[7];
    const float* temp = (const float*)d_in[8];
    float* out = (float*)d_out;

    float *vp = nullptr, *Rp = nullptr, *Pp = nullptr, *Gfp = nullptr;
    cudaGetSymbolAddress((void**)&vp,  g_v);
    cudaGetSymbolAddress((void**)&Rp,  g_R);
    cudaGetSymbolAddress((void**)&Pp,  g_P);
    cudaGetSymbolAddress((void**)&Gfp, g_Gf);

    dim3 gg(72, 2, 8);
    dim3 gm(4, 4, 8);

    k_gemm_tf32<<<gg, 128>>>(x, w3, b3, vp);            // v
    k_zm     <<<8, 256>>>();
    k_revx   <<<dim3(2048, 9), 256>>>(x);               // xrev + fused m sum
    k_gram6  <<<dim3(KCH, 3, 16), 128>>>(x);            // partial tiles
    k_gred   <<<dim3(64, 3, 16), 256>>>();              // -> S, M
    k_mirror <<<dim3(64, 16), 256>>>();
    k_mmA    <<<gm, 256>>>(w2);                         // P = M * W2^T
    k_mmB    <<<gm, 256>>>(w1, Pp, Gfp);                // Gf = W1 * P
    k_mmU    <<<dim3(4, 4, 16), 256>>>(w1, w2);         // U1 -> g_P, U2 -> g_gp
    k_rowdot2<<<dim3(2048, 2), 256>>>(w1, w2, b1, b2);
    k_gtab2  <<<3456, 256>>>();
    k_attn2  <<<64, 256>>>(b1, b2, temp);
    k_vconv  <<<dim3(96, 32), 128>>>();                 // conv via tensor cores
    k_mix2   <<<dim3(72, 64), 256>>>();                 // mix + transpose -> R
    k_gemm_tf32<<<gg, 128>>>(Rp, wo, nullptr, out);
}

// round 14
// speedup vs baseline: 2.8275x; 1.0086x over previous
#include <cuda_runtime.h>
#include <math.h>
#include <stdint.h>

#define NB 8
#define NC 256
#define NHW 9216
#define NHEAD 8
#define KCH 36            // gram split-K chunks

// ---------------- scratch (device globals; no allocation anywhere) ----------
__device__ float  g_v[NB*NC*NHW];         // tf32 bits (v-GEMM output)
__device__ float  g_xrev[NB*NC*NHW];      // tf32 bits, spatially reversed x
__device__ float  g_xtf[NB*NC*NHW];       // tf32 bits, linear x
__device__ float  g_gp[KCH*3*16*128*128]; // gram partials; first 2MB reused as U2
__device__ float  g_S[NB*256*256];
__device__ float  g_M[NB*256*256];
__device__ float  g_P[NB*256*256];
__device__ float  g_Gf[NB*256*256];
__device__ float  g_w3t[256*256], g_wot[256*256];   // tf32 bits weights
__device__ float  g_m[NB*256];
__device__ float  g_nq[NB*256], g_nk[NB*256];
__device__ float  g_w1m[NB*256], g_w2m[NB*256];
__device__ float2 g_Chat[64*1024];
__device__ float  g_gcre[96*96*96];       // tf32 bits conv tables
__device__ float  g_gcim[96*96*96];
__device__ float2 g_Tt[NB*NC*NHW];        // [ch][r][a]
__device__ float  g_R [NB*NC*NHW];        // tf32 bits (mix output)

// ---------------- helpers -----------------------------------------------------
__device__ __forceinline__ uint32_t f2tf32(float x) {
    uint32_t r;
    asm("cvt.rna.tf32.f32 %0, %1;" : "=r"(r) : "f"(x));
    return r;
}
__device__ __forceinline__ float tfbits(float x) { return __uint_as_float(f2tf32(x)); }
__device__ __forceinline__ void mma_tf32(float* c, const uint32_t* a, const uint32_t* b) {
    asm volatile(
        "mma.sync.aligned.m16n8k8.row.col.f32.tf32.tf32.f32 "
        "{%0,%1,%2,%3}, {%4,%5,%6,%7}, {%8,%9}, {%0,%1,%2,%3};"
        : "+f"(c[0]), "+f"(c[1]), "+f"(c[2]), "+f"(c[3])
        : "r"(a[0]), "r"(a[1]), "r"(a[2]), "r"(a[3]), "r"(b[0]), "r"(b[1]));
}
__device__ __forceinline__ void cpa16(void* dst, const void* src) {
    uint32_t d = (uint32_t)__cvta_generic_to_shared(dst);
    asm volatile("cp.async.cg.shared.global [%0], [%1], 16;" :: "r"(d), "l"(src));
}
#define CP_COMMIT() asm volatile("cp.async.commit_group;")
#define CP_WAIT0()  asm volatile("cp.async.wait_group 0;")

__device__ __forceinline__ unsigned long long pk2(float lo, float hi) {
    unsigned long long r;
    asm("mov.b64 %0, {%1, %2};" : "=l"(r) : "f"(lo), "f"(hi));
    return r;
}
__device__ __forceinline__ void upk2(float& lo, float& hi, unsigned long long v) {
    asm("mov.b64 {%0, %1}, %2;" : "=f"(lo), "=f"(hi) : "l"(v));
}
__device__ __forceinline__ unsigned long long fma2(
    unsigned long long a, unsigned long long b, unsigned long long c) {
    unsigned long long d;
    asm("fma.rn.f32x2 %0, %1, %2, %3;" : "=l"(d) : "l"(a), "l"(b), "l"(c));
    return d;
}

// ---------------- tf32 GEMM (operands pre-converted; no cvt in loop) ---------
// cvtout!=0: store tf32 bits; cvtout==0: store true fp32 (final output).
__global__ void __launch_bounds__(128, 3) k_gemm_tf32(
    const float* __restrict__ X, const float* __restrict__ W,
    const float* __restrict__ bias, float* __restrict__ Y, int cvtout)
{
    __shared__ __align__(16) float Wm[2][128][12];
    __shared__ __align__(16) float Xs[2][8][136];
    const int t  = threadIdx.x;
    const int s0 = blockIdx.x * 128;
    const int o0 = blockIdx.y * 128;
    const int b  = blockIdx.z;
    const int warp = t >> 5, lane = t & 31;
    const int gid = lane >> 2, tig = lane & 3;
    const int mrow = (warp >> 1) * 64;
    const int ncol = (warp & 1) * 64;
    const float* Xb = X + (size_t)b * NC * NHW;
    const int xr = t >> 4, xc = (t & 15) * 8;

    float c[4][8][4];
#pragma unroll
    for (int i = 0; i < 4; i++)
#pragma unroll
        for (int j = 0; j < 8; j++)
#pragma unroll
            for (int q = 0; q < 4; q++) c[i][j][q] = 0.f;

    cpa16(&Wm[0][t][0], &W[(o0 + t) * 256 + 0]);
    cpa16(&Wm[0][t][4], &W[(o0 + t) * 256 + 4]);
    cpa16(&Xs[0][xr][xc],     &Xb[(size_t)xr * NHW + s0 + xc]);
    cpa16(&Xs[0][xr][xc + 4], &Xb[(size_t)xr * NHW + s0 + xc + 4]);
    CP_COMMIT();

    for (int i = 0; i < 32; i++) {
        const int st = i & 1;
        CP_WAIT0();
        __syncthreads();
        if (i + 1 < 32) {
            const int kc = (i + 1) * 8, sn = st ^ 1;
            cpa16(&Wm[sn][t][0], &W[(o0 + t) * 256 + kc]);
            cpa16(&Wm[sn][t][4], &W[(o0 + t) * 256 + kc + 4]);
            cpa16(&Xs[sn][xr][xc],     &Xb[(size_t)(kc + xr) * NHW + s0 + xc]);
            cpa16(&Xs[sn][xr][xc + 4], &Xb[(size_t)(kc + xr) * NHW + s0 + xc + 4]);
        }
        CP_COMMIT();
        uint32_t afr[4][4], bfr[8][2];
#pragma unroll
        for (int mt = 0; mt < 4; mt++) {
            int m0 = mrow + mt * 16;
            afr[mt][0] = __float_as_uint(Wm[st][m0 + gid][tig]);
            afr[mt][1] = __float_as_uint(Wm[st][m0 + gid + 8][tig]);
            afr[mt][2] = __float_as_uint(Wm[st][m0 + gid][tig + 4]);
            afr[mt][3] = __float_as_uint(Wm[st][m0 + gid + 8][tig + 4]);
        }
#pragma unroll
        for (int nt = 0; nt < 8; nt++) {
            int n0 = ncol + nt * 8;
            bfr[nt][0] = __float_as_uint(Xs[st][tig][n0 + gid]);
            bfr[nt][1] = __float_as_uint(Xs[st][tig + 4][n0 + gid]);
        }
#pragma unroll
        for (int mt = 0; mt < 4; mt++)
#pragma unroll
            for (int nt = 0; nt < 8; nt++)
                mma_tf32(c[mt][nt], afr[mt], bfr[nt]);
    }

#pragma unroll
    for (int mt = 0; mt < 4; mt++) {
        int oa = o0 + mrow + mt * 16 + gid;
        int ob = oa + 8;
        float ba  = bias ? bias[oa] : 0.f;
        float bb_ = bias ? bias[ob] : 0.f;
        float* ya = Y + (size_t)(b * NC + oa) * NHW + s0;
        float* yb = Y + (size_t)(b * NC + ob) * NHW + s0;
#pragma unroll
        for (int nt = 0; nt < 8; nt++) {
            int sc = ncol + nt * 8 + tig * 2;
            float v0 = c[mt][nt][0] + ba,  v1 = c[mt][nt][1] + ba;
            float v2 = c[mt][nt][2] + bb_, v3 = c[mt][nt][3] + bb_;
            if (cvtout) { v0 = tfbits(v0); v1 = tfbits(v1); v2 = tfbits(v2); v3 = tfbits(v3); }
            *(float2*)&ya[sc] = make_float2(v0, v1);
            *(float2*)&yb[sc] = make_float2(v2, v3);
        }
    }
}

// ---------------- zero g_m ----------------------------------------------------
__global__ void k_zm() { g_m[blockIdx.x * 256 + threadIdx.x] = 0.f; }

// ---------------- pre-convert weights ----------------------------------------
__global__ void k_cvtw(const float* __restrict__ w3, const float* __restrict__ wo)
{
    int i = blockIdx.x * 256 + threadIdx.x;   // grid 256 -> 65536
    g_w3t[i] = tfbits(w3[i]);
    g_wot[i] = tfbits(wo[i]);
}

// ---------------- reversed copy + linear tf32 copy + fused channel sum -------
__global__ void __launch_bounds__(256) k_revx(const float* __restrict__ X)
{
    const int ch = blockIdx.x;
    const int seg = blockIdx.y;
    const float* src = X + (size_t)ch * NHW;
    float* dst = g_xrev + (size_t)ch * NHW;
    float* lin = g_xtf  + (size_t)ch * NHW;
    int s = seg * 1024 + threadIdx.x;
    float lsum = 0.f;
#pragma unroll
    for (int i = 0; i < 4; i++, s += 256) {
        int y = s / 96, x = s - y * 96;
        int ry = (y == 0) ? 0 : 96 - y;
        int rx = (x == 0) ? 0 : 96 - x;
        float v = src[ry * 96 + rx];
        float tv = tfbits(v);
        dst[s] = tv;
        lin[ry * 96 + rx] = tv;
        lsum += v;
    }
#pragma unroll
    for (int o = 16; o; o >>= 1) lsum += __shfl_xor_sync(0xffffffff, lsum, o);
    __shared__ float sb[8];
    int w = threadIdx.x >> 5;
    if ((threadIdx.x & 31) == 0) sb[w] = lsum;
    __syncthreads();
    if (threadIdx.x == 0) {
        float a = 0.f;
        for (int i = 0; i < 8; i++) a += sb[i];
        atomicAdd(&g_m[ch], a);
    }
}

// ---------------- Gram GEMM (pre-converted operands; no cvt in loop) ---------
__global__ void __launch_bounds__(128, 3) k_gram6(const float* __restrict__ X)
{
    const int sch = blockIdx.x, pr = blockIdx.y;
    const int b = blockIdx.z >> 1, mat = blockIdx.z & 1;
    const int ci = (pr == 2) ? 1 : 0;
    const int dj = (pr == 0) ? 0 : 1;
    __shared__ __align__(16) float Am[2][128][12];
    __shared__ __align__(16) float Dm[2][128][12];
    const float* Xa = X + (size_t)b * NC * NHW;
    const float* Xd = (mat ? g_xrev : X) + (size_t)b * NC * NHW;
    const int t = threadIdx.x;
    const int warp = t >> 5, lane = t & 31;
    const int gid = lane >> 2, tig = lane & 3;
    const int mrow = (warp >> 1) * 64;
    const int ncol = (warp & 1) * 64;
    const int base = sch * (NHW / KCH);
    const float* arow = &Xa[(size_t)(ci * 128 + t) * NHW + base];
    const float* drow = &Xd[(size_t)(dj * 128 + t) * NHW + base];

    float c[4][8][4];
#pragma unroll
    for (int i = 0; i < 4; i++)
#pragma unroll
        for (int j = 0; j < 8; j++)
#pragma unroll
            for (int q = 0; q < 4; q++) c[i][j][q] = 0.f;

    cpa16(&Am[0][t][0], &arow[0]);
    cpa16(&Am[0][t][4], &arow[4]);
    cpa16(&Dm[0][t][0], &drow[0]);
    cpa16(&Dm[0][t][4], &drow[4]);
    CP_COMMIT();

    const int NKS = NHW / (KCH * 8);   // 32
    for (int i = 0; i < NKS; i++) {
        const int st = i & 1;
        CP_WAIT0();
        __syncthreads();
        if (i + 1 < NKS) {
            const int ko = (i + 1) * 8, sn = st ^ 1;
            cpa16(&Am[sn][t][0], &arow[ko]);
            cpa16(&Am[sn][t][4], &arow[ko + 4]);
            cpa16(&Dm[sn][t][0], &drow[ko]);
            cpa16(&Dm[sn][t][4], &drow[ko + 4]);
        }
        CP_COMMIT();
        uint32_t afr[4][4], bfr[8][2];
#pragma unroll
        for (int mt = 0; mt < 4; mt++) {
            int m0 = mrow + mt * 16;
            afr[mt][0] = __float_as_uint(Am[st][m0 + gid][tig]);
            afr[mt][1] = __float_as_uint(Am[st][m0 + gid + 8][tig]);
            afr[mt][2] = __float_as_uint(Am[st][m0 + gid][tig + 4]);
            afr[mt][3] = __float_as_uint(Am[st][m0 + gid + 8][tig + 4]);
        }
#pragma unroll
        for (int nt = 0; nt < 8; nt++) {
            int n0 = ncol + nt * 8;
            bfr[nt][0] = __float_as_uint(Dm[st][n0 + gid][tig]);
            bfr[nt][1] = __float_as_uint(Dm[st][n0 + gid][tig + 4]);
        }
#pragma unroll
        for (int mt = 0; mt < 4; mt++)
#pragma unroll
            for (int nt = 0; nt < 8; nt++)
                mma_tf32(c[mt][nt], afr[mt], bfr[nt]);
    }

    float* Out = g_gp + ((size_t)(blockIdx.z * 3 + pr) * KCH + sch) * 16384;
#pragma unroll
    for (int mt = 0; mt < 4; mt++) {
        int ra = mrow + mt * 16 + gid;
        int rb = ra + 8;
#pragma unroll
        for (int nt = 0; nt < 8; nt++) {
            int col = ncol + nt * 8 + tig * 2;
            *(float2*)&Out[ra * 128 + col] = make_float2(c[mt][nt][0], c[mt][nt][1]);
            *(float2*)&Out[rb * 128 + col] = make_float2(c[mt][nt][2], c[mt][nt][3]);
        }
    }
}

// ---------------- reduce partials into S / M --------------------------------
__global__ void __launch_bounds__(256) k_gred()
{
    const int pr = blockIdx.y, bm = blockIdx.z;
    const int b = bm >> 1, mat = bm & 1;
    const int ci = (pr == 2) ? 1 : 0;
    const int dj = (pr == 0) ? 0 : 1;
    const int off = blockIdx.x * 256 + threadIdx.x;
    const float* Pp = g_gp + (size_t)(bm * 3 + pr) * KCH * 16384 + off;
    float s = 0.f;
#pragma unroll
    for (int c = 0; c < KCH; c++) s += Pp[c * 16384];
    int il = off >> 7, jl = off & 127;
    float* Out = (mat ? g_M : g_S) + b * 65536;
    Out[(ci * 128 + il) * 256 + dj * 128 + jl] = s;
}

// ---------------- mirror lower-left 128x128 block ---------------------------
__global__ void k_mirror()
{
    const int bm = blockIdx.y;
    float* Out = (bm & 1 ? g_M : g_S) + (bm >> 1) * 65536;
    int idx = blockIdx.x * 256 + threadIdx.x;
    int i = idx >> 7, jl = idx & 127;
    Out[(128 + jl) * 256 + i] = Out[i * 256 + 128 + jl];
}

// ---------------- P[b] = M[b] * W2^T ----------------------------------------
__global__ void __launch_bounds__(256) k_mmA(const float* __restrict__ Wg)
{
    const int j0 = blockIdx.x * 64, i0 = blockIdx.y * 64, b = blockIdx.z;
    const float* A = g_M + b * 65536;
    float* C = g_P + b * 65536;
    __shared__ float As[16][68];
    __shared__ float Bs[16][68];
    const int t = threadIdx.x;
    const int it = (t >> 4) * 4, jt = (t & 15) * 4;
    float acc[4][4];
#pragma unroll
    for (int i = 0; i < 4; i++)
#pragma unroll
        for (int j = 0; j < 4; j++) acc[i][j] = 0.f;
    for (int kc = 0; kc < 256; kc += 16) {
        __syncthreads();
#pragma unroll
        for (int i = 0; i < 4; i++) {
            int idx = i * 256 + t;
            int r = idx >> 4, kk = idx & 15;
            As[kk][r] = A[(i0 + r) * 256 + kc + kk];
            Bs[kk][r] = Wg[(j0 + r) * 256 + kc + kk];
        }
        __syncthreads();
#pragma unroll
        for (int kk = 0; kk < 16; kk++) {
            float a[4], bb[4];
            *(float4*)a  = *(float4*)&As[kk][it];
            *(float4*)bb = *(float4*)&Bs[kk][jt];
#pragma unroll
            for (int i = 0; i < 4; i++)
#pragma unroll
                for (int j = 0; j < 4; j++) acc[i][j] += a[i] * bb[j];
        }
    }
#pragma unroll
    for (int i = 0; i < 4; i++)
#pragma unroll
        for (int j = 0; j < 4; j++)
            C[(i0 + it + i) * 256 + j0 + jt + j] = acc[i][j];
}

// ---------------- C[b] = Ag * B[b]  (generic, used for Gf) -------------------
__global__ void __launch_bounds__(256) k_mmB(
    const float* __restrict__ Ag, const float* __restrict__ Bb, float* __restrict__ Cb)
{
    const int j0 = blockIdx.x * 64, i0 = blockIdx.y * 64, b = blockIdx.z;
    const float* B = Bb + b * 65536;
    float* C = Cb + b * 65536;
    __shared__ float As[16][68];
    __shared__ float Bs[16][68];
    const int t = threadIdx.x;
    const int it = (t >> 4) * 4, jt = (t & 15) * 4;
    float acc[4][4];
#pragma unroll
    for (int i = 0; i < 4; i++)
#pragma unroll
        for (int j = 0; j < 4; j++) acc[i][j] = 0.f;
    for (int kc = 0; kc < 256; kc += 16) {
        __syncthreads();
#pragma unroll
        for (int i = 0; i < 4; i++) {
            int idx = i * 256 + t;
            int r = idx >> 4, kk = idx & 15;
            As[kk][r] = Ag[(i0 + r) * 256 + kc + kk];
        }
#pragma unroll
        for (int i = 0; i < 4; i++) {
            int idx = i * 256 + t;
            int kk = idx >> 6, j = idx & 63;
            Bs[kk][j] = B[(kc + kk) * 256 + j0 + j];
        }
        __syncthreads();
#pragma unroll
        for (int kk = 0; kk < 16; kk++) {
            float a[4], bb[4];
            *(float4*)a  = *(float4*)&As[kk][it];
            *(float4*)bb = *(float4*)&Bs[kk][jt];
#pragma unroll
            for (int i = 0; i < 4; i++)
#pragma unroll
                for (int j = 0; j < 4; j++) acc[i][j] += a[i] * bb[j];
        }
    }
#pragma unroll
    for (int i = 0; i < 4; i++)
#pragma unroll
        for (int j = 0; j < 4; j++)
            C[(i0 + it + i) * 256 + j0 + jt + j] = acc[i][j];
}

// ---------------- batched U = W{1,2} * S  (z = b*2 + which) ------------------
__global__ void __launch_bounds__(256) k_mmU(
    const float* __restrict__ W1, const float* __restrict__ W2)
{
    const int j0 = blockIdx.x * 64, i0 = blockIdx.y * 64;
    const int b = blockIdx.z >> 1, which = blockIdx.z & 1;
    const float* Ag = which ? W2 : W1;
    const float* B = g_S + b * 65536;
    float* C = (which ? g_gp : g_P) + b * 65536;
    __shared__ float As[16][68];
    __shared__ float Bs[16][68];
    const int t = threadIdx.x;
    const int it = (t >> 4) * 4, jt = (t & 15) * 4;
    float acc[4][4];
#pragma unroll
    for (int i = 0; i < 4; i++)
#pragma unroll
        for (int j = 0; j < 4; j++) acc[i][j] = 0.f;
    for (int kc = 0; kc < 256; kc += 16) {
        __syncthreads();
#pragma unroll
        for (int i = 0; i < 4; i++) {
            int idx = i * 256 + t;
            int r = idx >> 4, kk = idx & 15;
            As[kk][r] = Ag[(i0 + r) * 256 + kc + kk];
        }
#pragma unroll
        for (int i = 0; i < 4; i++) {
            int idx = i * 256 + t;
            int kk = idx >> 6, j = idx & 63;
            Bs[kk][j] = B[(kc + kk) * 256 + j0 + j];
        }
        __syncthreads();
#pragma unroll
        for (int kk = 0; kk < 16; kk++) {
            float a[4], bb[4];
            *(float4*)a  = *(float4*)&As[kk][it];
            *(float4*)bb = *(float4*)&Bs[kk][jt];
#pragma unroll
            for (int i = 0; i < 4; i++)
#pragma unroll
                for (int j = 0; j < 4; j++) acc[i][j] += a[i] * bb[j];
        }
    }
#pragma unroll
    for (int i = 0; i < 4; i++)
#pragma unroll
        for (int j = 0; j < 4; j++)
            C[(i0 + it + i) * 256 + j0 + jt + j] = acc[i][j];
}

// ---------------- batched row-dot: norms + W*m (y = which) -------------------
__global__ void __launch_bounds__(256) k_rowdot2(
    const float* __restrict__ W1, const float* __restrict__ W2,
    const float* __restrict__ b1, const float* __restrict__ b2)
{
    const int bC = blockIdx.x;
    const int which = blockIdx.y;
    const int b = bC >> 8, C = bC & 255;
    const float* U = (which ? g_gp : g_P);
    const float* W = which ? W2 : W1;
    const float* bias = which ? b2 : b1;
    const int t = threadIdx.x;
    float wv = W[C * 256 + t];
    float un = U[(size_t)b * 65536 + C * 256 + t] * wv;
    float wm = wv * g_m[b * 256 + t];
#pragma unroll
    for (int o = 16; o; o >>= 1) {
        un += __shfl_xor_sync(0xffffffff, un, o);
        wm += __shfl_xor_sync(0xffffffff, wm, o);
    }
    __shared__ float s1[8], s2[8];
    int w = t >> 5;
    if ((t & 31) == 0) { s1[w] = un; s2[w] = wm; }
    __syncthreads();
    if (t == 0) {
        float a = 0.f, c = 0.f;
        for (int i = 0; i < 8; i++) { a += s1[i]; c += s2[i]; }
        float bc = bias[C];
        float nf = a + 2.f * bc * c + 9216.f * bc * bc;
        if (which) { g_nk[bC] = nf; g_w2m[bC] = c; }
        else       { g_nq[bC] = nf; g_w1m[bC] = c; }
    }
}

// ---------------- attn: logits, softmax, build Chat -------------------------
__global__ void __launch_bounds__(256) k_attn2(
    const float* __restrict__ b1, const float* __restrict__ b2,
    const float* __restrict__ temperature)
{
    const int bh = blockIdx.x;
    const int b = bh >> 3, h = bh & 7;
    const int ch0 = h * 32;
    __shared__ float A[32][33];
    __shared__ float rq[32], rk[32], sw1m[32], sw2m[32], sb1[32], sb2[32];
    __shared__ float2 tab[32];
    const int t = threadIdx.x;
    if (t < 32) {
        int C = b * 256 + ch0 + t;
        rq[t] = rsqrtf(g_nq[C]);
        rk[t] = rsqrtf(g_nk[C]);
        sw1m[t] = g_w1m[C];
        sw2m[t] = g_w2m[C];
        sb1[t] = b1[ch0 + t];
        sb2[t] = b2[ch0 + t];
        float ang = 6.283185307179586f * (float)t / 32.0f;
        tab[t] = make_float2(cosf(ang), sinf(ang));
    }
    __syncthreads();
    const float ts = temperature[h];
    const int w = t >> 5, lane = t & 31;
    for (int r = w; r < 32; r += 8) {
        float Gv = g_Gf[(size_t)b * 65536 + (ch0 + r) * 256 + ch0 + lane];
        float L = (Gv + sw1m[r] * sb2[lane] + sb1[r] * sw2m[lane]
                   + 9216.f * sb1[r] * sb2[lane]) * rq[r] * rk[lane] * ts;
        float m = L;
#pragma unroll
        for (int o = 16; o; o >>= 1) m = fmaxf(m, __shfl_xor_sync(0xffffffff, m, o));
        float e = expf(L - m);
        float s = e;
#pragma unroll
        for (int o = 16; o; o >>= 1) s += __shfl_xor_sync(0xffffffff, s, o);
        A[r][lane] = e / s;
    }
    __syncthreads();
    for (int idx = t; idx < 1024; idx += 256) {
        int e = idx >> 5, d = idx & 31;
        float re = 0.f, im = 0.f;
#pragma unroll 8
        for (int c = 0; c < 32; c++) {
            float a = A[c][d];
            float2 tb = tab[(c * e) & 31];
            re += a * tb.x; im += a * tb.y;
        }
        re *= (1.0f / 32.0f); im *= (1.0f / 32.0f);
        if (e == 0) im += (1.0f / 32.0f);
        g_Chat[bh * 1024 + idx] = make_float2(re, im);
    }
}

// ---------------- circulant tables (tf32 bits out) ---------------------------
__global__ void k_gtab2()
{
    int idx = blockIdx.x * 256 + threadIdx.x;
    int r = idx / 9216;
    int rem = idx - r * 9216;
    int w = rem / 96, a = rem - w * 96;
    int tt = a - w; if (tt < 0) tt += 96;
    float2 g;
    if (r == 0) {
        g = make_float2(tt == 0 ? 1.f : 0.f, 0.f);
    } else {
        const float PI = 3.14159265358979323846f;
        float h1 = PI * (float)r / 96.0f;
        float h2 = PI * (96.0f * (float)tt + (float)r) / 9216.0f;
        float rr = sinf(h1) / (96.0f * sinf(h2));
        float psi = h1 - h2;
        g = make_float2(rr * cosf(psi), rr * sinf(psi));
    }
    g_gcre[idx] = tfbits(g.x);
    g_gcim[idx] = tfbits(g.y);
}

// ---------------- conv as batched tf32 GEMM (pre-converted; no cvt) ----------
__global__ void __launch_bounds__(128) k_vconv()
{
    const int r = blockIdx.x;
    const int ch0 = blockIdx.y * 64;
    __shared__ __align__(16) uint32_t As[2][8][72];
    __shared__ __align__(16) uint32_t Br[2][8][104];
    __shared__ __align__(16) uint32_t Bi[2][8][104];
    const int t = threadIdx.x;
    const int warp = t >> 5, lane = t & 31;
    const int gid = lane >> 2, tig = lane & 3;
    const int mrow = (warp >> 1) * 32;
    const int ncol = (warp & 1) * 48;
    const int ach = t >> 1, aw4 = (t & 1) * 4;
    const int bw = t >> 4, ba0 = (t & 15) * 6;

    float cre[2][6][4], cim[2][6][4];
#pragma unroll
    for (int i = 0; i < 2; i++)
#pragma unroll
        for (int j = 0; j < 6; j++)
#pragma unroll
            for (int q = 0; q < 4; q++) { cre[i][j][q] = 0.f; cim[i][j][q] = 0.f; }

    float4 av;
    float br[6], bi[6];
    av = *(const float4*)&g_v[(size_t)(ch0 + ach) * NHW + r * 96 + aw4];
    {
        const float* pr_ = &g_gcre[(size_t)r * 9216 + bw * 96 + ba0];
        const float* pi_ = &g_gcim[(size_t)r * 9216 + bw * 96 + ba0];
#pragma unroll
        for (int i = 0; i < 6; i++) { br[i] = pr_[i]; bi[i] = pi_[i]; }
    }

    for (int ks = 0; ks < 12; ks++) {
        const int st = ks & 1;
        As[st][aw4 + 0][ach] = __float_as_uint(av.x);
        As[st][aw4 + 1][ach] = __float_as_uint(av.y);
        As[st][aw4 + 2][ach] = __float_as_uint(av.z);
        As[st][aw4 + 3][ach] = __float_as_uint(av.w);
#pragma unroll
        for (int i = 0; i < 6; i++) {
            Br[st][bw][ba0 + i] = __float_as_uint(br[i]);
            Bi[st][bw][ba0 + i] = __float_as_uint(bi[i]);
        }
        __syncthreads();

        int w0n = (ks + 1 < 12) ? (ks + 1) * 8 : 0;
        av = *(const float4*)&g_v[(size_t)(ch0 + ach) * NHW + r * 96 + w0n + aw4];
        {
            const float* pr_ = &g_gcre[(size_t)r * 9216 + (w0n + bw) * 96 + ba0];
            const float* pi_ = &g_gcim[(size_t)r * 9216 + (w0n + bw) * 96 + ba0];
#pragma unroll
            for (int i = 0; i < 6; i++) { br[i] = pr_[i]; bi[i] = pi_[i]; }
        }

        uint32_t afr[2][4], bre[6][2], bim[6][2];
#pragma unroll
        for (int mt = 0; mt < 2; mt++) {
            int m0 = mrow + mt * 16;
            afr[mt][0] = As[st][tig][m0 + gid];
            afr[mt][1] = As[st][tig][m0 + gid + 8];
            afr[mt][2] = As[st][tig + 4][m0 + gid];
            afr[mt][3] = As[st][tig + 4][m0 + gid + 8];
        }
#pragma unroll
        for (int nt = 0; nt < 6; nt++) {
            int n0 = ncol + nt * 8;
            bre[nt][0] = Br[st][tig][n0 + gid];
            bre[nt][1] = Br[st][tig + 4][n0 + gid];
            bim[nt][0] = Bi[st][tig][n0 + gid];
            bim[nt][1] = Bi[st][tig + 4][n0 + gid];
        }
#pragma unroll
        for (int mt = 0; mt < 2; mt++)
#pragma unroll
            for (int nt = 0; nt < 6; nt++) {
                mma_tf32(cre[mt][nt], afr[mt], bre[nt]);
                mma_tf32(cim[mt][nt], afr[mt], bim[nt]);
            }
    }

#pragma unroll
    for (int mt = 0; mt < 2; mt++) {
        int r0 = ch0 + mrow + mt * 16 + gid;
        int r1 = r0 + 8;
        float2* p0 = &g_Tt[(size_t)r0 * NHW + r * 96];
        float2* p1 = &g_Tt[(size_t)r1 * NHW + r * 96];
#pragma unroll
        for (int nt = 0; nt < 6; nt++) {
            int a = ncol + nt * 8 + tig * 2;
            p0[a]     = make_float2(cre[mt][nt][0], cim[mt][nt][0]);
            p0[a + 1] = make_float2(cre[mt][nt][1], cim[mt][nt][1]);
            p1[a]     = make_float2(cre[mt][nt][2], cim[mt][nt][2]);
            p1[a + 1] = make_float2(cre[mt][nt][3], cim[mt][nt][3]);
        }
    }
}

// ---------------- mix + fused transpose, packed f32x2; tf32-bit output -------
__global__ void __launch_bounds__(256) k_mix2()
{
    const int rt = blockIdx.x % 3;
    const int at = blockIdx.x / 3;
    const int bh = blockIdx.y;
    __shared__ float2 Ch[1024];
    __shared__ float2 Ts[32][128];
    const int t = threadIdx.x;
    for (int i = t; i < 1024; i += 256) Ch[i] = g_Chat[bh * 1024 + i];
    for (int i = t; i < 1024; i += 256) {
        int d = i >> 5, rl = i & 31;
        const float2* src = &g_Tt[(size_t)(bh * 32 + d) * NHW + (rt * 32 + rl) * 96 + at * 4];
        *(float4*)&Ts[d][rl * 4]     = *(const float4*)src;
        *(float4*)&Ts[d][rl * 4 + 2] = *(const float4*)(src + 2);
    }
    __syncthreads();
    const int sl = t & 63, eg = t >> 6;
    const unsigned long long SGN = 0x8000000080000000ULL;

    unsigned long long ar0p[4], ai0p[4], ar1p[4], ai1p[4];
#pragma unroll
    for (int j = 0; j < 4; j++) { ar0p[j] = ai0p[j] = ar1p[j] = ai1p[j] = 0ULL; }

    for (int d = 0; d < 32; d++) {
        float2 t0 = Ts[d][sl];
        float2 t1 = Ts[d][sl + 64];
        unsigned long long t0x = pk2(t0.x, t0.x), t0y = pk2(t0.y, t0.y);
        unsigned long long t1x = pk2(t1.x, t1.x), t1y = pk2(t1.y, t1.y);
#pragma unroll
        for (int j = 0; j < 4; j++) {
            float2 cA = Ch[(eg * 8 + 2 * j) * 32 + d];
            float2 cB = Ch[(eg * 8 + 2 * j + 1) * 32 + d];
            unsigned long long cx  = pk2(cA.x, cB.x);
            unsigned long long cy  = pk2(cA.y, cB.y);
            unsigned long long cyn = cy ^ SGN;
            ar0p[j] = fma2(cx,  t0x, ar0p[j]);
            ar0p[j] = fma2(cyn, t0y, ar0p[j]);
            ai0p[j] = fma2(cx,  t0y, ai0p[j]);
            ai0p[j] = fma2(cy,  t0x, ai0p[j]);
            ar1p[j] = fma2(cx,  t1x, ar1p[j]);
            ar1p[j] = fma2(cyn, t1y, ar1p[j]);
            ai1p[j] = fma2(cx,  t1y, ai1p[j]);
            ai1p[j] = fma2(cy,  t1x, ai1p[j]);
        }
    }

    const int al0 = sl & 3,        rl0 = sl >> 2;
    const int al1 = (sl + 64) & 3, rl1 = (sl + 64) >> 2;
#pragma unroll
    for (int j = 0; j < 4; j++) {
        float a0, a1, b0, b1, c0, c1, d0, d1;
        upk2(a0, a1, ar0p[j]);
        upk2(b0, b1, ai0p[j]);
        upk2(c0, c1, ar1p[j]);
        upk2(d0, d1, ai1p[j]);
        int row0 = bh * 32 + eg * 8 + 2 * j;
        int row1 = row0 + 1;
        g_R[(size_t)row0 * NHW + (at * 4 + al0) * 96 + rt * 32 + rl0] = tfbits(sqrtf(a0 * a0 + b0 * b0));
        g_R[(size_t)row1 * NHW + (at * 4 + al0) * 96 + rt * 32 + rl0] = tfbits(sqrtf(a1 * a1 + b1 * b1));
        g_R[(size_t)row0 * NHW + (at * 4 + al1) * 96 + rt * 32 + rl1] = tfbits(sqrtf(c0 * c0 + d0 * d0));
        g_R[(size_t)row1 * NHW + (at * 4 + al1) * 96 + rt * 32 + rl1] = tfbits(sqrtf(c1 * c1 + d1 * d1));
    }
}

// ---------------- launch ----------------
extern "C" void kernel_launch(void* const* d_in, const int* in_sizes, int n_in,
                              void* d_out, int out_size)
{
    const float* x    = (const float*)d_in[0];
    const float* w1   = (const float*)d_in[1];
    const float* b1   = (const float*)d_in[2];
    const float* w2   = (const float*)d_in[3];
    const float* b2   = (const float*)d_in[4];
    const float* w3   = (const float*)d_in[5];
    const float* b3   = (const float*)d_in[6];
    const float* wo   = (const float*)d_in[7];
    const float* temp = (const float*)d_in[8];
    float* out = (float*)d_out;

    float *vp = nullptr, *Rp = nullptr, *Pp = nullptr, *Gfp = nullptr;
    float *xtfp = nullptr, *w3tp = nullptr, *wotp = nullptr;
    cudaGetSymbolAddress((void**)&vp,   g_v);
    cudaGetSymbolAddress((void**)&Rp,   g_R);
    cudaGetSymbolAddress((void**)&Pp,   g_P);
    cudaGetSymbolAddress((void**)&Gfp,  g_Gf);
    cudaGetSymbolAddress((void**)&xtfp, g_xtf);
    cudaGetSymbolAddress((void**)&w3tp, g_w3t);
    cudaGetSymbolAddress((void**)&wotp, g_wot);

    dim3 gg(72, 2, 8);
    dim3 gm(4, 4, 8);

    k_zm     <<<8, 256>>>();
    k_revx   <<<dim3(2048, 9), 256>>>(x);               // xrev(tf32) + xtf(tf32) + m
    k_cvtw   <<<256, 256>>>(w3, wo);
    k_gemm_tf32<<<gg, 128>>>(xtfp, w3tp, b3, vp, 1);    // v (tf32 bits out)
    k_gram6  <<<dim3(KCH, 3, 16), 128>>>(xtfp);         // partial tiles
    k_gred   <<<dim3(64, 3, 16), 256>>>();              // -> S, M
    k_mirror <<<dim3(64, 16), 256>>>();
    k_mmA    <<<gm, 256>>>(w2);                         // P = M * W2^T
    k_mmB    <<<gm, 256>>>(w1, Pp, Gfp);                // Gf = W1 * P
    k_mmU    <<<dim3(4, 4, 16), 256>>>(w1, w2);         // U1 -> g_P, U2 -> g_gp
    k_rowdot2<<<dim3(2048, 2), 256>>>(w1, w2, b1, b2);
    k_gtab2  <<<3456, 256>>>();
    k_attn2  <<<64, 256>>>(b1, b2, temp);
    k_vconv  <<<dim3(96, 32), 128>>>();                 // conv via tensor cores
    k_mix2   <<<dim3(72, 64), 256>>>();                 // mix + transpose -> R (tf32 bits)
    k_gemm_tf32<<<gg, 128>>>(Rp, wotp, nullptr, out, 0);
}

// round 15
// speedup vs baseline: 2.9291x; 1.0359x over previous
#include <cuda_runtime.h>
#include <math.h>
#include <stdint.h>

#define NB 8
#define NC 256
#define NHW 9216
#define NHEAD 8
#define KCH 36            // gram split-K chunks

// ---------------- scratch (device globals; no allocation anywhere) ----------
__device__ float  g_v[NB*NC*NHW];         // tf32 bits (v-GEMM output)
__device__ float  g_xrev[NB*NC*NHW];      // tf32 bits, spatially reversed x
__device__ float  g_xtf[NB*NC*NHW];       // tf32 bits, linear x
__device__ float  g_gp[KCH*3*16*128*128]; // gram partials; first 2MB reused as U2
__device__ float  g_S[NB*256*256];
__device__ float  g_M[NB*256*256];
__device__ float  g_P[NB*256*256];
__device__ float  g_Gf[NB*256*256];
__device__ float  g_w3t[256*256], g_wot[256*256];   // tf32 bits weights
__device__ float  g_m[NB*256];
__device__ float  g_nq[NB*256], g_nk[NB*256];
__device__ float  g_w1m[NB*256], g_w2m[NB*256];
__device__ float2 g_Chat[64*1024];
__device__ float  g_gcre[96*96*96];       // tf32 bits conv tables
__device__ float  g_gcim[96*96*96];
__device__ float2 g_Tt[NB*NC*NHW];        // [ch][r][a]
__device__ float  g_R [NB*NC*NHW];        // tf32 bits (mix output)

// ---------------- helpers -----------------------------------------------------
__device__ __forceinline__ uint32_t f2tf32(float x) {
    uint32_t r;
    asm("cvt.rna.tf32.f32 %0, %1;" : "=r"(r) : "f"(x));
    return r;
}
__device__ __forceinline__ float tfbits(float x) { return __uint_as_float(f2tf32(x)); }
__device__ __forceinline__ void mma_tf32(float* c, const uint32_t* a, const uint32_t* b) {
    asm volatile(
        "mma.sync.aligned.m16n8k8.row.col.f32.tf32.tf32.f32 "
        "{%0,%1,%2,%3}, {%4,%5,%6,%7}, {%8,%9}, {%0,%1,%2,%3};"
        : "+f"(c[0]), "+f"(c[1]), "+f"(c[2]), "+f"(c[3])
        : "r"(a[0]), "r"(a[1]), "r"(a[2]), "r"(a[3]), "r"(b[0]), "r"(b[1]));
}
__device__ __forceinline__ void cpa16(void* dst, const void* src) {
    uint32_t d = (uint32_t)__cvta_generic_to_shared(dst);
    asm volatile("cp.async.cg.shared.global [%0], [%1], 16;" :: "r"(d), "l"(src));
}
#define CP_COMMIT() asm volatile("cp.async.commit_group;")
#define CP_WAIT1()  asm volatile("cp.async.wait_group 1;")
#define CP_WAIT0()  asm volatile("cp.async.wait_group 0;")

__device__ __forceinline__ unsigned long long pk2(float lo, float hi) {
    unsigned long long r;
    asm("mov.b64 %0, {%1, %2};" : "=l"(r) : "f"(lo), "f"(hi));
    return r;
}
__device__ __forceinline__ void upk2(float& lo, float& hi, unsigned long long v) {
    asm("mov.b64 {%0, %1}, %2;" : "=f"(lo), "=f"(hi) : "l"(v));
}
__device__ __forceinline__ unsigned long long fma2(
    unsigned long long a, unsigned long long b, unsigned long long c) {
    unsigned long long d;
    asm("fma.rn.f32x2 %0, %1, %2, %3;" : "=l"(d) : "l"(a), "l"(b), "l"(c));
    return d;
}

// ---------------- tf32 GEMM (3-stage cp.async pipeline) ----------------------
// cvtout!=0: store tf32 bits; cvtout==0: store true fp32 (final output).
__global__ void __launch_bounds__(128, 3) k_gemm_tf32(
    const float* __restrict__ X, const float* __restrict__ W,
    const float* __restrict__ bias, float* __restrict__ Y, int cvtout)
{
    __shared__ __align__(16) float Wm[3][128][12];
    __shared__ __align__(16) float Xs[3][8][136];
    const int t  = threadIdx.x;
    const int s0 = blockIdx.x * 128;
    const int o0 = blockIdx.y * 128;
    const int b  = blockIdx.z;
    const int warp = t >> 5, lane = t & 31;
    const int gid = lane >> 2, tig = lane & 3;
    const int mrow = (warp >> 1) * 64;
    const int ncol = (warp & 1) * 64;
    const float* Xb = X + (size_t)b * NC * NHW;
    const int xr = t >> 4, xc = (t & 15) * 8;

    float c[4][8][4];
#pragma unroll
    for (int i = 0; i < 4; i++)
#pragma unroll
        for (int j = 0; j < 8; j++)
#pragma unroll
            for (int q = 0; q < 4; q++) c[i][j][q] = 0.f;

    // prologue: stages 0 and 1
#pragma unroll
    for (int p = 0; p < 2; p++) {
        const int kc = p * 8;
        cpa16(&Wm[p][t][0], &W[(o0 + t) * 256 + kc]);
        cpa16(&Wm[p][t][4], &W[(o0 + t) * 256 + kc + 4]);
        cpa16(&Xs[p][xr][xc],     &Xb[(size_t)(kc + xr) * NHW + s0 + xc]);
        cpa16(&Xs[p][xr][xc + 4], &Xb[(size_t)(kc + xr) * NHW + s0 + xc + 4]);
        CP_COMMIT();
    }

    int st = 0, sf = 2;
    for (int i = 0; i < 32; i++) {
        CP_WAIT1();
        __syncthreads();
        if (i + 2 < 32) {
            const int kc = (i + 2) * 8;
            cpa16(&Wm[sf][t][0], &W[(o0 + t) * 256 + kc]);
            cpa16(&Wm[sf][t][4], &W[(o0 + t) * 256 + kc + 4]);
            cpa16(&Xs[sf][xr][xc],     &Xb[(size_t)(kc + xr) * NHW + s0 + xc]);
            cpa16(&Xs[sf][xr][xc + 4], &Xb[(size_t)(kc + xr) * NHW + s0 + xc + 4]);
        }
        CP_COMMIT();
        uint32_t afr[4][4], bfr[8][2];
#pragma unroll
        for (int mt = 0; mt < 4; mt++) {
            int m0 = mrow + mt * 16;
            afr[mt][0] = __float_as_uint(Wm[st][m0 + gid][tig]);
            afr[mt][1] = __float_as_uint(Wm[st][m0 + gid + 8][tig]);
            afr[mt][2] = __float_as_uint(Wm[st][m0 + gid][tig + 4]);
            afr[mt][3] = __float_as_uint(Wm[st][m0 + gid + 8][tig + 4]);
        }
#pragma unroll
        for (int nt = 0; nt < 8; nt++) {
            int n0 = ncol + nt * 8;
            bfr[nt][0] = __float_as_uint(Xs[st][tig][n0 + gid]);
            bfr[nt][1] = __float_as_uint(Xs[st][tig + 4][n0 + gid]);
        }
#pragma unroll
        for (int mt = 0; mt < 4; mt++)
#pragma unroll
            for (int nt = 0; nt < 8; nt++)
                mma_tf32(c[mt][nt], afr[mt], bfr[nt]);
        st = (st == 2) ? 0 : st + 1;
        sf = (sf == 2) ? 0 : sf + 1;
    }

#pragma unroll
    for (int mt = 0; mt < 4; mt++) {
        int oa = o0 + mrow + mt * 16 + gid;
        int ob = oa + 8;
        float ba  = bias ? bias[oa] : 0.f;
        float bb_ = bias ? bias[ob] : 0.f;
        float* ya = Y + (size_t)(b * NC + oa) * NHW + s0;
        float* yb = Y + (size_t)(b * NC + ob) * NHW + s0;
#pragma unroll
        for (int nt = 0; nt < 8; nt++) {
            int sc = ncol + nt * 8 + tig * 2;
            float v0 = c[mt][nt][0] + ba,  v1 = c[mt][nt][1] + ba;
            float v2 = c[mt][nt][2] + bb_, v3 = c[mt][nt][3] + bb_;
            if (cvtout) { v0 = tfbits(v0); v1 = tfbits(v1); v2 = tfbits(v2); v3 = tfbits(v3); }
            *(float2*)&ya[sc] = make_float2(v0, v1);
            *(float2*)&yb[sc] = make_float2(v2, v3);
        }
    }
}

// ---------------- zero g_m ----------------------------------------------------
__global__ void k_zm() { g_m[blockIdx.x * 256 + threadIdx.x] = 0.f; }

// ---------------- pre-convert weights ----------------------------------------
__global__ void k_cvtw(const float* __restrict__ w3, const float* __restrict__ wo)
{
    int i = blockIdx.x * 256 + threadIdx.x;
    g_w3t[i] = tfbits(w3[i]);
    g_wot[i] = tfbits(wo[i]);
}

// ---------------- reversed copy + linear tf32 copy + fused channel sum -------
__global__ void __launch_bounds__(256) k_revx(const float* __restrict__ X)
{
    const int ch = blockIdx.x;
    const int seg = blockIdx.y;
    const float* src = X + (size_t)ch * NHW;
    float* dst = g_xrev + (size_t)ch * NHW;
    float* lin = g_xtf  + (size_t)ch * NHW;
    int s = seg * 1024 + threadIdx.x;
    float lsum = 0.f;
#pragma unroll
    for (int i = 0; i < 4; i++, s += 256) {
        int y = s / 96, x = s - y * 96;
        int ry = (y == 0) ? 0 : 96 - y;
        int rx = (x == 0) ? 0 : 96 - x;
        float v = src[ry * 96 + rx];
        float tv = tfbits(v);
        dst[s] = tv;
        lin[ry * 96 + rx] = tv;
        lsum += v;
    }
#pragma unroll
    for (int o = 16; o; o >>= 1) lsum += __shfl_xor_sync(0xffffffff, lsum, o);
    __shared__ float sb[8];
    int w = threadIdx.x >> 5;
    if ((threadIdx.x & 31) == 0) sb[w] = lsum;
    __syncthreads();
    if (threadIdx.x == 0) {
        float a = 0.f;
        for (int i = 0; i < 8; i++) a += sb[i];
        atomicAdd(&g_m[ch], a);
    }
}

// ---------------- Gram GEMM (3-stage cp.async pipeline) ----------------------
__global__ void __launch_bounds__(128, 3) k_gram6(const float* __restrict__ X)
{
    const int sch = blockIdx.x, pr = blockIdx.y;
    const int b = blockIdx.z >> 1, mat = blockIdx.z & 1;
    const int ci = (pr == 2) ? 1 : 0;
    const int dj = (pr == 0) ? 0 : 1;
    __shared__ __align__(16) float Am[3][128][12];
    __shared__ __align__(16) float Dm[3][128][12];
    const float* Xa = X + (size_t)b * NC * NHW;
    const float* Xd = (mat ? g_xrev : X) + (size_t)b * NC * NHW;
    const int t = threadIdx.x;
    const int warp = t >> 5, lane = t & 31;
    const int gid = lane >> 2, tig = lane & 3;
    const int mrow = (warp >> 1) * 64;
    const int ncol = (warp & 1) * 64;
    const int base = sch * (NHW / KCH);
    const float* arow = &Xa[(size_t)(ci * 128 + t) * NHW + base];
    const float* drow = &Xd[(size_t)(dj * 128 + t) * NHW + base];

    float c[4][8][4];
#pragma unroll
    for (int i = 0; i < 4; i++)
#pragma unroll
        for (int j = 0; j < 8; j++)
#pragma unroll
            for (int q = 0; q < 4; q++) c[i][j][q] = 0.f;

#pragma unroll
    for (int p = 0; p < 2; p++) {
        const int ko = p * 8;
        cpa16(&Am[p][t][0], &arow[ko]);
        cpa16(&Am[p][t][4], &arow[ko + 4]);
        cpa16(&Dm[p][t][0], &drow[ko]);
        cpa16(&Dm[p][t][4], &drow[ko + 4]);
        CP_COMMIT();
    }

    const int NKS = NHW / (KCH * 8);   // 32
    int st = 0, sf = 2;
    for (int i = 0; i < NKS; i++) {
        CP_WAIT1();
        __syncthreads();
        if (i + 2 < NKS) {
            const int ko = (i + 2) * 8;
            cpa16(&Am[sf][t][0], &arow[ko]);
            cpa16(&Am[sf][t][4], &arow[ko + 4]);
            cpa16(&Dm[sf][t][0], &drow[ko]);
            cpa16(&Dm[sf][t][4], &drow[ko + 4]);
        }
        CP_COMMIT();
        uint32_t afr[4][4], bfr[8][2];
#pragma unroll
        for (int mt = 0; mt < 4; mt++) {
            int m0 = mrow + mt * 16;
            afr[mt][0] = __float_as_uint(Am[st][m0 + gid][tig]);
            afr[mt][1] = __float_as_uint(Am[st][m0 + gid + 8][tig]);
            afr[mt][2] = __float_as_uint(Am[st][m0 + gid][tig + 4]);
            afr[mt][3] = __float_as_uint(Am[st][m0 + gid + 8][tig + 4]);
        }
#pragma unroll
        for (int nt = 0; nt < 8; nt++) {
            int n0 = ncol + nt * 8;
            bfr[nt][0] = __float_as_uint(Dm[st][n0 + gid][tig]);
            bfr[nt][1] = __float_as_uint(Dm[st][n0 + gid][tig + 4]);
        }
#pragma unroll
        for (int mt = 0; mt < 4; mt++)
#pragma unroll
            for (int nt = 0; nt < 8; nt++)
                mma_tf32(c[mt][nt], afr[mt], bfr[nt]);
        st = (st == 2) ? 0 : st + 1;
        sf = (sf == 2) ? 0 : sf + 1;
    }

    float* Out = g_gp + ((size_t)(blockIdx.z * 3 + pr) * KCH + sch) * 16384;
#pragma unroll
    for (int mt = 0; mt < 4; mt++) {
        int ra = mrow + mt * 16 + gid;
        int rb = ra + 8;
#pragma unroll
        for (int nt = 0; nt < 8; nt++) {
            int col = ncol + nt * 8 + tig * 2;
            *(float2*)&Out[ra * 128 + col] = make_float2(c[mt][nt][0], c[mt][nt][1]);
            *(float2*)&Out[rb * 128 + col] = make_float2(c[mt][nt][2], c[mt][nt][3]);
        }
    }
}

// ---------------- reduce partials into S / M --------------------------------
__global__ void __launch_bounds__(256) k_gred()
{
    const int pr = blockIdx.y, bm = blockIdx.z;
    const int b = bm >> 1, mat = bm & 1;
    const int ci = (pr == 2) ? 1 : 0;
    const int dj = (pr == 0) ? 0 : 1;
    const int off = blockIdx.x * 256 + threadIdx.x;
    const float* Pp = g_gp + (size_t)(bm * 3 + pr) * KCH * 16384 + off;
    float s = 0.f;
#pragma unroll
    for (int c = 0; c < KCH; c++) s += Pp[c * 16384];
    int il = off >> 7, jl = off & 127;
    float* Out = (mat ? g_M : g_S) + b * 65536;
    Out[(ci * 128 + il) * 256 + dj * 128 + jl] = s;
}

// ---------------- mirror lower-left 128x128 block ---------------------------
__global__ void k_mirror()
{
    const int bm = blockIdx.y;
    float* Out = (bm & 1 ? g_M : g_S) + (bm >> 1) * 65536;
    int idx = blockIdx.x * 256 + threadIdx.x;
    int i = idx >> 7, jl = idx & 127;
    Out[(128 + jl) * 256 + i] = Out[i * 256 + 128 + jl];
}

// ---------------- P[b] = M[b] * W2^T ----------------------------------------
__global__ void __launch_bounds__(256) k_mmA(const float* __restrict__ Wg)
{
    const int j0 = blockIdx.x * 64, i0 = blockIdx.y * 64, b = blockIdx.z;
    const float* A = g_M + b * 65536;
    float* C = g_P + b * 65536;
    __shared__ float As[16][68];
    __shared__ float Bs[16][68];
    const int t = threadIdx.x;
    const int it = (t >> 4) * 4, jt = (t & 15) * 4;
    float acc[4][4];
#pragma unroll
    for (int i = 0; i < 4; i++)
#pragma unroll
        for (int j = 0; j < 4; j++) acc[i][j] = 0.f;
    for (int kc = 0; kc < 256; kc += 16) {
        __syncthreads();
#pragma unroll
        for (int i = 0; i < 4; i++) {
            int idx = i * 256 + t;
            int r = idx >> 4, kk = idx & 15;
            As[kk][r] = A[(i0 + r) * 256 + kc + kk];
            Bs[kk][r] = Wg[(j0 + r) * 256 + kc + kk];
        }
        __syncthreads();
#pragma unroll
        for (int kk = 0; kk < 16; kk++) {
            float a[4], bb[4];
            *(float4*)a  = *(float4*)&As[kk][it];
            *(float4*)bb = *(float4*)&Bs[kk][jt];
#pragma unroll
            for (int i = 0; i < 4; i++)
#pragma unroll
                for (int j = 0; j < 4; j++) acc[i][j] += a[i] * bb[j];
        }
    }
#pragma unroll
    for (int i = 0; i < 4; i++)
#pragma unroll
        for (int j = 0; j < 4; j++)
            C[(i0 + it + i) * 256 + j0 + jt + j] = acc[i][j];
}

// ---------------- C[b] = Ag * B[b]  (generic, used for Gf) -------------------
__global__ void __launch_bounds__(256) k_mmB(
    const float* __restrict__ Ag, const float* __restrict__ Bb, float* __restrict__ Cb)
{
    const int j0 = blockIdx.x * 64, i0 = blockIdx.y * 64, b = blockIdx.z;
    const float* B = Bb + b * 65536;
    float* C = Cb + b * 65536;
    __shared__ float As[16][68];
    __shared__ float Bs[16][68];
    const int t = threadIdx.x;
    const int it = (t >> 4) * 4, jt = (t & 15) * 4;
    float acc[4][4];
#pragma unroll
    for (int i = 0; i < 4; i++)
#pragma unroll
        for (int j = 0; j < 4; j++) acc[i][j] = 0.f;
    for (int kc = 0; kc < 256; kc += 16) {
        __syncthreads();
#pragma unroll
        for (int i = 0; i < 4; i++) {
            int idx = i * 256 + t;
            int r = idx >> 4, kk = idx & 15;
            As[kk][r] = Ag[(i0 + r) * 256 + kc + kk];
        }
#pragma unroll
        for (int i = 0; i < 4; i++) {
            int idx = i * 256 + t;
            int kk = idx >> 6, j = idx & 63;
            Bs[kk][j] = B[(kc + kk) * 256 + j0 + j];
        }
        __syncthreads();
#pragma unroll
        for (int kk = 0; kk < 16; kk++) {
            float a[4], bb[4];
            *(float4*)a  = *(float4*)&As[kk][it];
            *(float4*)bb = *(float4*)&Bs[kk][jt];
#pragma unroll
            for (int i = 0; i < 4; i++)
#pragma unroll
                for (int j = 0; j < 4; j++) acc[i][j] += a[i] * bb[j];
        }
    }
#pragma unroll
    for (int i = 0; i < 4; i++)
#pragma unroll
        for (int j = 0; j < 4; j++)
            C[(i0 + it + i) * 256 + j0 + jt + j] = acc[i][j];
}

// ---------------- batched U = W{1,2} * S  (z = b*2 + which) ------------------
__global__ void __launch_bounds__(256) k_mmU(
    const float* __restrict__ W1, const float* __restrict__ W2)
{
    const int j0 = blockIdx.x * 64, i0 = blockIdx.y * 64;
    const int b = blockIdx.z >> 1, which = blockIdx.z & 1;
    const float* Ag = which ? W2 : W1;
    const float* B = g_S + b * 65536;
    float* C = (which ? g_gp : g_P) + b * 65536;
    __shared__ float As[16][68];
    __shared__ float Bs[16][68];
    const int t = threadIdx.x;
    const int it = (t >> 4) * 4, jt = (t & 15) * 4;
    float acc[4][4];
#pragma unroll
    for (int i = 0; i < 4; i++)
#pragma unroll
        for (int j = 0; j < 4; j++) acc[i][j] = 0.f;
    for (int kc = 0; kc < 256; kc += 16) {
        __syncthreads();
#pragma unroll
        for (int i = 0; i < 4; i++) {
            int idx = i * 256 + t;
            int r = idx >> 4, kk = idx & 15;
            As[kk][r] = Ag[(i0 + r) * 256 + kc + kk];
        }
#pragma unroll
        for (int i = 0; i < 4; i++) {
            int idx = i * 256 + t;
            int kk = idx >> 6, j = idx & 63;
            Bs[kk][j] = B[(kc + kk) * 256 + j0 + j];
        }
        __syncthreads();
#pragma unroll
        for (int kk = 0; kk < 16; kk++) {
            float a[4], bb[4];
            *(float4*)a  = *(float4*)&As[kk][it];
            *(float4*)bb = *(float4*)&Bs[kk][jt];
#pragma unroll
            for (int i = 0; i < 4; i++)
#pragma unroll
                for (int j = 0; j < 4; j++) acc[i][j] += a[i] * bb[j];
        }
    }
#pragma unroll
    for (int i = 0; i < 4; i++)
#pragma unroll
        for (int j = 0; j < 4; j++)
            C[(i0 + it + i) * 256 + j0 + jt + j] = acc[i][j];
}

// ---------------- batched row-dot: norms + W*m (y = which) -------------------
__global__ void __launch_bounds__(256) k_rowdot2(
    const float* __restrict__ W1, const float* __restrict__ W2,
    const float* __restrict__ b1, const float* __restrict__ b2)
{
    const int bC = blockIdx.x;
    const int which = blockIdx.y;
    const int b = bC >> 8, C = bC & 255;
    const float* U = (which ? g_gp : g_P);
    const float* W = which ? W2 : W1;
    const float* bias = which ? b2 : b1;
    const int t = threadIdx.x;
    float wv = W[C * 256 + t];
    float un = U[(size_t)b * 65536 + C * 256 + t] * wv;
    float wm = wv * g_m[b * 256 + t];
#pragma unroll
    for (int o = 16; o; o >>= 1) {
        un += __shfl_xor_sync(0xffffffff, un, o);
        wm += __shfl_xor_sync(0xffffffff, wm, o);
    }
    __shared__ float s1[8], s2[8];
    int w = t >> 5;
    if ((t & 31) == 0) { s1[w] = un; s2[w] = wm; }
    __syncthreads();
    if (t == 0) {
        float a = 0.f, c = 0.f;
        for (int i = 0; i < 8; i++) { a += s1[i]; c += s2[i]; }
        float bc = bias[C];
        float nf = a + 2.f * bc * c + 9216.f * bc * bc;
        if (which) { g_nk[bC] = nf; g_w2m[bC] = c; }
        else       { g_nq[bC] = nf; g_w1m[bC] = c; }
    }
}

// ---------------- attn: logits, softmax, build Chat -------------------------
__global__ void __launch_bounds__(256) k_attn2(
    const float* __restrict__ b1, const float* __restrict__ b2,
    const float* __restrict__ temperature)
{
    const int bh = blockIdx.x;
    const int b = bh >> 3, h = bh & 7;
    const int ch0 = h * 32;
    __shared__ float A[32][33];
    __shared__ float rq[32], rk[32], sw1m[32], sw2m[32], sb1[32], sb2[32];
    __shared__ float2 tab[32];
    const int t = threadIdx.x;
    if (t < 32) {
        int C = b * 256 + ch0 + t;
        rq[t] = rsqrtf(g_nq[C]);
        rk[t] = rsqrtf(g_nk[C]);
        sw1m[t] = g_w1m[C];
        sw2m[t] = g_w2m[C];
        sb1[t] = b1[ch0 + t];
        sb2[t] = b2[ch0 + t];
        float ang = 6.283185307179586f * (float)t / 32.0f;
        tab[t] = make_float2(cosf(ang), sinf(ang));
    }
    __syncthreads();
    const float ts = temperature[h];
    const int w = t >> 5, lane = t & 31;
    for (int r = w; r < 32; r += 8) {
        float Gv = g_Gf[(size_t)b * 65536 + (ch0 + r) * 256 + ch0 + lane];
        float L = (Gv + sw1m[r] * sb2[lane] + sb1[r] * sw2m[lane]
                   + 9216.f * sb1[r] * sb2[lane]) * rq[r] * rk[lane] * ts;
        float m = L;
#pragma unroll
        for (int o = 16; o; o >>= 1) m = fmaxf(m, __shfl_xor_sync(0xffffffff, m, o));
        float e = expf(L - m);
        float s = e;
#pragma unroll
        for (int o = 16; o; o >>= 1) s += __shfl_xor_sync(0xffffffff, s, o);
        A[r][lane] = e / s;
    }
    __syncthreads();
    for (int idx = t; idx < 1024; idx += 256) {
        int e = idx >> 5, d = idx & 31;
        float re = 0.f, im = 0.f;
#pragma unroll 8
        for (int c = 0; c < 32; c++) {
            float a = A[c][d];
            float2 tb = tab[(c * e) & 31];
            re += a * tb.x; im += a * tb.y;
        }
        re *= (1.0f / 32.0f); im *= (1.0f / 32.0f);
        if (e == 0) im += (1.0f / 32.0f);
        g_Chat[bh * 1024 + idx] = make_float2(re, im);
    }
}

// ---------------- circulant tables (tf32 bits out) ---------------------------
__global__ void k_gtab2()
{
    int idx = blockIdx.x * 256 + threadIdx.x;
    int r = idx / 9216;
    int rem = idx - r * 9216;
    int w = rem / 96, a = rem - w * 96;
    int tt = a - w; if (tt < 0) tt += 96;
    float2 g;
    if (r == 0) {
        g = make_float2(tt == 0 ? 1.f : 0.f, 0.f);
    } else {
        const float PI = 3.14159265358979323846f;
        float h1 = PI * (float)r / 96.0f;
        float h2 = PI * (96.0f * (float)tt + (float)r) / 9216.0f;
        float rr = sinf(h1) / (96.0f * sinf(h2));
        float psi = h1 - h2;
        g = make_float2(rr * cosf(psi), rr * sinf(psi));
    }
    g_gcre[idx] = tfbits(g.x);
    g_gcim[idx] = tfbits(g.y);
}

// ---------------- conv as batched tf32 GEMM (pre-converted; no cvt) ----------
__global__ void __launch_bounds__(128) k_vconv()
{
    const int r = blockIdx.x;
    const int ch0 = blockIdx.y * 64;
    __shared__ __align__(16) uint32_t As[2][8][72];
    __shared__ __align__(16) uint32_t Br[2][8][104];
    __shared__ __align__(16) uint32_t Bi[2][8][104];
    const int t = threadIdx.x;
    const int warp = t >> 5, lane = t & 31;
    const int gid = lane >> 2, tig = lane & 3;
    const int mrow = (warp >> 1) * 32;
    const int ncol = (warp & 1) * 48;
    const int ach = t >> 1, aw4 = (t & 1) * 4;
    const int bw = t >> 4, ba0 = (t & 15) * 6;

    float cre[2][6][4], cim[2][6][4];
#pragma unroll
    for (int i = 0; i < 2; i++)
#pragma unroll
        for (int j = 0; j < 6; j++)
#pragma unroll
            for (int q = 0; q < 4; q++) { cre[i][j][q] = 0.f; cim[i][j][q] = 0.f; }

    float4 av;
    float br[6], bi[6];
    av = *(const float4*)&g_v[(size_t)(ch0 + ach) * NHW + r * 96 + aw4];
    {
        const float* pr_ = &g_gcre[(size_t)r * 9216 + bw * 96 + ba0];
        const float* pi_ = &g_gcim[(size_t)r * 9216 + bw * 96 + ba0];
#pragma unroll
        for (int i = 0; i < 6; i++) { br[i] = pr_[i]; bi[i] = pi_[i]; }
    }

    for (int ks = 0; ks < 12; ks++) {
        const int st = ks & 1;
        As[st][aw4 + 0][ach] = __float_as_uint(av.x);
        As[st][aw4 + 1][ach] = __float_as_uint(av.y);
        As[st][aw4 + 2][ach] = __float_as_uint(av.z);
        As[st][aw4 + 3][ach] = __float_as_uint(av.w);
#pragma unroll
        for (int i = 0; i < 6; i++) {
            Br[st][bw][ba0 + i] = __float_as_uint(br[i]);
            Bi[st][bw][ba0 + i] = __float_as_uint(bi[i]);
        }
        __syncthreads();

        int w0n = (ks + 1 < 12) ? (ks + 1) * 8 : 0;
        av = *(const float4*)&g_v[(size_t)(ch0 + ach) * NHW + r * 96 + w0n + aw4];
        {
            const float* pr_ = &g_gcre[(size_t)r * 9216 + (w0n + bw) * 96 + ba0];
            const float* pi_ = &g_gcim[(size_t)r * 9216 + (w0n + bw) * 96 + ba0];
#pragma unroll
            for (int i = 0; i < 6; i++) { br[i] = pr_[i]; bi[i] = pi_[i]; }
        }

        uint32_t afr[2][4], bre[6][2], bim[6][2];
#pragma unroll
        for (int mt = 0; mt < 2; mt++) {
            int m0 = mrow + mt * 16;
            afr[mt][0] = As[st][tig][m0 + gid];
            afr[mt][1] = As[st][tig][m0 + gid + 8];
            afr[mt][2] = As[st][tig + 4][m0 + gid];
            afr[mt][3] = As[st][tig + 4][m0 + gid + 8];
        }
#pragma unroll
        for (int nt = 0; nt < 6; nt++) {
            int n0 = ncol + nt * 8;
            bre[nt][0] = Br[st][tig][n0 + gid];
            bre[nt][1] = Br[st][tig + 4][n0 + gid];
            bim[nt][0] = Bi[st][tig][n0 + gid];
            bim[nt][1] = Bi[st][tig + 4][n0 + gid];
        }
#pragma unroll
        for (int mt = 0; mt < 2; mt++)
#pragma unroll
            for (int nt = 0; nt < 6; nt++) {
                mma_tf32(cre[mt][nt], afr[mt], bre[nt]);
                mma_tf32(cim[mt][nt], afr[mt], bim[nt]);
            }
    }

#pragma unroll
    for (int mt = 0; mt < 2; mt++) {
        int r0 = ch0 + mrow + mt * 16 + gid;
        int r1 = r0 + 8;
        float2* p0 = &g_Tt[(size_t)r0 * NHW + r * 96];
        float2* p1 = &g_Tt[(size_t)r1 * NHW + r * 96];
#pragma unroll
        for (int nt = 0; nt < 6; nt++) {
            int a = ncol + nt * 8 + tig * 2;
            p0[a]     = make_float2(cre[mt][nt][0], cim[mt][nt][0]);
            p0[a + 1] = make_float2(cre[mt][nt][1], cim[mt][nt][1]);
            p1[a]     = make_float2(cre[mt][nt][2], cim[mt][nt][2]);
            p1[a + 1] = make_float2(cre[mt][nt][3], cim[mt][nt][3]);
        }
    }
}

// ---------------- mix + fused transpose, packed f32x2; tf32-bit output -------
__global__ void __launch_bounds__(256) k_mix2()
{
    const int rt = blockIdx.x % 3;
    const int at = blockIdx.x / 3;
    const int bh = blockIdx.y;
    __shared__ float2 Ch[1024];
    __shared__ float2 Ts[32][128];
    const int t = threadIdx.x;
    for (int i = t; i < 1024; i += 256) Ch[i] = g_Chat[bh * 1024 + i];
    for (int i = t; i < 1024; i += 256) {
        int d = i >> 5, rl = i & 31;
        const float2* src = &g_Tt[(size_t)(bh * 32 + d) * NHW + (rt * 32 + rl) * 96 + at * 4];
        *(float4*)&Ts[d][rl * 4]     = *(const float4*)src;
        *(float4*)&Ts[d][rl * 4 + 2] = *(const float4*)(src + 2);
    }
    __syncthreads();
    const int sl = t & 63, eg = t >> 6;
    const unsigned long long SGN = 0x8000000080000000ULL;

    unsigned long long ar0p[4], ai0p[4], ar1p[4], ai1p[4];
#pragma unroll
    for (int j = 0; j < 4; j++) { ar0p[j] = ai0p[j] = ar1p[j] = ai1p[j] = 0ULL; }

    for (int d = 0; d < 32; d++) {
        float2 t0 = Ts[d][sl];
        float2 t1 = Ts[d][sl + 64];
        unsigned long long t0x = pk2(t0.x, t0.x), t0y = pk2(t0.y, t0.y);
        unsigned long long t1x = pk2(t1.x, t1.x), t1y = pk2(t1.y, t1.y);
#pragma unroll
        for (int j = 0; j < 4; j++) {
            float2 cA = Ch[(eg * 8 + 2 * j) * 32 + d];
            float2 cB = Ch[(eg * 8 + 2 * j + 1) * 32 + d];
            unsigned long long cx  = pk2(cA.x, cB.x);
            unsigned long long cy  = pk2(cA.y, cB.y);
            unsigned long long cyn = cy ^ SGN;
            ar0p[j] = fma2(cx,  t0x, ar0p[j]);
            ar0p[j] = fma2(cyn, t0y, ar0p[j]);
            ai0p[j] = fma2(cx,  t0y, ai0p[j]);
            ai0p[j] = fma2(cy,  t0x, ai0p[j]);
            ar1p[j] = fma2(cx,  t1x, ar1p[j]);
            ar1p[j] = fma2(cyn, t1y, ar1p[j]);
            ai1p[j] = fma2(cx,  t1y, ai1p[j]);
            ai1p[j] = fma2(cy,  t1x, ai1p[j]);
        }
    }

    const int al0 = sl & 3,        rl0 = sl >> 2;
    const int al1 = (sl + 64) & 3, rl1 = (sl + 64) >> 2;
#pragma unroll
    for (int j = 0; j < 4; j++) {
        float a0, a1, b0, b1, c0, c1, d0, d1;
        upk2(a0, a1, ar0p[j]);
        upk2(b0, b1, ai0p[j]);
        upk2(c0, c1, ar1p[j]);
        upk2(d0, d1, ai1p[j]);
        int row0 = bh * 32 + eg * 8 + 2 * j;
        int row1 = row0 + 1;
        g_R[(size_t)row0 * NHW + (at * 4 + al0) * 96 + rt * 32 + rl0] = tfbits(sqrtf(a0 * a0 + b0 * b0));
        g_R[(size_t)row1 * NHW + (at * 4 + al0) * 96 + rt * 32 + rl0] = tfbits(sqrtf(a1 * a1 + b1 * b1));
        g_R[(size_t)row0 * NHW + (at * 4 + al1) * 96 + rt * 32 + rl1] = tfbits(sqrtf(c0 * c0 + d0 * d0));
        g_R[(size_t)row1 * NHW + (at * 4 + al1) * 96 + rt * 32 + rl1] = tfbits(sqrtf(c1 * c1 + d1 * d1));
    }
}

// ---------------- launch ----------------
extern "C" void kernel_launch(void* const* d_in, const int* in_sizes, int n_in,
                              void* d_out, int out_size)
{
    const float* x    = (const float*)d_in[0];
    const float* w1   = (const float*)d_in[1];
    const float* b1   = (const float*)d_in[2];
    const float* w2   = (const float*)d_in[3];
    const float* b2   = (const float*)d_in[4];
    const float* w3   = (const float*)d_in[5];
    const float* b3   = (const float*)d_in[6];
    const float* wo   = (const float*)d_in[7];
    const float* temp = (const float*)d_in[8];
    float* out = (float*)d_out;

    float *vp = nullptr, *Rp = nullptr, *Pp = nullptr, *Gfp = nullptr;
    float *xtfp = nullptr, *w3tp = nullptr, *wotp = nullptr;
    cudaGetSymbolAddress((void**)&vp,   g_v);
    cudaGetSymbolAddress((void**)&Rp,   g_R);
    cudaGetSymbolAddress((void**)&Pp,   g_P);
    cudaGetSymbolAddress((void**)&Gfp,  g_Gf);
    cudaGetSymbolAddress((void**)&xtfp, g_xtf);
    cudaGetSymbolAddress((void**)&w3tp, g_w3t);
    cudaGetSymbolAddress((void**)&wotp, g_wot);

    dim3 gg(72, 2, 8);
    dim3 gm(4, 4, 8);

    k_zm     <<<8, 256>>>();
    k_revx   <<<dim3(2048, 9), 256>>>(x);               // xrev(tf32) + xtf(tf32) + m
    k_cvtw   <<<256, 256>>>(w3, wo);
    k_gemm_tf32<<<gg, 128>>>(xtfp, w3tp, b3, vp, 1);    // v (tf32 bits out)
    k_gram6  <<<dim3(KCH, 3, 16), 128>>>(xtfp);         // partial tiles
    k_gred   <<<dim3(64, 3, 16), 256>>>();              // -> S, M
    k_mirror <<<dim3(64, 16), 256>>>();
    k_mmA    <<<gm, 256>>>(w2);                         // P = M * W2^T
    k_mmB    <<<gm, 256>>>(w1, Pp, Gfp);                // Gf = W1 * P
    k_mmU    <<<dim3(4, 4, 16), 256>>>(w1, w2);         // U1 -> g_P, U2 -> g_gp
    k_rowdot2<<<dim3(2048, 2), 256>>>(w1, w2, b1, b2);
    k_gtab2  <<<3456, 256>>>();
    k_attn2  <<<64, 256>>>(b1, b2, temp);
    k_vconv  <<<dim3(96, 32), 128>>>();                 // conv via tensor cores
    k_mix2   <<<dim3(72, 64), 256>>>();                 // mix + transpose -> R (tf32 bits)
    k_gemm_tf32<<<gg, 128>>>(Rp, wotp, nullptr, out, 0);
}

// round 16
// speedup vs baseline: 3.0003x; 1.0243x over previous
#include <cuda_runtime.h>
#include <math.h>
#include <stdint.h>

#define NB 8
#define NC 256
#define NHW 9216
#define NHEAD 8
#define KCH 36            // gram split-K chunks

// ---------------- scratch (device globals; no allocation anywhere) ----------
__device__ float  g_v[NB*NC*NHW];         // tf32 bits (v-GEMM output)
__device__ float  g_xrev[NB*NC*NHW];      // tf32 bits, spatially reversed x
__device__ float  g_xtf[NB*NC*NHW];       // tf32 bits, linear x
__device__ float  g_gp[KCH*3*16*128*128]; // gram partials; first 2MB reused as U2
__device__ float  g_S[NB*256*256];
__device__ float  g_M[NB*256*256];
__device__ float  g_P[NB*256*256];
__device__ float  g_Gf[NB*256*256];
__device__ float  g_w3t[256*256], g_wot[256*256];   // tf32 bits weights
__device__ float  g_m[NB*256];
__device__ float  g_nq[NB*256], g_nk[NB*256];
__device__ float  g_w1m[NB*256], g_w2m[NB*256];
__device__ float2 g_Chat[64*1024];
__device__ float  g_gcre[96*96*96];       // tf32 bits conv tables
__device__ float  g_gcim[96*96*96];
__device__ float2 g_Tt[NB*NC*NHW];        // [ch][r][a]
__device__ float  g_R [NB*NC*NHW];        // tf32 bits (mix output)

// ---------------- helpers -----------------------------------------------------
__device__ __forceinline__ uint32_t f2tf32(float x) {
    uint32_t r;
    asm("cvt.rna.tf32.f32 %0, %1;" : "=r"(r) : "f"(x));
    return r;
}
__device__ __forceinline__ float tfbits(float x) { return __uint_as_float(f2tf32(x)); }
__device__ __forceinline__ void mma_tf32(float* c, const uint32_t* a, const uint32_t* b) {
    asm volatile(
        "mma.sync.aligned.m16n8k8.row.col.f32.tf32.tf32.f32 "
        "{%0,%1,%2,%3}, {%4,%5,%6,%7}, {%8,%9}, {%0,%1,%2,%3};"
        : "+f"(c[0]), "+f"(c[1]), "+f"(c[2]), "+f"(c[3])
        : "r"(a[0]), "r"(a[1]), "r"(a[2]), "r"(a[3]), "r"(b[0]), "r"(b[1]));
}
__device__ __forceinline__ void cpa16(void* dst, const void* src) {
    uint32_t d = (uint32_t)__cvta_generic_to_shared(dst);
    asm volatile("cp.async.cg.shared.global [%0], [%1], 16;" :: "r"(d), "l"(src));
}
#define CP_COMMIT() asm volatile("cp.async.commit_group;")
#define CP_WAIT1()  asm volatile("cp.async.wait_group 1;")
#define CP_WAIT0()  asm volatile("cp.async.wait_group 0;")

__device__ __forceinline__ unsigned long long pk2(float lo, float hi) {
    unsigned long long r;
    asm("mov.b64 %0, {%1, %2};" : "=l"(r) : "f"(lo), "f"(hi));
    return r;
}
__device__ __forceinline__ void upk2(float& lo, float& hi, unsigned long long v) {
    asm("mov.b64 {%0, %1}, %2;" : "=f"(lo), "=f"(hi) : "l"(v));
}
__device__ __forceinline__ unsigned long long fma2(
    unsigned long long a, unsigned long long b, unsigned long long c) {
    unsigned long long d;
    asm("fma.rn.f32x2 %0, %1, %2, %3;" : "=l"(d) : "l"(a), "l"(b), "l"(c));
    return d;
}

// ---------------- tf32 GEMM (3-stage cp.async pipeline) ----------------------
__global__ void __launch_bounds__(128, 3) k_gemm_tf32(
    const float* __restrict__ X, const float* __restrict__ W,
    const float* __restrict__ bias, float* __restrict__ Y, int cvtout)
{
    __shared__ __align__(16) float Wm[3][128][12];
    __shared__ __align__(16) float Xs[3][8][136];
    const int t  = threadIdx.x;
    const int s0 = blockIdx.x * 128;
    const int o0 = blockIdx.y * 128;
    const int b  = blockIdx.z;
    const int warp = t >> 5, lane = t & 31;
    const int gid = lane >> 2, tig = lane & 3;
    const int mrow = (warp >> 1) * 64;
    const int ncol = (warp & 1) * 64;
    const float* Xb = X + (size_t)b * NC * NHW;
    const int xr = t >> 4, xc = (t & 15) * 8;

    float c[4][8][4];
#pragma unroll
    for (int i = 0; i < 4; i++)
#pragma unroll
        for (int j = 0; j < 8; j++)
#pragma unroll
            for (int q = 0; q < 4; q++) c[i][j][q] = 0.f;

#pragma unroll
    for (int p = 0; p < 2; p++) {
        const int kc = p * 8;
        cpa16(&Wm[p][t][0], &W[(o0 + t) * 256 + kc]);
        cpa16(&Wm[p][t][4], &W[(o0 + t) * 256 + kc + 4]);
        cpa16(&Xs[p][xr][xc],     &Xb[(size_t)(kc + xr) * NHW + s0 + xc]);
        cpa16(&Xs[p][xr][xc + 4], &Xb[(size_t)(kc + xr) * NHW + s0 + xc + 4]);
        CP_COMMIT();
    }

    int st = 0, sf = 2;
    for (int i = 0; i < 32; i++) {
        CP_WAIT1();
        __syncthreads();
        if (i + 2 < 32) {
            const int kc = (i + 2) * 8;
            cpa16(&Wm[sf][t][0], &W[(o0 + t) * 256 + kc]);
            cpa16(&Wm[sf][t][4], &W[(o0 + t) * 256 + kc + 4]);
            cpa16(&Xs[sf][xr][xc],     &Xb[(size_t)(kc + xr) * NHW + s0 + xc]);
            cpa16(&Xs[sf][xr][xc + 4], &Xb[(size_t)(kc + xr) * NHW + s0 + xc + 4]);
        }
        CP_COMMIT();
        uint32_t afr[4][4], bfr[8][2];
#pragma unroll
        for (int mt = 0; mt < 4; mt++) {
            int m0 = mrow + mt * 16;
            afr[mt][0] = __float_as_uint(Wm[st][m0 + gid][tig]);
            afr[mt][1] = __float_as_uint(Wm[st][m0 + gid + 8][tig]);
            afr[mt][2] = __float_as_uint(Wm[st][m0 + gid][tig + 4]);
            afr[mt][3] = __float_as_uint(Wm[st][m0 + gid + 8][tig + 4]);
        }
#pragma unroll
        for (int nt = 0; nt < 8; nt++) {
            int n0 = ncol + nt * 8;
            bfr[nt][0] = __float_as_uint(Xs[st][tig][n0 + gid]);
            bfr[nt][1] = __float_as_uint(Xs[st][tig + 4][n0 + gid]);
        }
#pragma unroll
        for (int mt = 0; mt < 4; mt++)
#pragma unroll
            for (int nt = 0; nt < 8; nt++)
                mma_tf32(c[mt][nt], afr[mt], bfr[nt]);
        st = (st == 2) ? 0 : st + 1;
        sf = (sf == 2) ? 0 : sf + 1;
    }

#pragma unroll
    for (int mt = 0; mt < 4; mt++) {
        int oa = o0 + mrow + mt * 16 + gid;
        int ob = oa + 8;
        float ba  = bias ? bias[oa] : 0.f;
        float bb_ = bias ? bias[ob] : 0.f;
        float* ya = Y + (size_t)(b * NC + oa) * NHW + s0;
        float* yb = Y + (size_t)(b * NC + ob) * NHW + s0;
#pragma unroll
        for (int nt = 0; nt < 8; nt++) {
            int sc = ncol + nt * 8 + tig * 2;
            float v0 = c[mt][nt][0] + ba,  v1 = c[mt][nt][1] + ba;
            float v2 = c[mt][nt][2] + bb_, v3 = c[mt][nt][3] + bb_;
            if (cvtout) { v0 = tfbits(v0); v1 = tfbits(v1); v2 = tfbits(v2); v3 = tfbits(v3); }
            *(float2*)&ya[sc] = make_float2(v0, v1);
            *(float2*)&yb[sc] = make_float2(v2, v3);
        }
    }
}

// ---------------- zero g_m ----------------------------------------------------
__global__ void k_zm() { g_m[blockIdx.x * 256 + threadIdx.x] = 0.f; }

// ---------------- pre-convert weights ----------------------------------------
__global__ void k_cvtw(const float* __restrict__ w3, const float* __restrict__ wo)
{
    int i = blockIdx.x * 256 + threadIdx.x;
    g_w3t[i] = tfbits(w3[i]);
    g_wot[i] = tfbits(wo[i]);
}

// ---------------- reversed copy + linear tf32 copy + fused channel sum -------
__global__ void __launch_bounds__(256) k_revx(const float* __restrict__ X)
{
    const int ch = blockIdx.x;
    const int seg = blockIdx.y;
    const float* src = X + (size_t)ch * NHW;
    float* dst = g_xrev + (size_t)ch * NHW;
    float* lin = g_xtf  + (size_t)ch * NHW;
    int s = seg * 1024 + threadIdx.x;
    float lsum = 0.f;
#pragma unroll
    for (int i = 0; i < 4; i++, s += 256) {
        int y = s / 96, x = s - y * 96;
        int ry = (y == 0) ? 0 : 96 - y;
        int rx = (x == 0) ? 0 : 96 - x;
        float v = src[ry * 96 + rx];
        float tv = tfbits(v);
        dst[s] = tv;
        lin[ry * 96 + rx] = tv;
        lsum += v;
    }
#pragma unroll
    for (int o = 16; o; o >>= 1) lsum += __shfl_xor_sync(0xffffffff, lsum, o);
    __shared__ float sb[8];
    int w = threadIdx.x >> 5;
    if ((threadIdx.x & 31) == 0) sb[w] = lsum;
    __syncthreads();
    if (threadIdx.x == 0) {
        float a = 0.f;
        for (int i = 0; i < 8; i++) a += sb[i];
        atomicAdd(&g_m[ch], a);
    }
}

// ---------------- Gram GEMM (3-stage cp.async pipeline) ----------------------
__global__ void __launch_bounds__(128, 3) k_gram6(const float* __restrict__ X)
{
    const int sch = blockIdx.x, pr = blockIdx.y;
    const int b = blockIdx.z >> 1, mat = blockIdx.z & 1;
    const int ci = (pr == 2) ? 1 : 0;
    const int dj = (pr == 0) ? 0 : 1;
    __shared__ __align__(16) float Am[3][128][12];
    __shared__ __align__(16) float Dm[3][128][12];
    const float* Xa = X + (size_t)b * NC * NHW;
    const float* Xd = (mat ? g_xrev : X) + (size_t)b * NC * NHW;
    const int t = threadIdx.x;
    const int warp = t >> 5, lane = t & 31;
    const int gid = lane >> 2, tig = lane & 3;
    const int mrow = (warp >> 1) * 64;
    const int ncol = (warp & 1) * 64;
    const int base = sch * (NHW / KCH);
    const float* arow = &Xa[(size_t)(ci * 128 + t) * NHW + base];
    const float* drow = &Xd[(size_t)(dj * 128 + t) * NHW + base];

    float c[4][8][4];
#pragma unroll
    for (int i = 0; i < 4; i++)
#pragma unroll
        for (int j = 0; j < 8; j++)
#pragma unroll
            for (int q = 0; q < 4; q++) c[i][j][q] = 0.f;

#pragma unroll
    for (int p = 0; p < 2; p++) {
        const int ko = p * 8;
        cpa16(&Am[p][t][0], &arow[ko]);
        cpa16(&Am[p][t][4], &arow[ko + 4]);
        cpa16(&Dm[p][t][0], &drow[ko]);
        cpa16(&Dm[p][t][4], &drow[ko + 4]);
        CP_COMMIT();
    }

    const int NKS = NHW / (KCH * 8);   // 32
    int st = 0, sf = 2;
    for (int i = 0; i < NKS; i++) {
        CP_WAIT1();
        __syncthreads();
        if (i + 2 < NKS) {
            const int ko = (i + 2) * 8;
            cpa16(&Am[sf][t][0], &arow[ko]);
            cpa16(&Am[sf][t][4], &arow[ko + 4]);
            cpa16(&Dm[sf][t][0], &drow[ko]);
            cpa16(&Dm[sf][t][4], &drow[ko + 4]);
        }
        CP_COMMIT();
        uint32_t afr[4][4], bfr[8][2];
#pragma unroll
        for (int mt = 0; mt < 4; mt++) {
            int m0 = mrow + mt * 16;
            afr[mt][0] = __float_as_uint(Am[st][m0 + gid][tig]);
            afr[mt][1] = __float_as_uint(Am[st][m0 + gid + 8][tig]);
            afr[mt][2] = __float_as_uint(Am[st][m0 + gid][tig + 4]);
            afr[mt][3] = __float_as_uint(Am[st][m0 + gid + 8][tig + 4]);
        }
#pragma unroll
        for (int nt = 0; nt < 8; nt++) {
            int n0 = ncol + nt * 8;
            bfr[nt][0] = __float_as_uint(Dm[st][n0 + gid][tig]);
            bfr[nt][1] = __float_as_uint(Dm[st][n0 + gid][tig + 4]);
        }
#pragma unroll
        for (int mt = 0; mt < 4; mt++)
#pragma unroll
            for (int nt = 0; nt < 8; nt++)
                mma_tf32(c[mt][nt], afr[mt], bfr[nt]);
        st = (st == 2) ? 0 : st + 1;
        sf = (sf == 2) ? 0 : sf + 1;
    }

    float* Out = g_gp + ((size_t)(blockIdx.z * 3 + pr) * KCH + sch) * 16384;
#pragma unroll
    for (int mt = 0; mt < 4; mt++) {
        int ra = mrow + mt * 16 + gid;
        int rb = ra + 8;
#pragma unroll
        for (int nt = 0; nt < 8; nt++) {
            int col = ncol + nt * 8 + tig * 2;
            *(float2*)&Out[ra * 128 + col] = make_float2(c[mt][nt][0], c[mt][nt][1]);
            *(float2*)&Out[rb * 128 + col] = make_float2(c[mt][nt][2], c[mt][nt][3]);
        }
    }
}

// ---------------- reduce partials into S / M --------------------------------
__global__ void __launch_bounds__(256) k_gred()
{
    const int pr = blockIdx.y, bm = blockIdx.z;
    const int b = bm >> 1, mat = bm & 1;
    const int ci = (pr == 2) ? 1 : 0;
    const int dj = (pr == 0) ? 0 : 1;
    const int off = blockIdx.x * 256 + threadIdx.x;
    const float* Pp = g_gp + (size_t)(bm * 3 + pr) * KCH * 16384 + off;
    float s = 0.f;
#pragma unroll
    for (int c = 0; c < KCH; c++) s += Pp[c * 16384];
    int il = off >> 7, jl = off & 127;
    float* Out = (mat ? g_M : g_S) + b * 65536;
    Out[(ci * 128 + il) * 256 + dj * 128 + jl] = s;
}

// ---------------- mirror lower-left 128x128 block ---------------------------
__global__ void k_mirror()
{
    const int bm = blockIdx.y;
    float* Out = (bm & 1 ? g_M : g_S) + (bm >> 1) * 65536;
    int idx = blockIdx.x * 256 + threadIdx.x;
    int i = idx >> 7, jl = idx & 127;
    Out[(128 + jl) * 256 + i] = Out[i * 256 + 128 + jl];
}

// ---------------- P[b] = M[b] * W2^T ----------------------------------------
__global__ void __launch_bounds__(256) k_mmA(const float* __restrict__ Wg)
{
    const int j0 = blockIdx.x * 64, i0 = blockIdx.y * 64, b = blockIdx.z;
    const float* A = g_M + b * 65536;
    float* C = g_P + b * 65536;
    __shared__ float As[16][68];
    __shared__ float Bs[16][68];
    const int t = threadIdx.x;
    const int it = (t >> 4) * 4, jt = (t & 15) * 4;
    float acc[4][4];
#pragma unroll
    for (int i = 0; i < 4; i++)
#pragma unroll
        for (int j = 0; j < 4; j++) acc[i][j] = 0.f;
    for (int kc = 0; kc < 256; kc += 16) {
        __syncthreads();
#pragma unroll
        for (int i = 0; i < 4; i++) {
            int idx = i * 256 + t;
            int r = idx >> 4, kk = idx & 15;
            As[kk][r] = A[(i0 + r) * 256 + kc + kk];
            Bs[kk][r] = Wg[(j0 + r) * 256 + kc + kk];
        }
        __syncthreads();
#pragma unroll
        for (int kk = 0; kk < 16; kk++) {
            float a[4], bb[4];
            *(float4*)a  = *(float4*)&As[kk][it];
            *(float4*)bb = *(float4*)&Bs[kk][jt];
#pragma unroll
            for (int i = 0; i < 4; i++)
#pragma unroll
                for (int j = 0; j < 4; j++) acc[i][j] += a[i] * bb[j];
        }
    }
#pragma unroll
    for (int i = 0; i < 4; i++)
#pragma unroll
        for (int j = 0; j < 4; j++)
            C[(i0 + it + i) * 256 + j0 + jt + j] = acc[i][j];
}

// ---------------- C[b] = Ag * B[b]  (generic, used for Gf) -------------------
__global__ void __launch_bounds__(256) k_mmB(
    const float* __restrict__ Ag, const float* __restrict__ Bb, float* __restrict__ Cb)
{
    const int j0 = blockIdx.x * 64, i0 = blockIdx.y * 64, b = blockIdx.z;
    const float* B = Bb + b * 65536;
    float* C = Cb + b * 65536;
    __shared__ float As[16][68];
    __shared__ float Bs[16][68];
    const int t = threadIdx.x;
    const int it = (t >> 4) * 4, jt = (t & 15) * 4;
    float acc[4][4];
#pragma unroll
    for (int i = 0; i < 4; i++)
#pragma unroll
        for (int j = 0; j < 4; j++) acc[i][j] = 0.f;
    for (int kc = 0; kc < 256; kc += 16) {
        __syncthreads();
#pragma unroll
        for (int i = 0; i < 4; i++) {
            int idx = i * 256 + t;
            int r = idx >> 4, kk = idx & 15;
            As[kk][r] = Ag[(i0 + r) * 256 + kc + kk];
        }
#pragma unroll
        for (int i = 0; i < 4; i++) {
            int idx = i * 256 + t;
            int kk = idx >> 6, j = idx & 63;
            Bs[kk][j] = B[(kc + kk) * 256 + j0 + j];
        }
        __syncthreads();
#pragma unroll
        for (int kk = 0; kk < 16; kk++) {
            float a[4], bb[4];
            *(float4*)a  = *(float4*)&As[kk][it];
            *(float4*)bb = *(float4*)&Bs[kk][jt];
#pragma unroll
            for (int i = 0; i < 4; i++)
#pragma unroll
                for (int j = 0; j < 4; j++) acc[i][j] += a[i] * bb[j];
        }
    }
#pragma unroll
    for (int i = 0; i < 4; i++)
#pragma unroll
        for (int j = 0; j < 4; j++)
            C[(i0 + it + i) * 256 + j0 + jt + j] = acc[i][j];
}

// ---------------- batched U = W{1,2} * S  (z = b*2 + which) ------------------
__global__ void __launch_bounds__(256) k_mmU(
    const float* __restrict__ W1, const float* __restrict__ W2)
{
    const int j0 = blockIdx.x * 64, i0 = blockIdx.y * 64;
    const int b = blockIdx.z >> 1, which = blockIdx.z & 1;
    const float* Ag = which ? W2 : W1;
    const float* B = g_S + b * 65536;
    float* C = (which ? g_gp : g_P) + b * 65536;
    __shared__ float As[16][68];
    __shared__ float Bs[16][68];
    const int t = threadIdx.x;
    const int it = (t >> 4) * 4, jt = (t & 15) * 4;
    float acc[4][4];
#pragma unroll
    for (int i = 0; i < 4; i++)
#pragma unroll
        for (int j = 0; j < 4; j++) acc[i][j] = 0.f;
    for (int kc = 0; kc < 256; kc += 16) {
        __syncthreads();
#pragma unroll
        for (int i = 0; i < 4; i++) {
            int idx = i * 256 + t;
            int r = idx >> 4, kk = idx & 15;
            As[kk][r] = Ag[(i0 + r) * 256 + kc + kk];
        }
#pragma unroll
        for (int i = 0; i < 4; i++) {
            int idx = i * 256 + t;
            int kk = idx >> 6, j = idx & 63;
            Bs[kk][j] = B[(kc + kk) * 256 + j0 + j];
        }
        __syncthreads();
#pragma unroll
        for (int kk = 0; kk < 16; kk++) {
            float a[4], bb[4];
            *(float4*)a  = *(float4*)&As[kk][it];
            *(float4*)bb = *(float4*)&Bs[kk][jt];
#pragma unroll
            for (int i = 0; i < 4; i++)
#pragma unroll
                for (int j = 0; j < 4; j++) acc[i][j] += a[i] * bb[j];
        }
    }
#pragma unroll
    for (int i = 0; i < 4; i++)
#pragma unroll
        for (int j = 0; j < 4; j++)
            C[(i0 + it + i) * 256 + j0 + jt + j] = acc[i][j];
}

// ---------------- batched row-dot: norms + W*m (y = which) -------------------
__global__ void __launch_bounds__(256) k_rowdot2(
    const float* __restrict__ W1, const float* __restrict__ W2,
    const float* __restrict__ b1, const float* __restrict__ b2)
{
    const int bC = blockIdx.x;
    const int which = blockIdx.y;
    const int b = bC >> 8, C = bC & 255;
    const float* U = (which ? g_gp : g_P);
    const float* W = which ? W2 : W1;
    const float* bias = which ? b2 : b1;
    const int t = threadIdx.x;
    float wv = W[C * 256 + t];
    float un = U[(size_t)b * 65536 + C * 256 + t] * wv;
    float wm = wv * g_m[b * 256 + t];
#pragma unroll
    for (int o = 16; o; o >>= 1) {
        un += __shfl_xor_sync(0xffffffff, un, o);
        wm += __shfl_xor_sync(0xffffffff, wm, o);
    }
    __shared__ float s1_[8], s2_[8];
    int w = t >> 5;
    if ((t & 31) == 0) { s1_[w] = un; s2_[w] = wm; }
    __syncthreads();
    if (t == 0) {
        float a = 0.f, c = 0.f;
        for (int i = 0; i < 8; i++) { a += s1_[i]; c += s2_[i]; }
        float bc = bias[C];
        float nf = a + 2.f * bc * c + 9216.f * bc * bc;
        if (which) { g_nk[bC] = nf; g_w2m[bC] = c; }
        else       { g_nq[bC] = nf; g_w1m[bC] = c; }
    }
}

// ---------------- attn: logits, softmax, build Chat -------------------------
__global__ void __launch_bounds__(256) k_attn2(
    const float* __restrict__ b1, const float* __restrict__ b2,
    const float* __restrict__ temperature)
{
    const int bh = blockIdx.x;
    const int b = bh >> 3, h = bh & 7;
    const int ch0 = h * 32;
    __shared__ float A[32][33];
    __shared__ float rq[32], rk[32], sw1m[32], sw2m[32], sb1[32], sb2[32];
    __shared__ float2 tab[32];
    const int t = threadIdx.x;
    if (t < 32) {
        int C = b * 256 + ch0 + t;
        rq[t] = rsqrtf(g_nq[C]);
        rk[t] = rsqrtf(g_nk[C]);
        sw1m[t] = g_w1m[C];
        sw2m[t] = g_w2m[C];
        sb1[t] = b1[ch0 + t];
        sb2[t] = b2[ch0 + t];
        float ang = 6.283185307179586f * (float)t / 32.0f;
        tab[t] = make_float2(cosf(ang), sinf(ang));
    }
    __syncthreads();
    const float ts = temperature[h];
    const int w = t >> 5, lane = t & 31;
    for (int r = w; r < 32; r += 8) {
        float Gv = g_Gf[(size_t)b * 65536 + (ch0 + r) * 256 + ch0 + lane];
        float L = (Gv + sw1m[r] * sb2[lane] + sb1[r] * sw2m[lane]
                   + 9216.f * sb1[r] * sb2[lane]) * rq[r] * rk[lane] * ts;
        float m = L;
#pragma unroll
        for (int o = 16; o; o >>= 1) m = fmaxf(m, __shfl_xor_sync(0xffffffff, m, o));
        float e = expf(L - m);
        float s = e;
#pragma unroll
        for (int o = 16; o; o >>= 1) s += __shfl_xor_sync(0xffffffff, s, o);
        A[r][lane] = e / s;
    }
    __syncthreads();
    for (int idx = t; idx < 1024; idx += 256) {
        int e = idx >> 5, d = idx & 31;
        float re = 0.f, im = 0.f;
#pragma unroll 8
        for (int c = 0; c < 32; c++) {
            float a = A[c][d];
            float2 tb = tab[(c * e) & 31];
            re += a * tb.x; im += a * tb.y;
        }
        re *= (1.0f / 32.0f); im *= (1.0f / 32.0f);
        if (e == 0) im += (1.0f / 32.0f);
        g_Chat[bh * 1024 + idx] = make_float2(re, im);
    }
}

// ---------------- circulant tables (tf32 bits out) ---------------------------
__global__ void k_gtab2()
{
    int idx = blockIdx.x * 256 + threadIdx.x;
    int r = idx / 9216;
    int rem = idx - r * 9216;
    int w = rem / 96, a = rem - w * 96;
    int tt = a - w; if (tt < 0) tt += 96;
    float2 g;
    if (r == 0) {
        g = make_float2(tt == 0 ? 1.f : 0.f, 0.f);
    } else {
        const float PI = 3.14159265358979323846f;
        float h1 = PI * (float)r / 96.0f;
        float h2 = PI * (96.0f * (float)tt + (float)r) / 9216.0f;
        float rr = sinf(h1) / (96.0f * sinf(h2));
        float psi = h1 - h2;
        g = make_float2(rr * cosf(psi), rr * sinf(psi));
    }
    g_gcre[idx] = tfbits(g.x);
    g_gcim[idx] = tfbits(g.y);
}

// ---------------- conv as batched tf32 GEMM (pre-converted; no cvt) ----------
__global__ void __launch_bounds__(128) k_vconv()
{
    const int r = blockIdx.x;
    const int ch0 = blockIdx.y * 64;
    __shared__ __align__(16) uint32_t As[2][8][72];
    __shared__ __align__(16) uint32_t Br[2][8][104];
    __shared__ __align__(16) uint32_t Bi[2][8][104];
    const int t = threadIdx.x;
    const int warp = t >> 5, lane = t & 31;
    const int gid = lane >> 2, tig = lane & 3;
    const int mrow = (warp >> 1) * 32;
    const int ncol = (warp & 1) * 48;
    const int ach = t >> 1, aw4 = (t & 1) * 4;
    const int bw = t >> 4, ba0 = (t & 15) * 6;

    float cre[2][6][4], cim[2][6][4];
#pragma unroll
    for (int i = 0; i < 2; i++)
#pragma unroll
        for (int j = 0; j < 6; j++)
#pragma unroll
            for (int q = 0; q < 4; q++) { cre[i][j][q] = 0.f; cim[i][j][q] = 0.f; }

    float4 av;
    float br[6], bi[6];
    av = *(const float4*)&g_v[(size_t)(ch0 + ach) * NHW + r * 96 + aw4];
    {
        const float* pr_ = &g_gcre[(size_t)r * 9216 + bw * 96 + ba0];
        const float* pi_ = &g_gcim[(size_t)r * 9216 + bw * 96 + ba0];
#pragma unroll
        for (int i = 0; i < 6; i++) { br[i] = pr_[i]; bi[i] = pi_[i]; }
    }

    for (int ks = 0; ks < 12; ks++) {
        const int st = ks & 1;
        As[st][aw4 + 0][ach] = __float_as_uint(av.x);
        As[st][aw4 + 1][ach] = __float_as_uint(av.y);
        As[st][aw4 + 2][ach] = __float_as_uint(av.z);
        As[st][aw4 + 3][ach] = __float_as_uint(av.w);
#pragma unroll
        for (int i = 0; i < 6; i++) {
            Br[st][bw][ba0 + i] = __float_as_uint(br[i]);
            Bi[st][bw][ba0 + i] = __float_as_uint(bi[i]);
        }
        __syncthreads();

        int w0n = (ks + 1 < 12) ? (ks + 1) * 8 : 0;
        av = *(const float4*)&g_v[(size_t)(ch0 + ach) * NHW + r * 96 + w0n + aw4];
        {
            const float* pr_ = &g_gcre[(size_t)r * 9216 + (w0n + bw) * 96 + ba0];
            const float* pi_ = &g_gcim[(size_t)r * 9216 + (w0n + bw) * 96 + ba0];
#pragma unroll
            for (int i = 0; i < 6; i++) { br[i] = pr_[i]; bi[i] = pi_[i]; }
        }

        uint32_t afr[2][4], bre[6][2], bim[6][2];
#pragma unroll
        for (int mt = 0; mt < 2; mt++) {
            int m0 = mrow + mt * 16;
            afr[mt][0] = As[st][tig][m0 + gid];
            afr[mt][1] = As[st][tig][m0 + gid + 8];
            afr[mt][2] = As[st][tig + 4][m0 + gid];
            afr[mt][3] = As[st][tig + 4][m0 + gid + 8];
        }
#pragma unroll
        for (int nt = 0; nt < 6; nt++) {
            int n0 = ncol + nt * 8;
            bre[nt][0] = Br[st][tig][n0 + gid];
            bre[nt][1] = Br[st][tig + 4][n0 + gid];
            bim[nt][0] = Bi[st][tig][n0 + gid];
            bim[nt][1] = Bi[st][tig + 4][n0 + gid];
        }
#pragma unroll
        for (int mt = 0; mt < 2; mt++)
#pragma unroll
            for (int nt = 0; nt < 6; nt++) {
                mma_tf32(cre[mt][nt], afr[mt], bre[nt]);
                mma_tf32(cim[mt][nt], afr[mt], bim[nt]);
            }
    }

#pragma unroll
    for (int mt = 0; mt < 2; mt++) {
        int r0 = ch0 + mrow + mt * 16 + gid;
        int r1 = r0 + 8;
        float2* p0 = &g_Tt[(size_t)r0 * NHW + r * 96];
        float2* p1 = &g_Tt[(size_t)r1 * NHW + r * 96];
#pragma unroll
        for (int nt = 0; nt < 6; nt++) {
            int a = ncol + nt * 8 + tig * 2;
            p0[a]     = make_float2(cre[mt][nt][0], cim[mt][nt][0]);
            p0[a + 1] = make_float2(cre[mt][nt][1], cim[mt][nt][1]);
            p1[a]     = make_float2(cre[mt][nt][2], cim[mt][nt][2]);
            p1[a + 1] = make_float2(cre[mt][nt][3], cim[mt][nt][3]);
        }
    }
}

// ---------------- mix + fused transpose, packed f32x2; tf32-bit output -------
__global__ void __launch_bounds__(256) k_mix2()
{
    const int rt = blockIdx.x % 3;
    const int at = blockIdx.x / 3;
    const int bh = blockIdx.y;
    __shared__ float2 Ch[1024];
    __shared__ float2 Ts[32][128];
    const int t = threadIdx.x;
    for (int i = t; i < 1024; i += 256) Ch[i] = g_Chat[bh * 1024 + i];
    for (int i = t; i < 1024; i += 256) {
        int d = i >> 5, rl = i & 31;
        const float2* src = &g_Tt[(size_t)(bh * 32 + d) * NHW + (rt * 32 + rl) * 96 + at * 4];
        *(float4*)&Ts[d][rl * 4]     = *(const float4*)src;
        *(float4*)&Ts[d][rl * 4 + 2] = *(const float4*)(src + 2);
    }
    __syncthreads();
    const int sl = t & 63, eg = t >> 6;
    const unsigned long long SGN = 0x8000000080000000ULL;

    unsigned long long ar0p[4], ai0p[4], ar1p[4], ai1p[4];
#pragma unroll
    for (int j = 0; j < 4; j++) { ar0p[j] = ai0p[j] = ar1p[j] = ai1p[j] = 0ULL; }

    for (int d = 0; d < 32; d++) {
        float2 t0 = Ts[d][sl];
        float2 t1 = Ts[d][sl + 64];
        unsigned long long t0x = pk2(t0.x, t0.x), t0y = pk2(t0.y, t0.y);
        unsigned long long t1x = pk2(t1.x, t1.x), t1y = pk2(t1.y, t1.y);
#pragma unroll
        for (int j = 0; j < 4; j++) {
            float2 cA = Ch[(eg * 8 + 2 * j) * 32 + d];
            float2 cB = Ch[(eg * 8 + 2 * j + 1) * 32 + d];
            unsigned long long cx  = pk2(cA.x, cB.x);
            unsigned long long cy  = pk2(cA.y, cB.y);
            unsigned long long cyn = cy ^ SGN;
            ar0p[j] = fma2(cx,  t0x, ar0p[j]);
            ar0p[j] = fma2(cyn, t0y, ar0p[j]);
            ai0p[j] = fma2(cx,  t0y, ai0p[j]);
            ai0p[j] = fma2(cy,  t0x, ai0p[j]);
            ar1p[j] = fma2(cx,  t1x, ar1p[j]);
            ar1p[j] = fma2(cyn, t1y, ar1p[j]);
            ai1p[j] = fma2(cx,  t1y, ai1p[j]);
            ai1p[j] = fma2(cy,  t1x, ai1p[j]);
        }
    }

    const int al0 = sl & 3,        rl0 = sl >> 2;
    const int al1 = (sl + 64) & 3, rl1 = (sl + 64) >> 2;
#pragma unroll
    for (int j = 0; j < 4; j++) {
        float a0, a1, b0, b1, c0, c1, d0, d1;
        upk2(a0, a1, ar0p[j]);
        upk2(b0, b1, ai0p[j]);
        upk2(c0, c1, ar1p[j]);
        upk2(d0, d1, ai1p[j]);
        int row0 = bh * 32 + eg * 8 + 2 * j;
        int row1 = row0 + 1;
        g_R[(size_t)row0 * NHW + (at * 4 + al0) * 96 + rt * 32 + rl0] = tfbits(sqrtf(a0 * a0 + b0 * b0));
        g_R[(size_t)row1 * NHW + (at * 4 + al0) * 96 + rt * 32 + rl0] = tfbits(sqrtf(a1 * a1 + b1 * b1));
        g_R[(size_t)row0 * NHW + (at * 4 + al1) * 96 + rt * 32 + rl1] = tfbits(sqrtf(c0 * c0 + d0 * d0));
        g_R[(size_t)row1 * NHW + (at * 4 + al1) * 96 + rt * 32 + rl1] = tfbits(sqrtf(c1 * c1 + d1 * d1));
    }
}

// ---------------- launch (fork-join: chain B on side stream) -----------------
extern "C" void kernel_launch(void* const* d_in, const int* in_sizes, int n_in,
                              void* d_out, int out_size)
{
    const float* x    = (const float*)d_in[0];
    const float* w1   = (const float*)d_in[1];
    const float* b1   = (const float*)d_in[2];
    const float* w2   = (const float*)d_in[3];
    const float* b2   = (const float*)d_in[4];
    const float* w3   = (const float*)d_in[5];
    const float* b3   = (const float*)d_in[6];
    const float* wo   = (const float*)d_in[7];
    const float* temp = (const float*)d_in[8];
    float* out = (float*)d_out;

    float *vp = nullptr, *Rp = nullptr, *Pp = nullptr, *Gfp = nullptr;
    float *xtfp = nullptr, *w3tp = nullptr, *wotp = nullptr;
    cudaGetSymbolAddress((void**)&vp,   g_v);
    cudaGetSymbolAddress((void**)&Rp,   g_R);
    cudaGetSymbolAddress((void**)&Pp,   g_P);
    cudaGetSymbolAddress((void**)&Gfp,  g_Gf);
    cudaGetSymbolAddress((void**)&xtfp, g_xtf);
    cudaGetSymbolAddress((void**)&w3tp, g_w3t);
    cudaGetSymbolAddress((void**)&wotp, g_wot);

    static cudaStream_t sB = nullptr;
    static cudaEvent_t  evFork = nullptr, evJoin = nullptr;
    if (sB == nullptr) {
        cudaStreamCreateWithFlags(&sB, cudaStreamNonBlocking);
        cudaEventCreateWithFlags(&evFork, cudaEventDisableTiming);
        cudaEventCreateWithFlags(&evJoin, cudaEventDisableTiming);
    }

    dim3 gg(72, 2, 8);
    dim3 gm(4, 4, 8);

    // -- stream 0 (capture origin): prologue producing xtf/xrev/m
    k_zm     <<<8, 256>>>();
    k_revx   <<<dim3(2048, 9), 256>>>(x);
    cudaEventRecord(evFork, 0);

    // -- chain B (side stream): v path
    cudaStreamWaitEvent(sB, evFork, 0);
    k_cvtw   <<<256, 256, 0, sB>>>(w3, wo);
    k_gtab2  <<<3456, 256, 0, sB>>>();
    k_gemm_tf32<<<gg, 128, 0, sB>>>(xtfp, w3tp, b3, vp, 1);
    k_vconv  <<<dim3(96, 32), 128, 0, sB>>>();
    cudaEventRecord(evJoin, sB);

    // -- chain A (stream 0): attention path
    k_gram6  <<<dim3(KCH, 3, 16), 128>>>(xtfp);
    k_gred   <<<dim3(64, 3, 16), 256>>>();
    k_mirror <<<dim3(64, 16), 256>>>();
    k_mmA    <<<gm, 256>>>(w2);
    k_mmB    <<<gm, 256>>>(w1, Pp, Gfp);
    k_mmU    <<<dim3(4, 4, 16), 256>>>(w1, w2);
    k_rowdot2<<<dim3(2048, 2), 256>>>(w1, w2, b1, b2);
    k_attn2  <<<64, 256>>>(b1, b2, temp);

    // -- join, then epilogue
    cudaStreamWaitEvent(0, evJoin, 0);
    k_mix2   <<<dim3(72, 64), 256>>>();
    k_gemm_tf32<<<gg, 128>>>(Rp, wotp, nullptr, out, 0);
}